// round 9
// baseline (speedup 1.0000x reference)
#include <cuda_runtime.h>
#include <cuda_bf16.h>
#include <math.h>
#include <stdint.h>

// ---------------- problem constants ----------------
#define NT    365
#define NGRID 2048
#define NX    32
#define NH    256
#define NG4   1024
#define M_TOT (NT * NGRID)        // 747520
#define CHUNK 73                  // 365 = 5*73
#define NCHUNK 5
#define MCH   (CHUNK * NGRID)     // 149504

// dynamic SMEM: W hi [0,64K), W lo [64K,128K), A bufs [128K,192K)
#define AOFF  131072
#define DSMEM 196608

// ---------------- device globals (~1.5 GB) ----------------
__device__ __nv_bfloat16 g_x0h[(size_t)M_TOT * NH];
__device__ __nv_bfloat16 g_x0l[(size_t)M_TOT * NH];
__device__ float g_xg[(size_t)MCH * NG4];             // per-chunk ring
__device__ __nv_bfloat16 g_hh[2 * NGRID * NH];        // h ring hi
__device__ __nv_bfloat16 g_hl[2 * NGRID * NH];        // h ring lo
__device__ float g_part[(size_t)M_TOT * 32];
__device__ float g_c[NGRID * NH];
__device__ float g_WinT[NX * NH];
__device__ __nv_bfloat16 g_Wih_h[NG4 * NH], g_Wih_l[NG4 * NH];  // [c][k], c=h*4+g
__device__ __nv_bfloat16 g_Whh_h[NG4 * NH], g_Whh_l[NG4 * NH];
__device__ float g_biasr[NG4];

// ---------------- helpers ----------------
__device__ __forceinline__ float sigf(float x) { return 1.0f / (1.0f + expf(-x)); }

__device__ __forceinline__ uint32_t smem_u32(const void* p) {
    uint32_t a;
    asm("{ .reg .u64 t; cvta.to.shared.u64 t, %1; cvt.u32.u64 %0, t; }" : "=r"(a) : "l"(p));
    return a;
}
__device__ __forceinline__ uint32_t tadr(uint32_t tb, int row, int kcol) {
    uint32_t bo = (uint32_t)(row * 128 + kcol * 2);
    return tb + (bo ^ ((bo >> 3) & 0x70));
}
__device__ __forceinline__ void ldsm4(uint32_t* r, uint32_t addr) {
    asm volatile("ldmatrix.sync.aligned.m8n8.x4.shared.b16 {%0,%1,%2,%3}, [%4];"
                 : "=r"(r[0]), "=r"(r[1]), "=r"(r[2]), "=r"(r[3]) : "r"(addr));
}
__device__ __forceinline__ void mma16816(float* d, const uint32_t* a, const uint32_t* b) {
    asm volatile("mma.sync.aligned.m16n8k16.row.col.f32.bf16.bf16.f32 "
                 "{%0,%1,%2,%3}, {%4,%5,%6,%7}, {%8,%9}, {%0,%1,%2,%3};"
                 : "+f"(d[0]), "+f"(d[1]), "+f"(d[2]), "+f"(d[3])
                 : "r"(a[0]), "r"(a[1]), "r"(a[2]), "r"(a[3]), "r"(b[0]), "r"(b[1]));
}
__device__ __forceinline__ void pref_l2(const void* p) {
    asm volatile("prefetch.global.L2 [%0];" :: "l"(p));
}

// 512-thread tile movers: one 128x64 bf16 tile (row pitch 256 elems = 512B)
__device__ __forceinline__ void ldg_tile(uint4* R, const __nv_bfloat16* __restrict__ g, int tid) {
    const char* gp = (const char*)g;
#pragma unroll
    for (int j = 0; j < 2; j++) {
        int q = tid + j * 512;
        int row = q >> 3, ch = q & 7;
        R[j] = __ldcg((const uint4*)(gp + (size_t)row * 512 + ch * 16));
    }
}
__device__ __forceinline__ void sts_tile(uint32_t dst, const uint4* R, int tid) {
#pragma unroll
    for (int j = 0; j < 2; j++) {
        int q = tid + j * 512;
        int row = q >> 3, ch = q & 7;
        uint32_t bo = (uint32_t)(row * 128 + ch * 16);
        uint32_t off = dst + (bo ^ ((bo >> 3) & 0x70));
        asm volatile("st.shared.v4.b32 [%0], {%1,%2,%3,%4};"
                     :: "r"(off), "r"(R[j].x), "r"(R[j].y), "r"(R[j].z), "r"(R[j].w));
    }
}
__device__ __forceinline__ void ld_tile(uint32_t dst, const __nv_bfloat16* __restrict__ g, int tid) {
    uint4 R[2];
    ldg_tile(R, g, tid);
    sts_tile(dst, R, tid);
}

// one 64-wide K chunk, warp tile 32x32: 3-term precision split, 4 k16 steps
__device__ __forceinline__ void mma_chunk(uint32_t abuf, uint32_t whi, uint32_t wlo,
                                          float acc[2][4][4], int mrow, int nbase,
                                          int rowAl, int kselA, int rowBl, int kselB) {
    uint32_t ahi = abuf, alo = abuf + 16384;
#pragma unroll
    for (int ks = 0; ks < 4; ks++) {
        int kA = ks * 16 + kselA, kB = ks * 16 + kselB;
        uint32_t Ah[2][4], Al[2][4], Wh[2][4], Wl[2][4];
#pragma unroll
        for (int mf = 0; mf < 2; mf++) {
            int row = mrow + mf * 16 + rowAl;
            ldsm4(Ah[mf], tadr(ahi, row, kA));
            ldsm4(Al[mf], tadr(alo, row, kA));
        }
#pragma unroll
        for (int np = 0; np < 2; np++) {
            int n = nbase + np * 16 + rowBl;
            ldsm4(Wh[np], tadr(whi, n, kB));
            ldsm4(Wl[np], tadr(wlo, n, kB));
        }
#pragma unroll
        for (int mf = 0; mf < 2; mf++)
#pragma unroll
            for (int nf = 0; nf < 4; nf++)
                mma16816(acc[mf][nf], Ah[mf], &Wh[nf >> 1][(nf & 1) * 2]);
#pragma unroll
        for (int mf = 0; mf < 2; mf++)
#pragma unroll
            for (int nf = 0; nf < 4; nf++)
                mma16816(acc[mf][nf], Al[mf], &Wh[nf >> 1][(nf & 1) * 2]);
#pragma unroll
        for (int mf = 0; mf < 2; mf++)
#pragma unroll
            for (int nf = 0; nf < 4; nf++)
                mma16816(acc[mf][nf], Ah[mf], &Wl[nf >> 1][(nf & 1) * 2]);
    }
}

// ---------------- prep ----------------
__global__ void k_prep(const float* __restrict__ W_in,
                       const float* __restrict__ W_ih,
                       const float* __restrict__ b_ih,
                       const float* __restrict__ b_hh,
                       const float* __restrict__ W_hh) {
    int i = blockIdx.x * blockDim.x + threadIdx.x;
    if (i < NX * NH) {
        int k = i / NH, h = i % NH;
        g_WinT[k * NH + h] = W_in[h * NX + k];
    }
    if (i < NG4 * NH) {
        int c = i >> 8, k = i & 255;
        int h = c >> 2, g = c & 3;
        int n = g * NH + h;
        float wih = W_ih[n * NH + k];
        float whh = W_hh[n * NH + k];
        __nv_bfloat16 ih_h = __float2bfloat16(wih);
        __nv_bfloat16 hh_h = __float2bfloat16(whh);
        g_Wih_h[i] = ih_h;
        g_Wih_l[i] = __float2bfloat16(wih - __bfloat162float(ih_h));
        g_Whh_h[i] = hh_h;
        g_Whh_l[i] = __float2bfloat16(whh - __bfloat162float(hh_h));
    }
    if (i < NG4) {
        int h = i >> 2, g = i & 3;
        int n = g * NH + h;
        g_biasr[i] = b_ih[n] + b_hh[n];
    }
}

// ---------------- x0 = relu(x @ W_in^T + b_in) -> bf16 hi/lo ----------------
typedef unsigned long long u64t;
__device__ __forceinline__ u64t pk2(float lo, float hi) {
    u64t r; asm("mov.b64 %0, {%1, %2};" : "=l"(r) : "f"(lo), "f"(hi)); return r;
}
__device__ __forceinline__ float2 upk2(u64t v) {
    float2 r; asm("mov.b64 {%0, %1}, %2;" : "=f"(r.x), "=f"(r.y) : "l"(v)); return r;
}
#define FMA2(d, a, b) asm("fma.rn.f32x2 %0, %1, %2, %0;" : "+l"(d) : "l"(a), "l"(b))

__global__ __launch_bounds__(256, 1) void k_x0(const float* __restrict__ x,
                                               const float* __restrict__ b_in) {
    __shared__ float A_s[32][129];
    __shared__ float B_s[32][128];
    int tid = threadIdx.x;
    int r0 = blockIdx.x * 128;
    int c0 = blockIdx.y * 128;

    const float* Ag = x + (size_t)r0 * NX;
#pragma unroll
    for (int j = 0; j < 16; j++) {
        int idx = tid + j * 256;
        A_s[idx & 31][idx >> 5] = Ag[idx];
    }
#pragma unroll
    for (int j = 0; j < 16; j++) {
        int idx = tid + j * 256;
        int k = idx >> 7, col = idx & 127;
        B_s[k][col] = g_WinT[k * NH + c0 + col];
    }
    __syncthreads();

    int tx = tid & 7, ty = tid >> 3;
    int cb = tx * 16, rb = ty * 4;

    u64t acc[4][8];
#pragma unroll
    for (int p = 0; p < 8; p++) {
        u64t bp = pk2(b_in[c0 + cb + 2 * p], b_in[c0 + cb + 2 * p + 1]);
        acc[0][p] = bp; acc[1][p] = bp; acc[2][p] = bp; acc[3][p] = bp;
    }
#pragma unroll
    for (int kk = 0; kk < 32; kk++) {
        u64t a2[4];
#pragma unroll
        for (int i = 0; i < 4; i++) { float a = A_s[kk][rb + i]; a2[i] = pk2(a, a); }
        const u64t* bs = reinterpret_cast<const u64t*>(&B_s[kk][cb]);
        u64t b2[8];
#pragma unroll
        for (int p = 0; p < 8; p++) b2[p] = bs[p];
#pragma unroll
        for (int i = 0; i < 4; i++)
#pragma unroll
            for (int p = 0; p < 8; p++) FMA2(acc[i][p], a2[i], b2[p]);
    }
#pragma unroll
    for (int i = 0; i < 4; i++) {
        size_t r = (size_t)(r0 + rb + i);
        union { unsigned short s[16]; uint4 v[2]; } uh, ul;
#pragma unroll
        for (int p = 0; p < 8; p++) {
            float2 u = upk2(acc[i][p]);
            float f0 = fmaxf(u.x, 0.f), f1 = fmaxf(u.y, 0.f);
            __nv_bfloat16 h0 = __float2bfloat16(f0);
            __nv_bfloat16 h1 = __float2bfloat16(f1);
            __nv_bfloat16 l0 = __float2bfloat16(f0 - __bfloat162float(h0));
            __nv_bfloat16 l1 = __float2bfloat16(f1 - __bfloat162float(h1));
            uh.s[2 * p] = *(unsigned short*)&h0; uh.s[2 * p + 1] = *(unsigned short*)&h1;
            ul.s[2 * p] = *(unsigned short*)&l0; ul.s[2 * p + 1] = *(unsigned short*)&l1;
        }
        uint4* dh = (uint4*)(g_x0h + r * NH + c0 + cb);
        uint4* dl = (uint4*)(g_x0l + r * NH + c0 + cb);
        dh[0] = uh.v[0]; dh[1] = uh.v[1];
        dl[0] = ul.v[0]; dl[1] = ul.v[1];
    }
}

// ---------------- xg = x0 @ Wih^T + bias (HMMA 3-term, one chunk, 512 thr) ------
__global__ __launch_bounds__(512, 1) void k_xgt(int chunk) {
    extern __shared__ char sm[];
    __shared__ float bias_s[128];
    uint32_t sb = smem_u32(sm);
    int tid = threadIdx.x, lane = tid & 31, w = tid >> 5;
    int wm = w >> 2, wn = w & 3;
    int g8 = lane >> 3, r8 = lane & 7;
    int rowAl = (g8 & 1) * 8 + r8, kselA = (g8 >> 1) * 8;
    int rowBl = (g8 >> 1) * 8 + r8, kselB = (g8 & 1) * 8;
    int gid = lane >> 2, tig = lane & 3;
    int n0 = blockIdx.x * 128;

    if (tid < 128) bias_s[tid] = g_biasr[n0 + tid];
#pragma unroll
    for (int kt = 0; kt < 4; kt++) {
        ld_tile(sb + kt * 16384,         g_Wih_h + (size_t)n0 * NH + kt * 64, tid);
        ld_tile(sb + 65536 + kt * 16384, g_Wih_l + (size_t)n0 * NH + kt * 64, tid);
    }

    for (int it = 0; it < 8; it++) {
        size_t mtile = (size_t)blockIdx.y * 8 + it;
        const __nv_bfloat16* ah = g_x0h + ((size_t)chunk * MCH + mtile * 128) * NH;
        const __nv_bfloat16* al = g_x0l + ((size_t)chunk * MCH + mtile * 128) * NH;

        float acc[2][4][4];
#pragma unroll
        for (int a = 0; a < 2; a++)
#pragma unroll
            for (int b = 0; b < 4; b++)
#pragma unroll
                for (int c = 0; c < 4; c++) acc[a][b][c] = 0.f;

        uint4 R[4];
        ldg_tile(R,     ah, tid);
        ldg_tile(R + 2, al, tid);
#pragma unroll 1
        for (int kt = 0; kt < 4; kt++) {
            uint32_t ab = sb + AOFF + (kt & 1) * 32768;
            sts_tile(ab, R, tid);
            sts_tile(ab + 16384, R + 2, tid);
            if (kt < 3) {
                ldg_tile(R,     ah + (kt + 1) * 64, tid);
                ldg_tile(R + 2, al + (kt + 1) * 64, tid);
            }
            __syncthreads();
            mma_chunk(ab, sb + kt * 16384, sb + 65536 + kt * 16384, acc,
                      wm * 32, wn * 32, rowAl, kselA, rowBl, kselB);
        }

#pragma unroll
        for (int mf = 0; mf < 2; mf++)
#pragma unroll
            for (int nf = 0; nf < 4; nf++) {
                size_t row = mtile * 128 + wm * 32 + mf * 16 + gid;
                int coll = wn * 32 + nf * 8 + tig * 2;
                float b0 = bias_s[coll], b1 = bias_s[coll + 1];
                *(float2*)&g_xg[row * NG4 + n0 + coll] =
                    make_float2(acc[mf][nf][0] + b0, acc[mf][nf][1] + b1);
                *(float2*)&g_xg[(row + 8) * NG4 + n0 + coll] =
                    make_float2(acc[mf][nf][2] + b0, acc[mf][nf][3] + b1);
            }
        __syncthreads();
    }
}

// ---------------- persistent HMMA scan (512 thr, 8-CTA cluster barrier) --------
__global__ __launch_bounds__(512, 1) __cluster_dims__(8, 1, 1)
void k_scan(int chunk, const float* __restrict__ W_out) {
    extern __shared__ char sm[];
    __shared__ float Wout_s[NH];
    uint32_t sb = smem_u32(sm);
    int tid = threadIdx.x, lane = tid & 31, w = tid >> 5;
    int wm = w >> 2, wn = w & 3;
    int g8 = lane >> 3, r8 = lane & 7;
    int rowAl = (g8 & 1) * 8 + r8, kselA = (g8 >> 1) * 8;
    int rowBl = (g8 >> 1) * 8 + r8, kselB = (g8 & 1) * 8;
    int gid = lane >> 2, tig = lane & 3;
    int nhat = blockIdx.x & 7, rbk = blockIdx.x >> 3;   // cluster = one rbk group
    int n0 = nhat * 128, rbase = rbk * 128;

    if (tid < NH) Wout_s[tid] = W_out[tid];
#pragma unroll
    for (int kt = 0; kt < 4; kt++) {
        ld_tile(sb + kt * 16384,         g_Whh_h + (size_t)n0 * NH + kt * 64, tid);
        ld_tile(sb + 65536 + kt * 16384, g_Whh_l + (size_t)n0 * NH + kt * 64, tid);
    }

    float creg[2][4];
#pragma unroll
    for (int mf = 0; mf < 2; mf++)
#pragma unroll
        for (int nf = 0; nf < 4; nf++) {
            int row = rbase + wm * 32 + mf * 16 + gid + (tig & 1) * 8;
            int h = nhat * 32 + wn * 8 + nf * 2 + (tig >> 1);
            creg[mf][nf] = (chunk == 0) ? 0.f : g_c[row * NH + h];
        }
    __syncthreads();

    for (int tl = 0; tl < CHUNK; tl++) {
        int tg = chunk * CHUNK + tl;

        // prefetch this step's gate rows into L2
#pragma unroll
        for (int mf = 0; mf < 2; mf++) {
            int rloc = wm * 32 + mf * 16 + gid + (tig & 1) * 8;
            int row = rbase + rloc;
            pref_l2(&g_xg[((size_t)tl * NGRID + row) * NG4 + n0 + (wn * 8 + (tig >> 1)) * 4]);
        }

        float acc[2][4][4];
#pragma unroll
        for (int a = 0; a < 2; a++)
#pragma unroll
            for (int b = 0; b < 4; b++)
#pragma unroll
                for (int c = 0; c < 4; c++) acc[a][b][c] = 0.f;

        if (tg > 0) {
            const __nv_bfloat16* hh = g_hh + (size_t)((tg - 1) & 1) * NGRID * NH + (size_t)rbase * NH;
            const __nv_bfloat16* hl = g_hl + (size_t)((tg - 1) & 1) * NGRID * NH + (size_t)rbase * NH;
            uint4 R[4];
            ldg_tile(R,     hh, tid);
            ldg_tile(R + 2, hl, tid);
#pragma unroll 1
            for (int kt = 0; kt < 4; kt++) {
                uint32_t ab = sb + AOFF + (kt & 1) * 32768;
                sts_tile(ab, R, tid);
                sts_tile(ab + 16384, R + 2, tid);
                if (kt < 3) {
                    ldg_tile(R,     hh + (kt + 1) * 64, tid);
                    ldg_tile(R + 2, hl + (kt + 1) * 64, tid);
                }
                __syncthreads();
                mma_chunk(ab, sb + kt * 16384, sb + 65536 + kt * 16384, acc,
                          wm * 32, wn * 32, rowAl, kselA, rowBl, kselB);
            }
        }

        // epilogue: gate reassembly + cell update; stage h tile in smem
        uint32_t sh_hi = sb + AOFF;           // 128x32 bf16 = 8KB
        uint32_t sh_lo = sb + AOFF + 8192;
        __syncthreads();                       // all mma reads of A bufs done
#pragma unroll
        for (int mf = 0; mf < 2; mf++) {
            int rloc = wm * 32 + mf * 16 + gid + (tig & 1) * 8;
            int row = rbase + rloc;
            float pout = 0.f;
#pragma unroll
            for (int nf = 0; nf < 4; nf++) {
                float c0 = acc[mf][nf][0], c1 = acc[mf][nf][1];
                float c2 = acc[mf][nf][2], c3 = acc[mf][nf][3];
                float s0 = (lane & 1) ? c0 : c2;
                float s1 = (lane & 1) ? c1 : c3;
                float r0 = __shfl_xor_sync(0xffffffffu, s0, 1);
                float r1 = __shfl_xor_sync(0xffffffffu, s1, 1);
                float gi, gf, gg, go;
                if (!(lane & 1)) { gi = c0; gf = c1; gg = r0; go = r1; }
                else             { gi = r0; gf = r1; gg = c2; go = c3; }
                int hl_i = wn * 8 + nf * 2 + (tig >> 1);
                float4 xv = __ldcg((const float4*)&g_xg[((size_t)tl * NGRID + row) * NG4 + n0 + hl_i * 4]);
                float iv = gi + xv.x, fv = gf + xv.y, gv = gg + xv.z, ov = go + xv.w;
                float cn = sigf(fv) * creg[mf][nf] + sigf(iv) * tanhf(gv);
                creg[mf][nf] = cn;
                float hv = sigf(ov) * tanhf(cn);
                pout += hv * Wout_s[nhat * 32 + hl_i];
                __nv_bfloat16 bh = __float2bfloat16(hv);
                __nv_bfloat16 bl = __float2bfloat16(hv - __bfloat162float(bh));
                uint32_t so = (uint32_t)(rloc * 64 + hl_i * 2);
                asm volatile("st.shared.u16 [%0], %1;" :: "r"(sh_hi + so), "h"(*(unsigned short*)&bh));
                asm volatile("st.shared.u16 [%0], %1;" :: "r"(sh_lo + so), "h"(*(unsigned short*)&bl));
            }
            float pr = pout + __shfl_xor_sync(0xffffffffu, pout, 2);
            if ((tig >> 1) == 0)
                g_part[((size_t)tg * NGRID + row) * 32 + nhat * 4 + wn] = pr;
        }
        __syncthreads();

        // coalesced h writeout: 128 rows x 32 cols hi/lo
        {
            int row = tid >> 2, seg = tid & 3;
            uint4 vh, vl;
            asm volatile("ld.shared.v4.b32 {%0,%1,%2,%3}, [%4];"
                         : "=r"(vh.x), "=r"(vh.y), "=r"(vh.z), "=r"(vh.w)
                         : "r"(sh_hi + row * 64 + seg * 16));
            asm volatile("ld.shared.v4.b32 {%0,%1,%2,%3}, [%4];"
                         : "=r"(vl.x), "=r"(vl.y), "=r"(vl.z), "=r"(vl.w)
                         : "r"(sh_lo + row * 64 + seg * 16));
            size_t go = (size_t)(tg & 1) * NGRID * NH + (size_t)(rbase + row) * NH + nhat * 32 + seg * 8;
            *(uint4*)(g_hh + go) = vh;
            *(uint4*)(g_hl + go) = vl;
        }

        // hardware cluster barrier: release own h stores, acquire peers'
        if (tl < CHUNK - 1) {
            asm volatile("barrier.cluster.arrive.aligned;" ::: "memory");
            asm volatile("barrier.cluster.wait.aligned;" ::: "memory");
        }
    }

    // spill c
#pragma unroll
    for (int mf = 0; mf < 2; mf++)
#pragma unroll
        for (int nf = 0; nf < 4; nf++) {
            int row = rbase + wm * 32 + mf * 16 + gid + (tig & 1) * 8;
            int h = nhat * 32 + wn * 8 + nf * 2 + (tig >> 1);
            g_c[row * NH + h] = creg[mf][nf];
        }
}

// ---------------- out = sum(32 partials) + b_out ----------------
__global__ __launch_bounds__(256) void k_out(const float* __restrict__ b_out,
                                             float* __restrict__ out) {
    size_t r = (size_t)blockIdx.x * 256 + threadIdx.x;
    const float4* p = (const float4*)(g_part + r * 32);
    float s = 0.f;
#pragma unroll
    for (int j = 0; j < 8; j++) {
        float4 v = p[j];
        s += v.x + v.y + v.z + v.w;
    }
    out[r] = s + b_out[0];
}

// ---------------- launch ----------------
extern "C" void kernel_launch(void* const* d_in, const int* in_sizes, int n_in,
                              void* d_out, int out_size) {
    const float* x     = (const float*)d_in[0];
    const float* W_in  = (const float*)d_in[1];
    const float* b_in  = (const float*)d_in[2];
    const float* W_ih  = (const float*)d_in[3];
    const float* b_ih  = (const float*)d_in[4];
    const float* W_hh  = (const float*)d_in[5];
    const float* b_hh  = (const float*)d_in[6];
    const float* W_out = (const float*)d_in[7];
    const float* b_out = (const float*)d_in[8];
    float* out = (float*)d_out;

    static int attr_done = 0;
    if (!attr_done) {
        cudaFuncSetAttribute(k_xgt,  cudaFuncAttributeMaxDynamicSharedMemorySize, DSMEM);
        cudaFuncSetAttribute(k_scan, cudaFuncAttributeMaxDynamicSharedMemorySize, DSMEM);
        attr_done = 1;
    }

    k_prep<<<(NG4 * NH + 255) / 256, 256>>>(W_in, W_ih, b_ih, b_hh, W_hh);
    k_x0<<<dim3(M_TOT / 128, NH / 128), 256>>>(x, b_in);
    for (int chunk = 0; chunk < NCHUNK; chunk++) {
        k_xgt<<<dim3(8, 146), 512, DSMEM>>>(chunk);
        k_scan<<<128, 512, DSMEM>>>(chunk, W_out);
    }
    k_out<<<M_TOT / 256, 256>>>(b_out, out);
}

// round 10
// speedup vs baseline: 1.4546x; 1.4546x over previous
#include <cuda_runtime.h>
#include <cuda_bf16.h>
#include <math.h>
#include <stdint.h>

// ---------------- problem constants ----------------
#define NT    365
#define NGRID 2048
#define NX    32
#define NH    256
#define NG4   1024
#define M_TOT (NT * NGRID)        // 747520
#define CHUNK 73                  // 365 = 5*73
#define NCHUNK 5
#define MCH   (CHUNK * NGRID)     // 149504

// dynamic SMEM: W hi [0,64K), W lo [64K,128K), A bufs [128K,192K)
#define AOFF  131072
#define DSMEM 196608

// ---------------- device globals (~2.1 GB) ----------------
__device__ __nv_bfloat16 g_x0h[(size_t)M_TOT * NH];
__device__ __nv_bfloat16 g_x0l[(size_t)M_TOT * NH];
__device__ float g_xg[2][(size_t)MCH * NG4];          // double-buffered chunk ring
__device__ __nv_bfloat16 g_hh[2 * NGRID * NH];        // h ring hi
__device__ __nv_bfloat16 g_hl[2 * NGRID * NH];        // h ring lo
__device__ float g_part[(size_t)M_TOT * 32];
__device__ float g_c[NGRID * NH];
__device__ float g_WinT[NX * NH];
__device__ __nv_bfloat16 g_Wih_h[NG4 * NH], g_Wih_l[NG4 * NH];  // [c][k], c=h*4+g
__device__ __nv_bfloat16 g_Whh_h[NG4 * NH], g_Whh_l[NG4 * NH];
__device__ float g_biasr[NG4];
__device__ unsigned g_gcnt[16 * 32];   // per-rbk-group barrier (padded)
__device__ unsigned g_ggen[16 * 32];

// ---------------- helpers ----------------
__device__ __forceinline__ float sigf(float x) { return 1.0f / (1.0f + expf(-x)); }

__device__ __forceinline__ uint32_t smem_u32(const void* p) {
    uint32_t a;
    asm("{ .reg .u64 t; cvta.to.shared.u64 t, %1; cvt.u32.u64 %0, t; }" : "=r"(a) : "l"(p));
    return a;
}
__device__ __forceinline__ uint32_t tadr(uint32_t tb, int row, int kcol) {
    uint32_t bo = (uint32_t)(row * 128 + kcol * 2);
    return tb + (bo ^ ((bo >> 3) & 0x70));
}
__device__ __forceinline__ void ldsm4(uint32_t* r, uint32_t addr) {
    asm volatile("ldmatrix.sync.aligned.m8n8.x4.shared.b16 {%0,%1,%2,%3}, [%4];"
                 : "=r"(r[0]), "=r"(r[1]), "=r"(r[2]), "=r"(r[3]) : "r"(addr));
}
__device__ __forceinline__ void mma16816(float* d, const uint32_t* a, const uint32_t* b) {
    asm volatile("mma.sync.aligned.m16n8k16.row.col.f32.bf16.bf16.f32 "
                 "{%0,%1,%2,%3}, {%4,%5,%6,%7}, {%8,%9}, {%0,%1,%2,%3};"
                 : "+f"(d[0]), "+f"(d[1]), "+f"(d[2]), "+f"(d[3])
                 : "r"(a[0]), "r"(a[1]), "r"(a[2]), "r"(a[3]), "r"(b[0]), "r"(b[1]));
}
__device__ __forceinline__ void pref_l2(const void* p) {
    asm volatile("prefetch.global.L2 [%0];" :: "l"(p));
}

// 512-thread tile movers: one 128x64 bf16 tile (row pitch 256 elems = 512B)
__device__ __forceinline__ void ldg_tile(uint4* R, const __nv_bfloat16* __restrict__ g, int tid) {
    const char* gp = (const char*)g;
#pragma unroll
    for (int j = 0; j < 2; j++) {
        int q = tid + j * 512;
        int row = q >> 3, ch = q & 7;
        R[j] = __ldcg((const uint4*)(gp + (size_t)row * 512 + ch * 16));
    }
}
__device__ __forceinline__ void sts_tile(uint32_t dst, const uint4* R, int tid) {
#pragma unroll
    for (int j = 0; j < 2; j++) {
        int q = tid + j * 512;
        int row = q >> 3, ch = q & 7;
        uint32_t bo = (uint32_t)(row * 128 + ch * 16);
        uint32_t off = dst + (bo ^ ((bo >> 3) & 0x70));
        asm volatile("st.shared.v4.b32 [%0], {%1,%2,%3,%4};"
                     :: "r"(off), "r"(R[j].x), "r"(R[j].y), "r"(R[j].z), "r"(R[j].w));
    }
}
__device__ __forceinline__ void ld_tile(uint32_t dst, const __nv_bfloat16* __restrict__ g, int tid) {
    uint4 R[2];
    ldg_tile(R, g, tid);
    sts_tile(dst, R, tid);
}

// one 64-wide K chunk, warp tile 32x32: 3-term precision split, 4 k16 steps
__device__ __forceinline__ void mma_chunk(uint32_t abuf, uint32_t whi, uint32_t wlo,
                                          float acc[2][4][4], int mrow, int nbase,
                                          int rowAl, int kselA, int rowBl, int kselB) {
    uint32_t ahi = abuf, alo = abuf + 16384;
#pragma unroll
    for (int ks = 0; ks < 4; ks++) {
        int kA = ks * 16 + kselA, kB = ks * 16 + kselB;
        uint32_t Ah[2][4], Al[2][4], Wh[2][4], Wl[2][4];
#pragma unroll
        for (int mf = 0; mf < 2; mf++) {
            int row = mrow + mf * 16 + rowAl;
            ldsm4(Ah[mf], tadr(ahi, row, kA));
            ldsm4(Al[mf], tadr(alo, row, kA));
        }
#pragma unroll
        for (int np = 0; np < 2; np++) {
            int n = nbase + np * 16 + rowBl;
            ldsm4(Wh[np], tadr(whi, n, kB));
            ldsm4(Wl[np], tadr(wlo, n, kB));
        }
#pragma unroll
        for (int mf = 0; mf < 2; mf++)
#pragma unroll
            for (int nf = 0; nf < 4; nf++)
                mma16816(acc[mf][nf], Ah[mf], &Wh[nf >> 1][(nf & 1) * 2]);
#pragma unroll
        for (int mf = 0; mf < 2; mf++)
#pragma unroll
            for (int nf = 0; nf < 4; nf++)
                mma16816(acc[mf][nf], Al[mf], &Wh[nf >> 1][(nf & 1) * 2]);
#pragma unroll
        for (int mf = 0; mf < 2; mf++)
#pragma unroll
            for (int nf = 0; nf < 4; nf++)
                mma16816(acc[mf][nf], Ah[mf], &Wl[nf >> 1][(nf & 1) * 2]);
    }
}

// ---------------- per-rbk 8-CTA software barrier (proven fast) ----------------
__device__ __forceinline__ void group_sync(int grp) {
    __syncthreads();
    if (threadIdx.x == 0) {
        __threadfence();
        volatile unsigned* genp = &g_ggen[grp * 32];
        unsigned gen = *genp;
        if (atomicAdd(&g_gcnt[grp * 32], 1u) == 7u) {
            g_gcnt[grp * 32] = 0;
            __threadfence();
            atomicExch((unsigned*)&g_ggen[grp * 32], gen + 1);
        } else {
            while (*genp == gen) __nanosleep(20);
        }
        __threadfence();
    }
    __syncthreads();
}

// ---------------- prep ----------------
__global__ void k_prep(const float* __restrict__ W_in,
                       const float* __restrict__ W_ih,
                       const float* __restrict__ b_ih,
                       const float* __restrict__ b_hh,
                       const float* __restrict__ W_hh) {
    int i = blockIdx.x * blockDim.x + threadIdx.x;
    if (i < NX * NH) {
        int k = i / NH, h = i % NH;
        g_WinT[k * NH + h] = W_in[h * NX + k];
    }
    if (i < NG4 * NH) {
        int c = i >> 8, k = i & 255;
        int h = c >> 2, g = c & 3;
        int n = g * NH + h;
        float wih = W_ih[n * NH + k];
        float whh = W_hh[n * NH + k];
        __nv_bfloat16 ih_h = __float2bfloat16(wih);
        __nv_bfloat16 hh_h = __float2bfloat16(whh);
        g_Wih_h[i] = ih_h;
        g_Wih_l[i] = __float2bfloat16(wih - __bfloat162float(ih_h));
        g_Whh_h[i] = hh_h;
        g_Whh_l[i] = __float2bfloat16(whh - __bfloat162float(hh_h));
    }
    if (i < NG4) {
        int h = i >> 2, g = i & 3;
        int n = g * NH + h;
        g_biasr[i] = b_ih[n] + b_hh[n];
    }
}

// ---------------- x0 = relu(x @ W_in^T + b_in) -> bf16 hi/lo ----------------
typedef unsigned long long u64t;
__device__ __forceinline__ u64t pk2(float lo, float hi) {
    u64t r; asm("mov.b64 %0, {%1, %2};" : "=l"(r) : "f"(lo), "f"(hi)); return r;
}
__device__ __forceinline__ float2 upk2(u64t v) {
    float2 r; asm("mov.b64 {%0, %1}, %2;" : "=f"(r.x), "=f"(r.y) : "l"(v)); return r;
}
#define FMA2(d, a, b) asm("fma.rn.f32x2 %0, %1, %2, %0;" : "+l"(d) : "l"(a), "l"(b))

__global__ __launch_bounds__(256, 1) void k_x0(const float* __restrict__ x,
                                               const float* __restrict__ b_in) {
    __shared__ float A_s[32][129];
    __shared__ float B_s[32][128];
    int tid = threadIdx.x;
    int r0 = blockIdx.x * 128;
    int c0 = blockIdx.y * 128;

    const float* Ag = x + (size_t)r0 * NX;
#pragma unroll
    for (int j = 0; j < 16; j++) {
        int idx = tid + j * 256;
        A_s[idx & 31][idx >> 5] = Ag[idx];
    }
#pragma unroll
    for (int j = 0; j < 16; j++) {
        int idx = tid + j * 256;
        int k = idx >> 7, col = idx & 127;
        B_s[k][col] = g_WinT[k * NH + c0 + col];
    }
    __syncthreads();

    int tx = tid & 7, ty = tid >> 3;
    int cb = tx * 16, rb = ty * 4;

    u64t acc[4][8];
#pragma unroll
    for (int p = 0; p < 8; p++) {
        u64t bp = pk2(b_in[c0 + cb + 2 * p], b_in[c0 + cb + 2 * p + 1]);
        acc[0][p] = bp; acc[1][p] = bp; acc[2][p] = bp; acc[3][p] = bp;
    }
#pragma unroll
    for (int kk = 0; kk < 32; kk++) {
        u64t a2[4];
#pragma unroll
        for (int i = 0; i < 4; i++) { float a = A_s[kk][rb + i]; a2[i] = pk2(a, a); }
        const u64t* bs = reinterpret_cast<const u64t*>(&B_s[kk][cb]);
        u64t b2[8];
#pragma unroll
        for (int p = 0; p < 8; p++) b2[p] = bs[p];
#pragma unroll
        for (int i = 0; i < 4; i++)
#pragma unroll
            for (int p = 0; p < 8; p++) FMA2(acc[i][p], a2[i], b2[p]);
    }
#pragma unroll
    for (int i = 0; i < 4; i++) {
        size_t r = (size_t)(r0 + rb + i);
        union { unsigned short s[16]; uint4 v[2]; } uh, ul;
#pragma unroll
        for (int p = 0; p < 8; p++) {
            float2 u = upk2(acc[i][p]);
            float f0 = fmaxf(u.x, 0.f), f1 = fmaxf(u.y, 0.f);
            __nv_bfloat16 h0 = __float2bfloat16(f0);
            __nv_bfloat16 h1 = __float2bfloat16(f1);
            __nv_bfloat16 l0 = __float2bfloat16(f0 - __bfloat162float(h0));
            __nv_bfloat16 l1 = __float2bfloat16(f1 - __bfloat162float(h1));
            uh.s[2 * p] = *(unsigned short*)&h0; uh.s[2 * p + 1] = *(unsigned short*)&h1;
            ul.s[2 * p] = *(unsigned short*)&l0; ul.s[2 * p + 1] = *(unsigned short*)&l1;
        }
        uint4* dh = (uint4*)(g_x0h + r * NH + c0 + cb);
        uint4* dl = (uint4*)(g_x0l + r * NH + c0 + cb);
        dh[0] = uh.v[0]; dh[1] = uh.v[1];
        dl[0] = ul.v[0]; dl[1] = ul.v[1];
    }
}

// ---------------- xg = x0 @ Wih^T + bias (HMMA 3-term, one chunk, 512 thr) ------
__global__ __launch_bounds__(512, 1) void k_xgt(int chunk) {
    extern __shared__ char sm[];
    __shared__ float bias_s[128];
    float* xgp = g_xg[chunk & 1];
    uint32_t sb = smem_u32(sm);
    int tid = threadIdx.x, lane = tid & 31, w = tid >> 5;
    int wm = w >> 2, wn = w & 3;
    int g8 = lane >> 3, r8 = lane & 7;
    int rowAl = (g8 & 1) * 8 + r8, kselA = (g8 >> 1) * 8;
    int rowBl = (g8 >> 1) * 8 + r8, kselB = (g8 & 1) * 8;
    int gid = lane >> 2, tig = lane & 3;
    int n0 = blockIdx.x * 128;

    if (tid < 128) bias_s[tid] = g_biasr[n0 + tid];
#pragma unroll
    for (int kt = 0; kt < 4; kt++) {
        ld_tile(sb + kt * 16384,         g_Wih_h + (size_t)n0 * NH + kt * 64, tid);
        ld_tile(sb + 65536 + kt * 16384, g_Wih_l + (size_t)n0 * NH + kt * 64, tid);
    }

    for (int it = 0; it < 8; it++) {
        size_t mtile = (size_t)blockIdx.y * 8 + it;
        const __nv_bfloat16* ah = g_x0h + ((size_t)chunk * MCH + mtile * 128) * NH;
        const __nv_bfloat16* al = g_x0l + ((size_t)chunk * MCH + mtile * 128) * NH;

        float acc[2][4][4];
#pragma unroll
        for (int a = 0; a < 2; a++)
#pragma unroll
            for (int b = 0; b < 4; b++)
#pragma unroll
                for (int c = 0; c < 4; c++) acc[a][b][c] = 0.f;

        uint4 R[4];
        ldg_tile(R,     ah, tid);
        ldg_tile(R + 2, al, tid);
#pragma unroll 1
        for (int kt = 0; kt < 4; kt++) {
            uint32_t ab = sb + AOFF + (kt & 1) * 32768;
            sts_tile(ab, R, tid);
            sts_tile(ab + 16384, R + 2, tid);
            if (kt < 3) {
                ldg_tile(R,     ah + (kt + 1) * 64, tid);
                ldg_tile(R + 2, al + (kt + 1) * 64, tid);
            }
            __syncthreads();
            mma_chunk(ab, sb + kt * 16384, sb + 65536 + kt * 16384, acc,
                      wm * 32, wn * 32, rowAl, kselA, rowBl, kselB);
        }

#pragma unroll
        for (int mf = 0; mf < 2; mf++)
#pragma unroll
            for (int nf = 0; nf < 4; nf++) {
                size_t row = mtile * 128 + wm * 32 + mf * 16 + gid;
                int coll = wn * 32 + nf * 8 + tig * 2;
                float b0 = bias_s[coll], b1 = bias_s[coll + 1];
                *(float2*)&xgp[row * NG4 + n0 + coll] =
                    make_float2(acc[mf][nf][0] + b0, acc[mf][nf][1] + b1);
                *(float2*)&xgp[(row + 8) * NG4 + n0 + coll] =
                    make_float2(acc[mf][nf][2] + b0, acc[mf][nf][3] + b1);
            }
        __syncthreads();
    }
}

// ---------------- persistent HMMA scan (512 thr, software group barrier) --------
__global__ __launch_bounds__(512, 1) void k_scan(int chunk, const float* __restrict__ W_out) {
    extern __shared__ char sm[];
    __shared__ float Wout_s[NH];
    const float* xgp = g_xg[chunk & 1];
    uint32_t sb = smem_u32(sm);
    int tid = threadIdx.x, lane = tid & 31, w = tid >> 5;
    int wm = w >> 2, wn = w & 3;
    int g8 = lane >> 3, r8 = lane & 7;
    int rowAl = (g8 & 1) * 8 + r8, kselA = (g8 >> 1) * 8;
    int rowBl = (g8 >> 1) * 8 + r8, kselB = (g8 & 1) * 8;
    int gid = lane >> 2, tig = lane & 3;
    int nhat = blockIdx.x & 7, rbk = blockIdx.x >> 3;
    int n0 = nhat * 128, rbase = rbk * 128;

    if (tid < NH) Wout_s[tid] = W_out[tid];
#pragma unroll
    for (int kt = 0; kt < 4; kt++) {
        ld_tile(sb + kt * 16384,         g_Whh_h + (size_t)n0 * NH + kt * 64, tid);
        ld_tile(sb + 65536 + kt * 16384, g_Whh_l + (size_t)n0 * NH + kt * 64, tid);
    }

    float creg[2][4];
#pragma unroll
    for (int mf = 0; mf < 2; mf++)
#pragma unroll
        for (int nf = 0; nf < 4; nf++) {
            int row = rbase + wm * 32 + mf * 16 + gid + (tig & 1) * 8;
            int h = nhat * 32 + wn * 8 + nf * 2 + (tig >> 1);
            creg[mf][nf] = (chunk == 0) ? 0.f : g_c[row * NH + h];
        }
    __syncthreads();

    for (int tl = 0; tl < CHUNK; tl++) {
        int tg = chunk * CHUNK + tl;

        // prefetch this step's gate rows into L2
#pragma unroll
        for (int mf = 0; mf < 2; mf++) {
            int rloc = wm * 32 + mf * 16 + gid + (tig & 1) * 8;
            int row = rbase + rloc;
            pref_l2(&xgp[((size_t)tl * NGRID + row) * NG4 + n0 + (wn * 8 + (tig >> 1)) * 4]);
        }

        float acc[2][4][4];
#pragma unroll
        for (int a = 0; a < 2; a++)
#pragma unroll
            for (int b = 0; b < 4; b++)
#pragma unroll
                for (int c = 0; c < 4; c++) acc[a][b][c] = 0.f;

        if (tg > 0) {
            const __nv_bfloat16* hh = g_hh + (size_t)((tg - 1) & 1) * NGRID * NH + (size_t)rbase * NH;
            const __nv_bfloat16* hl = g_hl + (size_t)((tg - 1) & 1) * NGRID * NH + (size_t)rbase * NH;
            uint4 R[4];
            ldg_tile(R,     hh, tid);
            ldg_tile(R + 2, hl, tid);
#pragma unroll 1
            for (int kt = 0; kt < 4; kt++) {
                uint32_t ab = sb + AOFF + (kt & 1) * 32768;
                sts_tile(ab, R, tid);
                sts_tile(ab + 16384, R + 2, tid);
                if (kt < 3) {
                    ldg_tile(R,     hh + (kt + 1) * 64, tid);
                    ldg_tile(R + 2, hl + (kt + 1) * 64, tid);
                }
                __syncthreads();
                mma_chunk(ab, sb + kt * 16384, sb + 65536 + kt * 16384, acc,
                          wm * 32, wn * 32, rowAl, kselA, rowBl, kselB);
            }
        }

        // epilogue: gate reassembly + cell update; stage h tile in smem
        uint32_t sh_hi = sb + AOFF;           // 128x32 bf16 = 8KB
        uint32_t sh_lo = sb + AOFF + 8192;
        __syncthreads();                       // all mma reads of A bufs done
#pragma unroll
        for (int mf = 0; mf < 2; mf++) {
            int rloc = wm * 32 + mf * 16 + gid + (tig & 1) * 8;
            int row = rbase + rloc;
            float pout = 0.f;
#pragma unroll
            for (int nf = 0; nf < 4; nf++) {
                float c0 = acc[mf][nf][0], c1 = acc[mf][nf][1];
                float c2 = acc[mf][nf][2], c3 = acc[mf][nf][3];
                float s0 = (lane & 1) ? c0 : c2;
                float s1 = (lane & 1) ? c1 : c3;
                float r0 = __shfl_xor_sync(0xffffffffu, s0, 1);
                float r1 = __shfl_xor_sync(0xffffffffu, s1, 1);
                float gi, gf, gg, go;
                if (!(lane & 1)) { gi = c0; gf = c1; gg = r0; go = r1; }
                else             { gi = r0; gf = r1; gg = c2; go = c3; }
                int hl_i = wn * 8 + nf * 2 + (tig >> 1);
                float4 xv = __ldcg((const float4*)&xgp[((size_t)tl * NGRID + row) * NG4 + n0 + hl_i * 4]);
                float iv = gi + xv.x, fv = gf + xv.y, gv = gg + xv.z, ov = go + xv.w;
                float cn = sigf(fv) * creg[mf][nf] + sigf(iv) * tanhf(gv);
                creg[mf][nf] = cn;
                float hv = sigf(ov) * tanhf(cn);
                pout += hv * Wout_s[nhat * 32 + hl_i];
                __nv_bfloat16 bh = __float2bfloat16(hv);
                __nv_bfloat16 bl = __float2bfloat16(hv - __bfloat162float(bh));
                uint32_t so = (uint32_t)(rloc * 64 + hl_i * 2);
                asm volatile("st.shared.u16 [%0], %1;" :: "r"(sh_hi + so), "h"(*(unsigned short*)&bh));
                asm volatile("st.shared.u16 [%0], %1;" :: "r"(sh_lo + so), "h"(*(unsigned short*)&bl));
            }
            float pr = pout + __shfl_xor_sync(0xffffffffu, pout, 2);
            if ((tig >> 1) == 0)
                g_part[((size_t)tg * NGRID + row) * 32 + nhat * 4 + wn] = pr;
        }
        __syncthreads();

        // coalesced h writeout: 128 rows x 32 cols hi/lo
        {
            int row = tid >> 2, seg = tid & 3;
            uint4 vh, vl;
            asm volatile("ld.shared.v4.b32 {%0,%1,%2,%3}, [%4];"
                         : "=r"(vh.x), "=r"(vh.y), "=r"(vh.z), "=r"(vh.w)
                         : "r"(sh_hi + row * 64 + seg * 16));
            asm volatile("ld.shared.v4.b32 {%0,%1,%2,%3}, [%4];"
                         : "=r"(vl.x), "=r"(vl.y), "=r"(vl.z), "=r"(vl.w)
                         : "r"(sh_lo + row * 64 + seg * 16));
            size_t go = (size_t)(tg & 1) * NGRID * NH + (size_t)(rbase + row) * NH + nhat * 32 + seg * 8;
            *(uint4*)(g_hh + go) = vh;
            *(uint4*)(g_hl + go) = vl;
        }

        if (tl < CHUNK - 1) group_sync(rbk);
    }

    // spill c
#pragma unroll
    for (int mf = 0; mf < 2; mf++)
#pragma unroll
        for (int nf = 0; nf < 4; nf++) {
            int row = rbase + wm * 32 + mf * 16 + gid + (tig & 1) * 8;
            int h = nhat * 32 + wn * 8 + nf * 2 + (tig >> 1);
            g_c[row * NH + h] = creg[mf][nf];
        }
}

// ---------------- out = sum(32 partials) + b_out ----------------
__global__ __launch_bounds__(256) void k_out(const float* __restrict__ b_out,
                                             float* __restrict__ out) {
    size_t r = (size_t)blockIdx.x * 256 + threadIdx.x;
    const float4* p = (const float4*)(g_part + r * 32);
    float s = 0.f;
#pragma unroll
    for (int j = 0; j < 8; j++) {
        float4 v = p[j];
        s += v.x + v.y + v.z + v.w;
    }
    out[r] = s + b_out[0];
}

// ---------------- launch: fork/join overlap of xgt (s1) with scan (origin) ------
extern "C" void kernel_launch(void* const* d_in, const int* in_sizes, int n_in,
                              void* d_out, int out_size) {
    const float* x     = (const float*)d_in[0];
    const float* W_in  = (const float*)d_in[1];
    const float* b_in  = (const float*)d_in[2];
    const float* W_ih  = (const float*)d_in[3];
    const float* b_ih  = (const float*)d_in[4];
    const float* W_hh  = (const float*)d_in[5];
    const float* b_hh  = (const float*)d_in[6];
    const float* W_out = (const float*)d_in[7];
    const float* b_out = (const float*)d_in[8];
    float* out = (float*)d_out;

    static cudaStream_t s1 = nullptr;
    static cudaEvent_t evFork, exg[NCHUNK], escan[NCHUNK];
    if (!s1) {
        cudaFuncSetAttribute(k_xgt,  cudaFuncAttributeMaxDynamicSharedMemorySize, DSMEM);
        cudaFuncSetAttribute(k_scan, cudaFuncAttributeMaxDynamicSharedMemorySize, DSMEM);
        cudaStreamCreateWithFlags(&s1, cudaStreamNonBlocking);
        cudaEventCreateWithFlags(&evFork, cudaEventDisableTiming);
        for (int i = 0; i < NCHUNK; i++) {
            cudaEventCreateWithFlags(&exg[i], cudaEventDisableTiming);
            cudaEventCreateWithFlags(&escan[i], cudaEventDisableTiming);
        }
    }

    k_prep<<<(NG4 * NH + 255) / 256, 256>>>(W_in, W_ih, b_ih, b_hh, W_hh);
    k_x0<<<dim3(M_TOT / 128, NH / 128), 256>>>(x, b_in);

    // fork: xgt work goes to s1
    cudaEventRecord(evFork, 0);
    cudaStreamWaitEvent(s1, evFork, 0);
    k_xgt<<<dim3(8, 146), 512, DSMEM, s1>>>(0);
    cudaEventRecord(exg[0], s1);
    k_xgt<<<dim3(8, 146), 512, DSMEM, s1>>>(1);
    cudaEventRecord(exg[1], s1);

    for (int c = 0; c < NCHUNK; c++) {
        cudaStreamWaitEvent(0, exg[c], 0);
        k_scan<<<128, 512, DSMEM>>>(c, W_out);
        cudaEventRecord(escan[c], 0);
        if (c + 2 < NCHUNK) {
            // buffer (c+2)&1 == c&1 was read by scan(c); safe to overwrite after it
            cudaStreamWaitEvent(s1, escan[c], 0);
            k_xgt<<<dim3(8, 146), 512, DSMEM, s1>>>(c + 2);
            cudaEventRecord(exg[c + 2], s1);
        }
    }

    k_out<<<M_TOT / 256, 256>>>(b_out, out);
}

// round 11
// speedup vs baseline: 1.5024x; 1.0328x over previous
#include <cuda_runtime.h>
#include <cuda_bf16.h>
#include <math.h>
#include <stdint.h>

// ---------------- problem constants ----------------
#define NT    365
#define NGRID 2048
#define NX    32
#define NH    256
#define NG4   1024
#define M_TOT (NT * NGRID)        // 747520

// scan SMEM layout (dynamic):
//   Whh hi  [0, 64K)   Whh lo [64K, 128K)
//   STRM    [128K, 192K)  (x0 phase: x0h/x0l/WihH/WihL 16K each; h phase: 2x32K dbuf)
//   STAGE   [192K, 208K)  (h writeout staging)
#define WHHL_OFF  65536
#define STRM_OFF  131072
#define STAGE_OFF 196608
#define DSMEM     212992

// ---------------- device globals (~0.9 GB) ----------------
__device__ __nv_bfloat16 g_x0h[(size_t)M_TOT * NH];
__device__ __nv_bfloat16 g_x0l[(size_t)M_TOT * NH];
__device__ __nv_bfloat16 g_hh[2 * NGRID * NH];        // h ring hi
__device__ __nv_bfloat16 g_hl[2 * NGRID * NH];        // h ring lo
__device__ float g_part[(size_t)M_TOT * 32];
__device__ float g_WinT[NX * NH];
__device__ __nv_bfloat16 g_Wih_h[NG4 * NH], g_Wih_l[NG4 * NH];  // [c][k], c=h*4+g
__device__ __nv_bfloat16 g_Whh_h[NG4 * NH], g_Whh_l[NG4 * NH];
__device__ float g_biasr[NG4];
__device__ unsigned g_cnt[16 * 32];    // per-row-group progress counters (padded)

// ---------------- helpers ----------------
__device__ __forceinline__ float sigf(float x) { return 1.0f / (1.0f + expf(-x)); }

__device__ __forceinline__ uint32_t smem_u32(const void* p) {
    uint32_t a;
    asm("{ .reg .u64 t; cvta.to.shared.u64 t, %1; cvt.u32.u64 %0, t; }" : "=r"(a) : "l"(p));
    return a;
}
__device__ __forceinline__ uint32_t tadr(uint32_t tb, int row, int kcol) {
    uint32_t bo = (uint32_t)(row * 128 + kcol * 2);
    return tb + (bo ^ ((bo >> 3) & 0x70));
}
__device__ __forceinline__ void ldsm4(uint32_t* r, uint32_t addr) {
    asm volatile("ldmatrix.sync.aligned.m8n8.x4.shared.b16 {%0,%1,%2,%3}, [%4];"
                 : "=r"(r[0]), "=r"(r[1]), "=r"(r[2]), "=r"(r[3]) : "r"(addr));
}
__device__ __forceinline__ void mma16816(float* d, const uint32_t* a, const uint32_t* b) {
    asm volatile("mma.sync.aligned.m16n8k16.row.col.f32.bf16.bf16.f32 "
                 "{%0,%1,%2,%3}, {%4,%5,%6,%7}, {%8,%9}, {%0,%1,%2,%3};"
                 : "+f"(d[0]), "+f"(d[1]), "+f"(d[2]), "+f"(d[3])
                 : "r"(a[0]), "r"(a[1]), "r"(a[2]), "r"(a[3]), "r"(b[0]), "r"(b[1]));
}

// 512-thread tile movers: one 128x64 bf16 tile (row pitch 256 elems = 512B)
__device__ __forceinline__ void ldg_tile(uint4* R, const __nv_bfloat16* __restrict__ g, int tid) {
    const char* gp = (const char*)g;
#pragma unroll
    for (int j = 0; j < 2; j++) {
        int q = tid + j * 512;
        int row = q >> 3, ch = q & 7;
        R[j] = __ldcg((const uint4*)(gp + (size_t)row * 512 + ch * 16));
    }
}
__device__ __forceinline__ void sts_tile(uint32_t dst, const uint4* R, int tid) {
#pragma unroll
    for (int j = 0; j < 2; j++) {
        int q = tid + j * 512;
        int row = q >> 3, ch = q & 7;
        uint32_t bo = (uint32_t)(row * 128 + ch * 16);
        uint32_t off = dst + (bo ^ ((bo >> 3) & 0x70));
        asm volatile("st.shared.v4.b32 [%0], {%1,%2,%3,%4};"
                     :: "r"(off), "r"(R[j].x), "r"(R[j].y), "r"(R[j].z), "r"(R[j].w));
    }
}
__device__ __forceinline__ void ld_tile(uint32_t dst, const __nv_bfloat16* __restrict__ g, int tid) {
    uint4 R[2];
    ldg_tile(R, g, tid);
    sts_tile(dst, R, tid);
}
// cp.async version (global -> swizzled smem, no registers)
__device__ __forceinline__ void cpa_tile(uint32_t dst, const __nv_bfloat16* __restrict__ g, int tid) {
    const char* gp = (const char*)g;
#pragma unroll
    for (int j = 0; j < 2; j++) {
        int q = tid + j * 512;
        int row = q >> 3, ch = q & 7;
        uint32_t bo = (uint32_t)(row * 128 + ch * 16);
        uint32_t off = dst + (bo ^ ((bo >> 3) & 0x70));
        asm volatile("cp.async.cg.shared.global [%0], [%1], 16;"
                     :: "r"(off), "l"(gp + (size_t)row * 512 + ch * 16));
    }
}

// one 64-wide K chunk, warp tile 32x32: 3-term precision split, 4 k16 steps
__device__ __forceinline__ void mma_chunk(uint32_t abuf, uint32_t whi, uint32_t wlo,
                                          float acc[2][4][4], int mrow, int nbase,
                                          int rowAl, int kselA, int rowBl, int kselB) {
    uint32_t ahi = abuf, alo = abuf + 16384;
#pragma unroll
    for (int ks = 0; ks < 4; ks++) {
        int kA = ks * 16 + kselA, kB = ks * 16 + kselB;
        uint32_t Ah[2][4], Al[2][4], Wh[2][4], Wl[2][4];
#pragma unroll
        for (int mf = 0; mf < 2; mf++) {
            int row = mrow + mf * 16 + rowAl;
            ldsm4(Ah[mf], tadr(ahi, row, kA));
            ldsm4(Al[mf], tadr(alo, row, kA));
        }
#pragma unroll
        for (int np = 0; np < 2; np++) {
            int n = nbase + np * 16 + rowBl;
            ldsm4(Wh[np], tadr(whi, n, kB));
            ldsm4(Wl[np], tadr(wlo, n, kB));
        }
#pragma unroll
        for (int mf = 0; mf < 2; mf++)
#pragma unroll
            for (int nf = 0; nf < 4; nf++)
                mma16816(acc[mf][nf], Ah[mf], &Wh[nf >> 1][(nf & 1) * 2]);
#pragma unroll
        for (int mf = 0; mf < 2; mf++)
#pragma unroll
            for (int nf = 0; nf < 4; nf++)
                mma16816(acc[mf][nf], Al[mf], &Wh[nf >> 1][(nf & 1) * 2]);
#pragma unroll
        for (int mf = 0; mf < 2; mf++)
#pragma unroll
            for (int nf = 0; nf < 4; nf++)
                mma16816(acc[mf][nf], Ah[mf], &Wl[nf >> 1][(nf & 1) * 2]);
    }
}

// ---------------- prep ----------------
__global__ void k_prep(const float* __restrict__ W_in,
                       const float* __restrict__ W_ih,
                       const float* __restrict__ b_ih,
                       const float* __restrict__ b_hh,
                       const float* __restrict__ W_hh) {
    int i = blockIdx.x * blockDim.x + threadIdx.x;
    if (i < 16) g_cnt[i * 32] = 0;           // reset progress counters each launch
    if (i < NX * NH) {
        int k = i / NH, h = i % NH;
        g_WinT[k * NH + h] = W_in[h * NX + k];
    }
    if (i < NG4 * NH) {
        int c = i >> 8, k = i & 255;
        int h = c >> 2, g = c & 3;
        int n = g * NH + h;
        float wih = W_ih[n * NH + k];
        float whh = W_hh[n * NH + k];
        __nv_bfloat16 ih_h = __float2bfloat16(wih);
        __nv_bfloat16 hh_h = __float2bfloat16(whh);
        g_Wih_h[i] = ih_h;
        g_Wih_l[i] = __float2bfloat16(wih - __bfloat162float(ih_h));
        g_Whh_h[i] = hh_h;
        g_Whh_l[i] = __float2bfloat16(whh - __bfloat162float(hh_h));
    }
    if (i < NG4) {
        int h = i >> 2, g = i & 3;
        int n = g * NH + h;
        g_biasr[i] = b_ih[n] + b_hh[n];
    }
}

// ---------------- x0 = relu(x @ W_in^T + b_in) -> bf16 hi/lo ----------------
typedef unsigned long long u64t;
__device__ __forceinline__ u64t pk2(float lo, float hi) {
    u64t r; asm("mov.b64 %0, {%1, %2};" : "=l"(r) : "f"(lo), "f"(hi)); return r;
}
__device__ __forceinline__ float2 upk2(u64t v) {
    float2 r; asm("mov.b64 {%0, %1}, %2;" : "=f"(r.x), "=f"(r.y) : "l"(v)); return r;
}
#define FMA2(d, a, b) asm("fma.rn.f32x2 %0, %1, %2, %0;" : "+l"(d) : "l"(a), "l"(b))

__global__ __launch_bounds__(256, 1) void k_x0(const float* __restrict__ x,
                                               const float* __restrict__ b_in) {
    __shared__ float A_s[32][129];
    __shared__ float B_s[32][128];
    int tid = threadIdx.x;
    int r0 = blockIdx.x * 128;
    int c0 = blockIdx.y * 128;

    const float* Ag = x + (size_t)r0 * NX;
#pragma unroll
    for (int j = 0; j < 16; j++) {
        int idx = tid + j * 256;
        A_s[idx & 31][idx >> 5] = Ag[idx];
    }
#pragma unroll
    for (int j = 0; j < 16; j++) {
        int idx = tid + j * 256;
        int k = idx >> 7, col = idx & 127;
        B_s[k][col] = g_WinT[k * NH + c0 + col];
    }
    __syncthreads();

    int tx = tid & 7, ty = tid >> 3;
    int cb = tx * 16, rb = ty * 4;

    u64t acc[4][8];
#pragma unroll
    for (int p = 0; p < 8; p++) {
        u64t bp = pk2(b_in[c0 + cb + 2 * p], b_in[c0 + cb + 2 * p + 1]);
        acc[0][p] = bp; acc[1][p] = bp; acc[2][p] = bp; acc[3][p] = bp;
    }
#pragma unroll
    for (int kk = 0; kk < 32; kk++) {
        u64t a2[4];
#pragma unroll
        for (int i = 0; i < 4; i++) { float a = A_s[kk][rb + i]; a2[i] = pk2(a, a); }
        const u64t* bs = reinterpret_cast<const u64t*>(&B_s[kk][cb]);
        u64t b2[8];
#pragma unroll
        for (int p = 0; p < 8; p++) b2[p] = bs[p];
#pragma unroll
        for (int i = 0; i < 4; i++)
#pragma unroll
            for (int p = 0; p < 8; p++) FMA2(acc[i][p], a2[i], b2[p]);
    }
#pragma unroll
    for (int i = 0; i < 4; i++) {
        size_t r = (size_t)(r0 + rb + i);
        union { unsigned short s[16]; uint4 v[2]; } uh, ul;
#pragma unroll
        for (int p = 0; p < 8; p++) {
            float2 u = upk2(acc[i][p]);
            float f0 = fmaxf(u.x, 0.f), f1 = fmaxf(u.y, 0.f);
            __nv_bfloat16 h0 = __float2bfloat16(f0);
            __nv_bfloat16 h1 = __float2bfloat16(f1);
            __nv_bfloat16 l0 = __float2bfloat16(f0 - __bfloat162float(h0));
            __nv_bfloat16 l1 = __float2bfloat16(f1 - __bfloat162float(h1));
            uh.s[2 * p] = *(unsigned short*)&h0; uh.s[2 * p + 1] = *(unsigned short*)&h1;
            ul.s[2 * p] = *(unsigned short*)&l0; ul.s[2 * p + 1] = *(unsigned short*)&l1;
        }
        uint4* dh = (uint4*)(g_x0h + r * NH + c0 + cb);
        uint4* dl = (uint4*)(g_x0l + r * NH + c0 + cb);
        dh[0] = uh.v[0]; dh[1] = uh.v[1];
        dl[0] = ul.v[0]; dl[1] = ul.v[1];
    }
}

// ---------------- fused persistent scan: all 365 steps, xg GEMM inlined --------
__global__ __launch_bounds__(512, 1) void k_scan(const float* __restrict__ W_out) {
    extern __shared__ char sm[];
    __shared__ float Wout_s[NH];
    __shared__ float bias_s[128];
    uint32_t sb = smem_u32(sm);
    const uint32_t WHH_H = sb, WHH_L = sb + WHHL_OFF;
    const uint32_t STRM = sb + STRM_OFF, STAGE = sb + STAGE_OFF;

    int tid = threadIdx.x, lane = tid & 31, w = tid >> 5;
    int wm = w >> 2, wn = w & 3;
    int g8 = lane >> 3, r8 = lane & 7;
    int rowAl = (g8 & 1) * 8 + r8, kselA = (g8 >> 1) * 8;
    int rowBl = (g8 >> 1) * 8 + r8, kselB = (g8 & 1) * 8;
    int gid = lane >> 2, tig = lane & 3;
    int nhat = blockIdx.x & 7, rbk = blockIdx.x >> 3;
    int n0 = nhat * 128, rbase = rbk * 128;

    if (tid < NH) Wout_s[tid] = W_out[tid];
    if (tid < 128) bias_s[tid] = g_biasr[n0 + tid];
#pragma unroll
    for (int kt = 0; kt < 4; kt++) {
        ld_tile(WHH_H + kt * 16384, g_Whh_h + (size_t)n0 * NH + kt * 64, tid);
        ld_tile(WHH_L + kt * 16384, g_Whh_l + (size_t)n0 * NH + kt * 64, tid);
    }

    float creg[2][4];
#pragma unroll
    for (int mf = 0; mf < 2; mf++)
#pragma unroll
        for (int nf = 0; nf < 4; nf++) creg[mf][nf] = 0.f;
    __syncthreads();

    for (int tg = 0; tg < NT; tg++) {
        float acc[2][4][4];
#pragma unroll
        for (int a = 0; a < 2; a++)
#pragma unroll
            for (int b = 0; b < 4; b++)
#pragma unroll
                for (int c = 0; c < 4; c++) acc[a][b][c] = 0.f;

        // ---- x0 phase: acc += x0(tg) @ Wih^T  (no h dependency) ----
        {
            const __nv_bfloat16* x0h = g_x0h + ((size_t)tg * NGRID + rbase) * NH;
            const __nv_bfloat16* x0l = g_x0l + ((size_t)tg * NGRID + rbase) * NH;
#pragma unroll 1
            for (int kt = 0; kt < 4; kt++) {
                cpa_tile(STRM,         x0h + kt * 64, tid);
                cpa_tile(STRM + 16384, x0l + kt * 64, tid);
                cpa_tile(STRM + 32768, g_Wih_h + (size_t)n0 * NH + kt * 64, tid);
                cpa_tile(STRM + 49152, g_Wih_l + (size_t)n0 * NH + kt * 64, tid);
                asm volatile("cp.async.commit_group;" ::: "memory");
                asm volatile("cp.async.wait_group 0;" ::: "memory");
                __syncthreads();
                mma_chunk(STRM, STRM + 32768, STRM + 49152, acc,
                          wm * 32, wn * 32, rowAl, kselA, rowBl, kselB);
                __syncthreads();   // buffer reuse next kt
            }
        }

        // ---- h phase: acc += h(tg-1) @ Whh^T ----
        if (tg > 0) {
            if (tid == 0) {
                volatile unsigned* c = &g_cnt[rbk * 32];
                while (*c < 8u * (unsigned)tg) __nanosleep(20);
                __threadfence();
            }
            __syncthreads();
            const __nv_bfloat16* hh = g_hh + (size_t)((tg - 1) & 1) * NGRID * NH + (size_t)rbase * NH;
            const __nv_bfloat16* hl = g_hl + (size_t)((tg - 1) & 1) * NGRID * NH + (size_t)rbase * NH;
            uint4 R[4];
            ldg_tile(R,     hh, tid);
            ldg_tile(R + 2, hl, tid);
#pragma unroll 1
            for (int kt = 0; kt < 4; kt++) {
                uint32_t ab = STRM + (kt & 1) * 32768;
                sts_tile(ab, R, tid);
                sts_tile(ab + 16384, R + 2, tid);
                if (kt < 3) {
                    ldg_tile(R,     hh + (kt + 1) * 64, tid);
                    ldg_tile(R + 2, hl + (kt + 1) * 64, tid);
                }
                __syncthreads();
                mma_chunk(ab, WHH_H + kt * 16384, WHH_L + kt * 16384, acc,
                          wm * 32, wn * 32, rowAl, kselA, rowBl, kselB);
            }
        }

        // ---- epilogue: gates -> cell update; stage h tile; out partials ----
        __syncthreads();
#pragma unroll
        for (int mf = 0; mf < 2; mf++) {
            int rloc = wm * 32 + mf * 16 + gid + (tig & 1) * 8;
            int row = rbase + rloc;
            float pout = 0.f;
#pragma unroll
            for (int nf = 0; nf < 4; nf++) {
                float c0 = acc[mf][nf][0], c1 = acc[mf][nf][1];
                float c2 = acc[mf][nf][2], c3 = acc[mf][nf][3];
                float s0 = (lane & 1) ? c0 : c2;
                float s1 = (lane & 1) ? c1 : c3;
                float r0 = __shfl_xor_sync(0xffffffffu, s0, 1);
                float r1 = __shfl_xor_sync(0xffffffffu, s1, 1);
                float gi, gf, gg, go;
                if (!(lane & 1)) { gi = c0; gf = c1; gg = r0; go = r1; }
                else             { gi = r0; gf = r1; gg = c2; go = c3; }
                int hl_i = wn * 8 + nf * 2 + (tig >> 1);
                float4 bv = *(const float4*)&bias_s[hl_i * 4];
                float iv = gi + bv.x, fv = gf + bv.y, gv = gg + bv.z, ov = go + bv.w;
                float cn = sigf(fv) * creg[mf][nf] + sigf(iv) * tanhf(gv);
                creg[mf][nf] = cn;
                float hv = sigf(ov) * tanhf(cn);
                pout += hv * Wout_s[nhat * 32 + hl_i];
                __nv_bfloat16 bh = __float2bfloat16(hv);
                __nv_bfloat16 bl = __float2bfloat16(hv - __bfloat162float(bh));
                uint32_t so = (uint32_t)(rloc * 64 + hl_i * 2);
                asm volatile("st.shared.u16 [%0], %1;" :: "r"(STAGE + so), "h"(*(unsigned short*)&bh));
                asm volatile("st.shared.u16 [%0], %1;" :: "r"(STAGE + 8192 + so), "h"(*(unsigned short*)&bl));
            }
            float pr = pout + __shfl_xor_sync(0xffffffffu, pout, 2);
            if ((tig >> 1) == 0)
                g_part[((size_t)tg * NGRID + row) * 32 + nhat * 4 + wn] = pr;
        }
        __syncthreads();

        // coalesced h writeout: 128 rows x 32 cols hi/lo
        {
            int row = tid >> 2, seg = tid & 3;
            uint4 vh, vl;
            asm volatile("ld.shared.v4.b32 {%0,%1,%2,%3}, [%4];"
                         : "=r"(vh.x), "=r"(vh.y), "=r"(vh.z), "=r"(vh.w)
                         : "r"(STAGE + row * 64 + seg * 16));
            asm volatile("ld.shared.v4.b32 {%0,%1,%2,%3}, [%4];"
                         : "=r"(vl.x), "=r"(vl.y), "=r"(vl.z), "=r"(vl.w)
                         : "r"(STAGE + 8192 + row * 64 + seg * 16));
            size_t go = (size_t)(tg & 1) * NGRID * NH + (size_t)(rbase + row) * NH + nhat * 32 + seg * 8;
            *(uint4*)(g_hh + go) = vh;
            *(uint4*)(g_hl + go) = vl;
        }
        __syncthreads();
        if (tid == 0) {
            __threadfence();
            atomicAdd(&g_cnt[rbk * 32], 1u);
        }
    }
}

// ---------------- out = sum(32 partials) + b_out ----------------
__global__ __launch_bounds__(256) void k_out(const float* __restrict__ b_out,
                                             float* __restrict__ out) {
    size_t r = (size_t)blockIdx.x * 256 + threadIdx.x;
    const float4* p = (const float4*)(g_part + r * 32);
    float s = 0.f;
#pragma unroll
    for (int j = 0; j < 8; j++) {
        float4 v = p[j];
        s += v.x + v.y + v.z + v.w;
    }
    out[r] = s + b_out[0];
}

// ---------------- launch ----------------
extern "C" void kernel_launch(void* const* d_in, const int* in_sizes, int n_in,
                              void* d_out, int out_size) {
    const float* x     = (const float*)d_in[0];
    const float* W_in  = (const float*)d_in[1];
    const float* b_in  = (const float*)d_in[2];
    const float* W_ih  = (const float*)d_in[3];
    const float* b_ih  = (const float*)d_in[4];
    const float* W_hh  = (const float*)d_in[5];
    const float* b_hh  = (const float*)d_in[6];
    const float* W_out = (const float*)d_in[7];
    const float* b_out = (const float*)d_in[8];
    float* out = (float*)d_out;

    static int attr_done = 0;
    if (!attr_done) {
        cudaFuncSetAttribute(k_scan, cudaFuncAttributeMaxDynamicSharedMemorySize, DSMEM);
        attr_done = 1;
    }

    k_prep<<<(NG4 * NH + 255) / 256, 256>>>(W_in, W_ih, b_ih, b_hh, W_hh);
    k_x0<<<dim3(M_TOT / 128, NH / 128), 256>>>(x, b_in);
    k_scan<<<128, 512, DSMEM>>>(W_out);
    k_out<<<M_TOT / 256, 256>>>(b_out, out);
}

// round 12
// speedup vs baseline: 1.5543x; 1.0345x over previous
#include <cuda_runtime.h>
#include <cuda_bf16.h>
#include <math.h>
#include <stdint.h>

// ---------------- problem constants ----------------
#define NT    365
#define NGRID 2048
#define NX    32
#define NH    256
#define NG4   1024
#define M_TOT (NT * NGRID)        // 747520

// scan SMEM layout (dynamic):
//   WHH_HI  [0, 64K)                resident Whh hi (4 kt x 16K)
//   STRM    [64K, 192K)             2 x 64K parity bufs {x0h,x0l,wihh,wihl}
//                                   h phase: A dbuf = STRM[0,64K); Whh_lo ring
//                                   at STRM+98304 / STRM+114688
//   STAGE   [192K, 208K)
#define STRM_OFF  65536
#define STAGE_OFF 196608
#define DSMEM     212992

// ---------------- device globals (~0.9 GB) ----------------
__device__ __nv_bfloat16 g_x0h[(size_t)M_TOT * NH];
__device__ __nv_bfloat16 g_x0l[(size_t)M_TOT * NH];
__device__ __nv_bfloat16 g_hh[2 * NGRID * NH];        // h ring hi
__device__ __nv_bfloat16 g_hl[2 * NGRID * NH];        // h ring lo
__device__ float g_part[(size_t)M_TOT * 32];
__device__ float g_WinT[NX * NH];
__device__ __nv_bfloat16 g_Wih_h[NG4 * NH], g_Wih_l[NG4 * NH];  // [c][k], c=h*4+g
__device__ __nv_bfloat16 g_Whh_h[NG4 * NH], g_Whh_l[NG4 * NH];
__device__ float g_biasr[NG4];
__device__ unsigned g_cnt[16 * 32];    // per-row-group progress counters (padded)

// ---------------- helpers ----------------
__device__ __forceinline__ float sigf(float x) { return 1.0f / (1.0f + expf(-x)); }

__device__ __forceinline__ uint32_t smem_u32(const void* p) {
    uint32_t a;
    asm("{ .reg .u64 t; cvta.to.shared.u64 t, %1; cvt.u32.u64 %0, t; }" : "=r"(a) : "l"(p));
    return a;
}
__device__ __forceinline__ uint32_t tadr(uint32_t tb, int row, int kcol) {
    uint32_t bo = (uint32_t)(row * 128 + kcol * 2);
    return tb + (bo ^ ((bo >> 3) & 0x70));
}
__device__ __forceinline__ void ldsm4(uint32_t* r, uint32_t addr) {
    asm volatile("ldmatrix.sync.aligned.m8n8.x4.shared.b16 {%0,%1,%2,%3}, [%4];"
                 : "=r"(r[0]), "=r"(r[1]), "=r"(r[2]), "=r"(r[3]) : "r"(addr));
}
__device__ __forceinline__ void mma16816(float* d, const uint32_t* a, const uint32_t* b) {
    asm volatile("mma.sync.aligned.m16n8k16.row.col.f32.bf16.bf16.f32 "
                 "{%0,%1,%2,%3}, {%4,%5,%6,%7}, {%8,%9}, {%0,%1,%2,%3};"
                 : "+f"(d[0]), "+f"(d[1]), "+f"(d[2]), "+f"(d[3])
                 : "r"(a[0]), "r"(a[1]), "r"(a[2]), "r"(a[3]), "r"(b[0]), "r"(b[1]));
}

// 512-thread tile movers: one 128x64 bf16 tile (row pitch 256 elems = 512B)
__device__ __forceinline__ void ldg_tile(uint4* R, const __nv_bfloat16* __restrict__ g, int tid) {
    const char* gp = (const char*)g;
#pragma unroll
    for (int j = 0; j < 2; j++) {
        int q = tid + j * 512;
        int row = q >> 3, ch = q & 7;
        R[j] = __ldcg((const uint4*)(gp + (size_t)row * 512 + ch * 16));
    }
}
__device__ __forceinline__ void sts_tile(uint32_t dst, const uint4* R, int tid) {
#pragma unroll
    for (int j = 0; j < 2; j++) {
        int q = tid + j * 512;
        int row = q >> 3, ch = q & 7;
        uint32_t bo = (uint32_t)(row * 128 + ch * 16);
        uint32_t off = dst + (bo ^ ((bo >> 3) & 0x70));
        asm volatile("st.shared.v4.b32 [%0], {%1,%2,%3,%4};"
                     :: "r"(off), "r"(R[j].x), "r"(R[j].y), "r"(R[j].z), "r"(R[j].w));
    }
}
__device__ __forceinline__ void ld_tile(uint32_t dst, const __nv_bfloat16* __restrict__ g, int tid) {
    uint4 R[2];
    ldg_tile(R, g, tid);
    sts_tile(dst, R, tid);
}
// cp.async version (global -> swizzled smem)
__device__ __forceinline__ void cpa_tile(uint32_t dst, const __nv_bfloat16* __restrict__ g, int tid) {
    const char* gp = (const char*)g;
#pragma unroll
    for (int j = 0; j < 2; j++) {
        int q = tid + j * 512;
        int row = q >> 3, ch = q & 7;
        uint32_t bo = (uint32_t)(row * 128 + ch * 16);
        uint32_t off = dst + (bo ^ ((bo >> 3) & 0x70));
        asm volatile("cp.async.cg.shared.global [%0], [%1], 16;"
                     :: "r"(off), "l"(gp + (size_t)row * 512 + ch * 16));
    }
}
#define CPA_COMMIT() asm volatile("cp.async.commit_group;" ::: "memory")
#define CPA_WAIT0()  asm volatile("cp.async.wait_group 0;" ::: "memory")

// issue full x0-phase kt package {x0h, x0l, wihh, wihl} into a 64K parity buffer
__device__ __forceinline__ void issue_x0(uint32_t P,
                                         const __nv_bfloat16* __restrict__ x0h,
                                         const __nv_bfloat16* __restrict__ x0l,
                                         int n0, int kt, int tid) {
    cpa_tile(P,         x0h + kt * 64, tid);
    cpa_tile(P + 16384, x0l + kt * 64, tid);
    cpa_tile(P + 32768, g_Wih_h + (size_t)n0 * NH + kt * 64, tid);
    cpa_tile(P + 49152, g_Wih_l + (size_t)n0 * NH + kt * 64, tid);
    CPA_COMMIT();
}

// 64-wide K chunk, warp tile 32x32: all 3 terms (x0 phase; all tiles present)
__device__ __forceinline__ void mma_chunk(uint32_t abuf, uint32_t whi, uint32_t wlo,
                                          float acc[2][4][4], int mrow, int nbase,
                                          int rowAl, int kselA, int rowBl, int kselB) {
    uint32_t ahi = abuf, alo = abuf + 16384;
#pragma unroll
    for (int ks = 0; ks < 4; ks++) {
        int kA = ks * 16 + kselA, kB = ks * 16 + kselB;
        uint32_t Ah[2][4], Al[2][4], Wh[2][4], Wl[2][4];
#pragma unroll
        for (int mf = 0; mf < 2; mf++) {
            int row = mrow + mf * 16 + rowAl;
            ldsm4(Ah[mf], tadr(ahi, row, kA));
            ldsm4(Al[mf], tadr(alo, row, kA));
        }
#pragma unroll
        for (int np = 0; np < 2; np++) {
            int n = nbase + np * 16 + rowBl;
            ldsm4(Wh[np], tadr(whi, n, kB));
            ldsm4(Wl[np], tadr(wlo, n, kB));
        }
#pragma unroll
        for (int mf = 0; mf < 2; mf++)
#pragma unroll
            for (int nf = 0; nf < 4; nf++)
                mma16816(acc[mf][nf], Ah[mf], &Wh[nf >> 1][(nf & 1) * 2]);
#pragma unroll
        for (int mf = 0; mf < 2; mf++)
#pragma unroll
            for (int nf = 0; nf < 4; nf++)
                mma16816(acc[mf][nf], Al[mf], &Wh[nf >> 1][(nf & 1) * 2]);
#pragma unroll
        for (int mf = 0; mf < 2; mf++)
#pragma unroll
            for (int nf = 0; nf < 4; nf++)
                mma16816(acc[mf][nf], Ah[mf], &Wl[nf >> 1][(nf & 1) * 2]);
    }
}

// h phase: terms 1+2 against resident Whh_hi
__device__ __forceinline__ void mma_h12(uint32_t abuf, uint32_t whi,
                                        float acc[2][4][4], int mrow, int nbase,
                                        int rowAl, int kselA, int rowBl, int kselB) {
    uint32_t ahi = abuf, alo = abuf + 16384;
#pragma unroll
    for (int ks = 0; ks < 4; ks++) {
        int kA = ks * 16 + kselA, kB = ks * 16 + kselB;
        uint32_t Ah[2][4], Al[2][4], Wh[2][4];
#pragma unroll
        for (int mf = 0; mf < 2; mf++) {
            int row = mrow + mf * 16 + rowAl;
            ldsm4(Ah[mf], tadr(ahi, row, kA));
            ldsm4(Al[mf], tadr(alo, row, kA));
        }
#pragma unroll
        for (int np = 0; np < 2; np++) {
            int n = nbase + np * 16 + rowBl;
            ldsm4(Wh[np], tadr(whi, n, kB));
        }
#pragma unroll
        for (int mf = 0; mf < 2; mf++)
#pragma unroll
            for (int nf = 0; nf < 4; nf++)
                mma16816(acc[mf][nf], Ah[mf], &Wh[nf >> 1][(nf & 1) * 2]);
#pragma unroll
        for (int mf = 0; mf < 2; mf++)
#pragma unroll
            for (int nf = 0; nf < 4; nf++)
                mma16816(acc[mf][nf], Al[mf], &Wh[nf >> 1][(nf & 1) * 2]);
    }
}

// h phase: term 3 against streamed Whh_lo
__device__ __forceinline__ void mma_h3(uint32_t abuf, uint32_t wlo,
                                       float acc[2][4][4], int mrow, int nbase,
                                       int rowAl, int kselA, int rowBl, int kselB) {
    uint32_t ahi = abuf;
#pragma unroll
    for (int ks = 0; ks < 4; ks++) {
        int kA = ks * 16 + kselA, kB = ks * 16 + kselB;
        uint32_t Ah[2][4], Wl[2][4];
#pragma unroll
        for (int mf = 0; mf < 2; mf++)
            ldsm4(Ah[mf], tadr(ahi, mrow + mf * 16 + rowAl, kA));
#pragma unroll
        for (int np = 0; np < 2; np++)
            ldsm4(Wl[np], tadr(wlo, nbase + np * 16 + rowBl, kB));
#pragma unroll
        for (int mf = 0; mf < 2; mf++)
#pragma unroll
            for (int nf = 0; nf < 4; nf++)
                mma16816(acc[mf][nf], Ah[mf], &Wl[nf >> 1][(nf & 1) * 2]);
    }
}

// ---------------- prep ----------------
__global__ void k_prep(const float* __restrict__ W_in,
                       const float* __restrict__ W_ih,
                       const float* __restrict__ b_ih,
                       const float* __restrict__ b_hh,
                       const float* __restrict__ W_hh) {
    int i = blockIdx.x * blockDim.x + threadIdx.x;
    if (i < 16) g_cnt[i * 32] = 0;
    if (i < NX * NH) {
        int k = i / NH, h = i % NH;
        g_WinT[k * NH + h] = W_in[h * NX + k];
    }
    if (i < NG4 * NH) {
        int c = i >> 8, k = i & 255;
        int h = c >> 2, g = c & 3;
        int n = g * NH + h;
        float wih = W_ih[n * NH + k];
        float whh = W_hh[n * NH + k];
        __nv_bfloat16 ih_h = __float2bfloat16(wih);
        __nv_bfloat16 hh_h = __float2bfloat16(whh);
        g_Wih_h[i] = ih_h;
        g_Wih_l[i] = __float2bfloat16(wih - __bfloat162float(ih_h));
        g_Whh_h[i] = hh_h;
        g_Whh_l[i] = __float2bfloat16(whh - __bfloat162float(hh_h));
    }
    if (i < NG4) {
        int h = i >> 2, g = i & 3;
        int n = g * NH + h;
        g_biasr[i] = b_ih[n] + b_hh[n];
    }
}

// ---------------- x0 = relu(x @ W_in^T + b_in) -> bf16 hi/lo ----------------
typedef unsigned long long u64t;
__device__ __forceinline__ u64t pk2(float lo, float hi) {
    u64t r; asm("mov.b64 %0, {%1, %2};" : "=l"(r) : "f"(lo), "f"(hi)); return r;
}
__device__ __forceinline__ float2 upk2(u64t v) {
    float2 r; asm("mov.b64 {%0, %1}, %2;" : "=f"(r.x), "=f"(r.y) : "l"(v)); return r;
}
#define FMA2(d, a, b) asm("fma.rn.f32x2 %0, %1, %2, %0;" : "+l"(d) : "l"(a), "l"(b))

__global__ __launch_bounds__(256, 1) void k_x0(const float* __restrict__ x,
                                               const float* __restrict__ b_in) {
    __shared__ float A_s[32][129];
    __shared__ float B_s[32][128];
    int tid = threadIdx.x;
    int r0 = blockIdx.x * 128;
    int c0 = blockIdx.y * 128;

    const float* Ag = x + (size_t)r0 * NX;
#pragma unroll
    for (int j = 0; j < 16; j++) {
        int idx = tid + j * 256;
        A_s[idx & 31][idx >> 5] = Ag[idx];
    }
#pragma unroll
    for (int j = 0; j < 16; j++) {
        int idx = tid + j * 256;
        int k = idx >> 7, col = idx & 127;
        B_s[k][col] = g_WinT[k * NH + c0 + col];
    }
    __syncthreads();

    int tx = tid & 7, ty = tid >> 3;
    int cb = tx * 16, rb = ty * 4;

    u64t acc[4][8];
#pragma unroll
    for (int p = 0; p < 8; p++) {
        u64t bp = pk2(b_in[c0 + cb + 2 * p], b_in[c0 + cb + 2 * p + 1]);
        acc[0][p] = bp; acc[1][p] = bp; acc[2][p] = bp; acc[3][p] = bp;
    }
#pragma unroll
    for (int kk = 0; kk < 32; kk++) {
        u64t a2[4];
#pragma unroll
        for (int i = 0; i < 4; i++) { float a = A_s[kk][rb + i]; a2[i] = pk2(a, a); }
        const u64t* bs = reinterpret_cast<const u64t*>(&B_s[kk][cb]);
        u64t b2[8];
#pragma unroll
        for (int p = 0; p < 8; p++) b2[p] = bs[p];
#pragma unroll
        for (int i = 0; i < 4; i++)
#pragma unroll
            for (int p = 0; p < 8; p++) FMA2(acc[i][p], a2[i], b2[p]);
    }
#pragma unroll
    for (int i = 0; i < 4; i++) {
        size_t r = (size_t)(r0 + rb + i);
        union { unsigned short s[16]; uint4 v[2]; } uh, ul;
#pragma unroll
        for (int p = 0; p < 8; p++) {
            float2 u = upk2(acc[i][p]);
            float f0 = fmaxf(u.x, 0.f), f1 = fmaxf(u.y, 0.f);
            __nv_bfloat16 h0 = __float2bfloat16(f0);
            __nv_bfloat16 h1 = __float2bfloat16(f1);
            __nv_bfloat16 l0 = __float2bfloat16(f0 - __bfloat162float(h0));
            __nv_bfloat16 l1 = __float2bfloat16(f1 - __bfloat162float(h1));
            uh.s[2 * p] = *(unsigned short*)&h0; uh.s[2 * p + 1] = *(unsigned short*)&h1;
            ul.s[2 * p] = *(unsigned short*)&l0; ul.s[2 * p + 1] = *(unsigned short*)&l1;
        }
        uint4* dh = (uint4*)(g_x0h + r * NH + c0 + cb);
        uint4* dl = (uint4*)(g_x0l + r * NH + c0 + cb);
        dh[0] = uh.v[0]; dh[1] = uh.v[1];
        dl[0] = ul.v[0]; dl[1] = ul.v[1];
    }
}

// ---------------- fused persistent scan, pipelined streams ----------------
__global__ __launch_bounds__(512, 1) void k_scan(const float* __restrict__ W_out) {
    extern __shared__ char sm[];
    __shared__ float Wout_s[NH];
    __shared__ float bias_s[128];
    uint32_t sb = smem_u32(sm);
    const uint32_t WHH = sb;                       // resident Whh_hi (64K)
    const uint32_t STRM = sb + STRM_OFF;           // 128K stream region
    const uint32_t STAGE = sb + STAGE_OFF;

    int tid = threadIdx.x, lane = tid & 31, w = tid >> 5;
    int wm = w >> 2, wn = w & 3;
    int g8 = lane >> 3, r8 = lane & 7;
    int rowAl = (g8 & 1) * 8 + r8, kselA = (g8 >> 1) * 8;
    int rowBl = (g8 >> 1) * 8 + r8, kselB = (g8 & 1) * 8;
    int gid = lane >> 2, tig = lane & 3;
    int nhat = blockIdx.x & 7, rbk = blockIdx.x >> 3;
    int n0 = nhat * 128, rbase = rbk * 128;

    if (tid < NH) Wout_s[tid] = W_out[tid];
    if (tid < 128) bias_s[tid] = g_biasr[n0 + tid];
#pragma unroll
    for (int kt = 0; kt < 4; kt++)
        ld_tile(WHH + kt * 16384, g_Whh_h + (size_t)n0 * NH + kt * 64, tid);

    float creg[2][4];
#pragma unroll
    for (int mf = 0; mf < 2; mf++)
#pragma unroll
        for (int nf = 0; nf < 4; nf++) creg[mf][nf] = 0.f;
    __syncthreads();

    // prefetch step-0 kt0 package into parity0
    issue_x0(STRM, g_x0h + (size_t)rbase * NH, g_x0l + (size_t)rbase * NH, n0, 0, tid);

    for (int tg = 0; tg < NT; tg++) {
        const __nv_bfloat16* x0h = g_x0h + ((size_t)tg * NGRID + rbase) * NH;
        const __nv_bfloat16* x0l = g_x0l + ((size_t)tg * NGRID + rbase) * NH;

        float acc[2][4][4];
#pragma unroll
        for (int a = 0; a < 2; a++)
#pragma unroll
            for (int b = 0; b < 4; b++)
#pragma unroll
                for (int c = 0; c < 4; c++) acc[a][b][c] = 0.f;

        // ---- x0 phase: pipelined (kt+1 in flight during kt's MMA) ----
#pragma unroll 1
        for (int kt = 0; kt < 4; kt++) {
            uint32_t P = STRM + (uint32_t)(kt & 1) * 65536;
            CPA_WAIT0();
            __syncthreads();
            if (kt < 3)
                issue_x0(STRM + (uint32_t)((kt + 1) & 1) * 65536, x0h, x0l, n0, kt + 1, tid);
            mma_chunk(P, P + 32768, P + 49152, acc,
                      wm * 32, wn * 32, rowAl, kselA, rowBl, kselB);
        }

        // ---- h phase: resident Whh_hi (T1,T2) + streamed Whh_lo ring (T3) ----
        if (tg > 0) {
            if (tid == 0) {
                volatile unsigned* c = &g_cnt[rbk * 32];
                while (*c < 8u * (unsigned)tg) __nanosleep(20);
                __threadfence();
            }
            __syncthreads();   // also: all warps done with x0-phase kt3 mma

            // Whh_lo ring slots (inside parity1's upper half, consumed by kt3)
            const uint32_t WL0 = STRM + 98304, WL1 = STRM + 114688;
            cpa_tile(WL0, g_Whh_l + (size_t)n0 * NH, tid);
            CPA_COMMIT();

            const __nv_bfloat16* hh = g_hh + (size_t)((tg - 1) & 1) * NGRID * NH + (size_t)rbase * NH;
            const __nv_bfloat16* hl = g_hl + (size_t)((tg - 1) & 1) * NGRID * NH + (size_t)rbase * NH;
            uint4 R[4];
            ldg_tile(R,     hh, tid);
            ldg_tile(R + 2, hl, tid);
#pragma unroll 1
            for (int kt = 0; kt < 4; kt++) {
                uint32_t ab = STRM + (uint32_t)(kt & 1) * 32768;   // A dbuf in parity0
                sts_tile(ab, R, tid);
                sts_tile(ab + 16384, R + 2, tid);
                if (kt < 3) {
                    ldg_tile(R,     hh + (kt + 1) * 64, tid);
                    ldg_tile(R + 2, hl + (kt + 1) * 64, tid);
                }
                __syncthreads();
                mma_h12(ab, WHH + kt * 16384, acc,
                        wm * 32, wn * 32, rowAl, kselA, rowBl, kselB);
                CPA_WAIT0();
                __syncthreads();
                if (kt < 3) {
                    cpa_tile((kt & 1) ? WL0 : WL1,
                             g_Whh_l + (size_t)n0 * NH + (kt + 1) * 64, tid);
                    CPA_COMMIT();
                }
                mma_h3(ab, (kt & 1) ? WL1 : WL0, acc,
                       wm * 32, wn * 32, rowAl, kselA, rowBl, kselB);
            }
        }

        __syncthreads();   // stream region fully consumed; stage safe

        // prefetch next step's kt0 package (lands during epilogue/writeout)
        if (tg + 1 < NT)
            issue_x0(STRM, x0h + (size_t)NGRID * NH, x0l + (size_t)NGRID * NH, n0, 0, tid);

        // ---- epilogue: gates -> cell update; stage h tile; out partials ----
#pragma unroll
        for (int mf = 0; mf < 2; mf++) {
            int rloc = wm * 32 + mf * 16 + gid + (tig & 1) * 8;
            int row = rbase + rloc;
            float pout = 0.f;
#pragma unroll
            for (int nf = 0; nf < 4; nf++) {
                float c0 = acc[mf][nf][0], c1 = acc[mf][nf][1];
                float c2 = acc[mf][nf][2], c3 = acc[mf][nf][3];
                float s0 = (lane & 1) ? c0 : c2;
                float s1 = (lane & 1) ? c1 : c3;
                float r0 = __shfl_xor_sync(0xffffffffu, s0, 1);
                float r1 = __shfl_xor_sync(0xffffffffu, s1, 1);
                float gi, gf, gg, go;
                if (!(lane & 1)) { gi = c0; gf = c1; gg = r0; go = r1; }
                else             { gi = r0; gf = r1; gg = c2; go = c3; }
                int hl_i = wn * 8 + nf * 2 + (tig >> 1);
                float4 bv = *(const float4*)&bias_s[hl_i * 4];
                float iv = gi + bv.x, fv = gf + bv.y, gv = gg + bv.z, ov = go + bv.w;
                float cn = sigf(fv) * creg[mf][nf] + sigf(iv) * tanhf(gv);
                creg[mf][nf] = cn;
                float hv = sigf(ov) * tanhf(cn);
                pout += hv * Wout_s[nhat * 32 + hl_i];
                __nv_bfloat16 bh = __float2bfloat16(hv);
                __nv_bfloat16 bl = __float2bfloat16(hv - __bfloat162float(bh));
                uint32_t so = (uint32_t)(rloc * 64 + hl_i * 2);
                asm volatile("st.shared.u16 [%0], %1;" :: "r"(STAGE + so), "h"(*(unsigned short*)&bh));
                asm volatile("st.shared.u16 [%0], %1;" :: "r"(STAGE + 8192 + so), "h"(*(unsigned short*)&bl));
            }
            float pr = pout + __shfl_xor_sync(0xffffffffu, pout, 2);
            if ((tig >> 1) == 0)
                g_part[((size_t)tg * NGRID + row) * 32 + nhat * 4 + wn] = pr;
        }
        __syncthreads();

        // coalesced h writeout: 128 rows x 32 cols hi/lo
        {
            int row = tid >> 2, seg = tid & 3;
            uint4 vh, vl;
            asm volatile("ld.shared.v4.b32 {%0,%1,%2,%3}, [%4];"
                         : "=r"(vh.x), "=r"(vh.y), "=r"(vh.z), "=r"(vh.w)
                         : "r"(STAGE + row * 64 + seg * 16));
            asm volatile("ld.shared.v4.b32 {%0,%1,%2,%3}, [%4];"
                         : "=r"(vl.x), "=r"(vl.y), "=r"(vl.z), "=r"(vl.w)
                         : "r"(STAGE + 8192 + row * 64 + seg * 16));
            size_t go = (size_t)(tg & 1) * NGRID * NH + (size_t)(rbase + row) * NH + nhat * 32 + seg * 8;
            *(uint4*)(g_hh + go) = vh;
            *(uint4*)(g_hl + go) = vl;
        }
        __syncthreads();
        if (tid == 0) {
            __threadfence();
            atomicAdd(&g_cnt[rbk * 32], 1u);
        }
    }
}

// ---------------- out = sum(32 partials) + b_out ----------------
__global__ __launch_bounds__(256) void k_out(const float* __restrict__ b_out,
                                             float* __restrict__ out) {
    size_t r = (size_t)blockIdx.x * 256 + threadIdx.x;
    const float4* p = (const float4*)(g_part + r * 32);
    float s = 0.f;
#pragma unroll
    for (int j = 0; j < 8; j++) {
        float4 v = p[j];
        s += v.x + v.y + v.z + v.w;
    }
    out[r] = s + b_out[0];
}

// ---------------- launch ----------------
extern "C" void kernel_launch(void* const* d_in, const int* in_sizes, int n_in,
                              void* d_out, int out_size) {
    const float* x     = (const float*)d_in[0];
    const float* W_in  = (const float*)d_in[1];
    const float* b_in  = (const float*)d_in[2];
    const float* W_ih  = (const float*)d_in[3];
    const float* b_ih  = (const float*)d_in[4];
    const float* W_hh  = (const float*)d_in[5];
    const float* b_hh  = (const float*)d_in[6];
    const float* W_out = (const float*)d_in[7];
    const float* b_out = (const float*)d_in[8];
    float* out = (float*)d_out;

    static int attr_done = 0;
    if (!attr_done) {
        cudaFuncSetAttribute(k_scan, cudaFuncAttributeMaxDynamicSharedMemorySize, DSMEM);
        attr_done = 1;
    }

    k_prep<<<(NG4 * NH + 255) / 256, 256>>>(W_in, W_ih, b_ih, b_hh, W_hh);
    k_x0<<<dim3(M_TOT / 128, NH / 128), 256>>>(x, b_in);
    k_scan<<<128, 512, DSMEM>>>(W_out);
    k_out<<<M_TOT / 256, 256>>>(b_out, out);
}

// round 13
// speedup vs baseline: 1.6319x; 1.0500x over previous
#include <cuda_runtime.h>
#include <cuda_bf16.h>
#include <math.h>
#include <stdint.h>

// ---------------- problem constants ----------------
#define NT    365
#define NGRID 2048
#define NX    32
#define NH    256
#define NG4   1024
#define M_TOT (NT * NGRID)        // 747520

// scan SMEM layout (dynamic):
//   WHH_HI  [0, 64K)                resident Whh hi (4 kt x 16K)
//   STRM    [64K, 192K)             2 x 64K parity bufs {x0h,x0l,wihh,wihl}
//                                   h phase: A dbuf = STRM[0,64K); Whh_lo ring
//                                   at STRM+98304 / STRM+114688
//   STAGE   [192K, 208K)
#define STRM_OFF  65536
#define STAGE_OFF 196608
#define DSMEM     212992

// ---------------- device globals (~0.9 GB) ----------------
__device__ __nv_bfloat16 g_x0h[(size_t)M_TOT * NH];
__device__ __nv_bfloat16 g_x0l[(size_t)M_TOT * NH];
__device__ __nv_bfloat16 g_hh[2 * NGRID * NH];        // h ring hi
__device__ __nv_bfloat16 g_hl[2 * NGRID * NH];        // h ring lo
__device__ float g_part[(size_t)M_TOT * 32];
__device__ float g_WinT[NX * NH];
__device__ __nv_bfloat16 g_Wih_h[NG4 * NH], g_Wih_l[NG4 * NH];  // [c][k], c=h*4+g
__device__ __nv_bfloat16 g_Whh_h[NG4 * NH], g_Whh_l[NG4 * NH];
__device__ float g_biasr[NG4];
__device__ unsigned g_cnt[16 * 32];    // per-row-group progress counters (padded)

// ---------------- helpers ----------------
// fast sigmoid / tanh: __expf rel-err ~2^-21 -> gate-level error ~1e-6 (safe)
__device__ __forceinline__ float sigf(float x) {
    return __fdividef(1.0f, 1.0f + __expf(-x));
}
__device__ __forceinline__ float tanhfast(float x) {
    return 2.0f * sigf(2.0f * x) - 1.0f;
}

__device__ __forceinline__ uint32_t smem_u32(const void* p) {
    uint32_t a;
    asm("{ .reg .u64 t; cvta.to.shared.u64 t, %1; cvt.u32.u64 %0, t; }" : "=r"(a) : "l"(p));
    return a;
}
__device__ __forceinline__ uint32_t tadr(uint32_t tb, int row, int kcol) {
    uint32_t bo = (uint32_t)(row * 128 + kcol * 2);
    return tb + (bo ^ ((bo >> 3) & 0x70));
}
__device__ __forceinline__ void ldsm4(uint32_t* r, uint32_t addr) {
    asm volatile("ldmatrix.sync.aligned.m8n8.x4.shared.b16 {%0,%1,%2,%3}, [%4];"
                 : "=r"(r[0]), "=r"(r[1]), "=r"(r[2]), "=r"(r[3]) : "r"(addr));
}
__device__ __forceinline__ void mma16816(float* d, const uint32_t* a, const uint32_t* b) {
    asm volatile("mma.sync.aligned.m16n8k16.row.col.f32.bf16.bf16.f32 "
                 "{%0,%1,%2,%3}, {%4,%5,%6,%7}, {%8,%9}, {%0,%1,%2,%3};"
                 : "+f"(d[0]), "+f"(d[1]), "+f"(d[2]), "+f"(d[3])
                 : "r"(a[0]), "r"(a[1]), "r"(a[2]), "r"(a[3]), "r"(b[0]), "r"(b[1]));
}

// 512-thread tile movers: one 128x64 bf16 tile (row pitch 256 elems = 512B)
__device__ __forceinline__ void ldg_tile(uint4* R, const __nv_bfloat16* __restrict__ g, int tid) {
    const char* gp = (const char*)g;
#pragma unroll
    for (int j = 0; j < 2; j++) {
        int q = tid + j * 512;
        int row = q >> 3, ch = q & 7;
        R[j] = __ldcg((const uint4*)(gp + (size_t)row * 512 + ch * 16));
    }
}
__device__ __forceinline__ void sts_tile(uint32_t dst, const uint4* R, int tid) {
#pragma unroll
    for (int j = 0; j < 2; j++) {
        int q = tid + j * 512;
        int row = q >> 3, ch = q & 7;
        uint32_t bo = (uint32_t)(row * 128 + ch * 16);
        uint32_t off = dst + (bo ^ ((bo >> 3) & 0x70));
        asm volatile("st.shared.v4.b32 [%0], {%1,%2,%3,%4};"
                     :: "r"(off), "r"(R[j].x), "r"(R[j].y), "r"(R[j].z), "r"(R[j].w));
    }
}
__device__ __forceinline__ void ld_tile(uint32_t dst, const __nv_bfloat16* __restrict__ g, int tid) {
    uint4 R[2];
    ldg_tile(R, g, tid);
    sts_tile(dst, R, tid);
}
// cp.async version (global -> swizzled smem)
__device__ __forceinline__ void cpa_tile(uint32_t dst, const __nv_bfloat16* __restrict__ g, int tid) {
    const char* gp = (const char*)g;
#pragma unroll
    for (int j = 0; j < 2; j++) {
        int q = tid + j * 512;
        int row = q >> 3, ch = q & 7;
        uint32_t bo = (uint32_t)(row * 128 + ch * 16);
        uint32_t off = dst + (bo ^ ((bo >> 3) & 0x70));
        asm volatile("cp.async.cg.shared.global [%0], [%1], 16;"
                     :: "r"(off), "l"(gp + (size_t)row * 512 + ch * 16));
    }
}
#define CPA_COMMIT() asm volatile("cp.async.commit_group;" ::: "memory")
#define CPA_WAIT0()  asm volatile("cp.async.wait_group 0;" ::: "memory")

// issue full x0-phase kt package {x0h, x0l, wihh, wihl} into a 64K parity buffer
__device__ __forceinline__ void issue_x0(uint32_t P,
                                         const __nv_bfloat16* __restrict__ x0h,
                                         const __nv_bfloat16* __restrict__ x0l,
                                         int n0, int kt, int tid) {
    cpa_tile(P,         x0h + kt * 64, tid);
    cpa_tile(P + 16384, x0l + kt * 64, tid);
    cpa_tile(P + 32768, g_Wih_h + (size_t)n0 * NH + kt * 64, tid);
    cpa_tile(P + 49152, g_Wih_l + (size_t)n0 * NH + kt * 64, tid);
    CPA_COMMIT();
}

// 64-wide K chunk, warp tile 32x32: all 3 terms (x0 phase; all tiles present)
__device__ __forceinline__ void mma_chunk(uint32_t abuf, uint32_t whi, uint32_t wlo,
                                          float acc[2][4][4], int mrow, int nbase,
                                          int rowAl, int kselA, int rowBl, int kselB) {
    uint32_t ahi = abuf, alo = abuf + 16384;
#pragma unroll
    for (int ks = 0; ks < 4; ks++) {
        int kA = ks * 16 + kselA, kB = ks * 16 + kselB;
        uint32_t Ah[2][4], Al[2][4], Wh[2][4], Wl[2][4];
#pragma unroll
        for (int mf = 0; mf < 2; mf++) {
            int row = mrow + mf * 16 + rowAl;
            ldsm4(Ah[mf], tadr(ahi, row, kA));
            ldsm4(Al[mf], tadr(alo, row, kA));
        }
#pragma unroll
        for (int np = 0; np < 2; np++) {
            int n = nbase + np * 16 + rowBl;
            ldsm4(Wh[np], tadr(whi, n, kB));
            ldsm4(Wl[np], tadr(wlo, n, kB));
        }
#pragma unroll
        for (int mf = 0; mf < 2; mf++)
#pragma unroll
            for (int nf = 0; nf < 4; nf++)
                mma16816(acc[mf][nf], Ah[mf], &Wh[nf >> 1][(nf & 1) * 2]);
#pragma unroll
        for (int mf = 0; mf < 2; mf++)
#pragma unroll
            for (int nf = 0; nf < 4; nf++)
                mma16816(acc[mf][nf], Al[mf], &Wh[nf >> 1][(nf & 1) * 2]);
#pragma unroll
        for (int mf = 0; mf < 2; mf++)
#pragma unroll
            for (int nf = 0; nf < 4; nf++)
                mma16816(acc[mf][nf], Ah[mf], &Wl[nf >> 1][(nf & 1) * 2]);
    }
}

// h phase: terms 1+2 against resident Whh_hi
__device__ __forceinline__ void mma_h12(uint32_t abuf, uint32_t whi,
                                        float acc[2][4][4], int mrow, int nbase,
                                        int rowAl, int kselA, int rowBl, int kselB) {
    uint32_t ahi = abuf, alo = abuf + 16384;
#pragma unroll
    for (int ks = 0; ks < 4; ks++) {
        int kA = ks * 16 + kselA, kB = ks * 16 + kselB;
        uint32_t Ah[2][4], Al[2][4], Wh[2][4];
#pragma unroll
        for (int mf = 0; mf < 2; mf++) {
            int row = mrow + mf * 16 + rowAl;
            ldsm4(Ah[mf], tadr(ahi, row, kA));
            ldsm4(Al[mf], tadr(alo, row, kA));
        }
#pragma unroll
        for (int np = 0; np < 2; np++) {
            int n = nbase + np * 16 + rowBl;
            ldsm4(Wh[np], tadr(whi, n, kB));
        }
#pragma unroll
        for (int mf = 0; mf < 2; mf++)
#pragma unroll
            for (int nf = 0; nf < 4; nf++)
                mma16816(acc[mf][nf], Ah[mf], &Wh[nf >> 1][(nf & 1) * 2]);
#pragma unroll
        for (int mf = 0; mf < 2; mf++)
#pragma unroll
            for (int nf = 0; nf < 4; nf++)
                mma16816(acc[mf][nf], Al[mf], &Wh[nf >> 1][(nf & 1) * 2]);
    }
}

// h phase: term 3 against streamed Whh_lo
__device__ __forceinline__ void mma_h3(uint32_t abuf, uint32_t wlo,
                                       float acc[2][4][4], int mrow, int nbase,
                                       int rowAl, int kselA, int rowBl, int kselB) {
    uint32_t ahi = abuf;
#pragma unroll
    for (int ks = 0; ks < 4; ks++) {
        int kA = ks * 16 + kselA, kB = ks * 16 + kselB;
        uint32_t Ah[2][4], Wl[2][4];
#pragma unroll
        for (int mf = 0; mf < 2; mf++)
            ldsm4(Ah[mf], tadr(ahi, mrow + mf * 16 + rowAl, kA));
#pragma unroll
        for (int np = 0; np < 2; np++)
            ldsm4(Wl[np], tadr(wlo, nbase + np * 16 + rowBl, kB));
#pragma unroll
        for (int mf = 0; mf < 2; mf++)
#pragma unroll
            for (int nf = 0; nf < 4; nf++)
                mma16816(acc[mf][nf], Ah[mf], &Wl[nf >> 1][(nf & 1) * 2]);
    }
}

// ---------------- prep ----------------
__global__ void k_prep(const float* __restrict__ W_in,
                       const float* __restrict__ W_ih,
                       const float* __restrict__ b_ih,
                       const float* __restrict__ b_hh,
                       const float* __restrict__ W_hh) {
    int i = blockIdx.x * blockDim.x + threadIdx.x;
    if (i < 16) g_cnt[i * 32] = 0;
    if (i < NX * NH) {
        int k = i / NH, h = i % NH;
        g_WinT[k * NH + h] = W_in[h * NX + k];
    }
    if (i < NG4 * NH) {
        int c = i >> 8, k = i & 255;
        int h = c >> 2, g = c & 3;
        int n = g * NH + h;
        float wih = W_ih[n * NH + k];
        float whh = W_hh[n * NH + k];
        __nv_bfloat16 ih_h = __float2bfloat16(wih);
        __nv_bfloat16 hh_h = __float2bfloat16(whh);
        g_Wih_h[i] = ih_h;
        g_Wih_l[i] = __float2bfloat16(wih - __bfloat162float(ih_h));
        g_Whh_h[i] = hh_h;
        g_Whh_l[i] = __float2bfloat16(whh - __bfloat162float(hh_h));
    }
    if (i < NG4) {
        int h = i >> 2, g = i & 3;
        int n = g * NH + h;
        g_biasr[i] = b_ih[n] + b_hh[n];
    }
}

// ---------------- x0 = relu(x @ W_in^T + b_in) -> bf16 hi/lo ----------------
typedef unsigned long long u64t;
__device__ __forceinline__ u64t pk2(float lo, float hi) {
    u64t r; asm("mov.b64 %0, {%1, %2};" : "=l"(r) : "f"(lo), "f"(hi)); return r;
}
__device__ __forceinline__ float2 upk2(u64t v) {
    float2 r; asm("mov.b64 {%0, %1}, %2;" : "=f"(r.x), "=f"(r.y) : "l"(v)); return r;
}
#define FMA2(d, a, b) asm("fma.rn.f32x2 %0, %1, %2, %0;" : "+l"(d) : "l"(a), "l"(b))

__global__ __launch_bounds__(256, 1) void k_x0(const float* __restrict__ x,
                                               const float* __restrict__ b_in) {
    __shared__ float A_s[32][129];
    __shared__ float B_s[32][128];
    int tid = threadIdx.x;
    int r0 = blockIdx.x * 128;
    int c0 = blockIdx.y * 128;

    const float* Ag = x + (size_t)r0 * NX;
#pragma unroll
    for (int j = 0; j < 16; j++) {
        int idx = tid + j * 256;
        A_s[idx & 31][idx >> 5] = Ag[idx];
    }
#pragma unroll
    for (int j = 0; j < 16; j++) {
        int idx = tid + j * 256;
        int k = idx >> 7, col = idx & 127;
        B_s[k][col] = g_WinT[k * NH + c0 + col];
    }
    __syncthreads();

    int tx = tid & 7, ty = tid >> 3;
    int cb = tx * 16, rb = ty * 4;

    u64t acc[4][8];
#pragma unroll
    for (int p = 0; p < 8; p++) {
        u64t bp = pk2(b_in[c0 + cb + 2 * p], b_in[c0 + cb + 2 * p + 1]);
        acc[0][p] = bp; acc[1][p] = bp; acc[2][p] = bp; acc[3][p] = bp;
    }
#pragma unroll
    for (int kk = 0; kk < 32; kk++) {
        u64t a2[4];
#pragma unroll
        for (int i = 0; i < 4; i++) { float a = A_s[kk][rb + i]; a2[i] = pk2(a, a); }
        const u64t* bs = reinterpret_cast<const u64t*>(&B_s[kk][cb]);
        u64t b2[8];
#pragma unroll
        for (int p = 0; p < 8; p++) b2[p] = bs[p];
#pragma unroll
        for (int i = 0; i < 4; i++)
#pragma unroll
            for (int p = 0; p < 8; p++) FMA2(acc[i][p], a2[i], b2[p]);
    }
#pragma unroll
    for (int i = 0; i < 4; i++) {
        size_t r = (size_t)(r0 + rb + i);
        union { unsigned short s[16]; uint4 v[2]; } uh, ul;
#pragma unroll
        for (int p = 0; p < 8; p++) {
            float2 u = upk2(acc[i][p]);
            float f0 = fmaxf(u.x, 0.f), f1 = fmaxf(u.y, 0.f);
            __nv_bfloat16 h0 = __float2bfloat16(f0);
            __nv_bfloat16 h1 = __float2bfloat16(f1);
            __nv_bfloat16 l0 = __float2bfloat16(f0 - __bfloat162float(h0));
            __nv_bfloat16 l1 = __float2bfloat16(f1 - __bfloat162float(h1));
            uh.s[2 * p] = *(unsigned short*)&h0; uh.s[2 * p + 1] = *(unsigned short*)&h1;
            ul.s[2 * p] = *(unsigned short*)&l0; ul.s[2 * p + 1] = *(unsigned short*)&l1;
        }
        uint4* dh = (uint4*)(g_x0h + r * NH + c0 + cb);
        uint4* dl = (uint4*)(g_x0l + r * NH + c0 + cb);
        dh[0] = uh.v[0]; dh[1] = uh.v[1];
        dl[0] = ul.v[0]; dl[1] = ul.v[1];
    }
}

// ---------------- fused persistent scan, pipelined streams ----------------
__global__ __launch_bounds__(512, 1) void k_scan(const float* __restrict__ W_out) {
    extern __shared__ char sm[];
    __shared__ float Wout_s[NH];
    __shared__ float bias_s[128];
    uint32_t sb = smem_u32(sm);
    const uint32_t WHH = sb;                       // resident Whh_hi (64K)
    const uint32_t STRM = sb + STRM_OFF;           // 128K stream region
    const uint32_t STAGE = sb + STAGE_OFF;

    int tid = threadIdx.x, lane = tid & 31, w = tid >> 5;
    int wm = w >> 2, wn = w & 3;
    int g8 = lane >> 3, r8 = lane & 7;
    int rowAl = (g8 & 1) * 8 + r8, kselA = (g8 >> 1) * 8;
    int rowBl = (g8 >> 1) * 8 + r8, kselB = (g8 & 1) * 8;
    int gid = lane >> 2, tig = lane & 3;
    int nhat = blockIdx.x & 7, rbk = blockIdx.x >> 3;
    int n0 = nhat * 128, rbase = rbk * 128;

    if (tid < NH) Wout_s[tid] = W_out[tid];
    if (tid < 128) bias_s[tid] = g_biasr[n0 + tid];
#pragma unroll
    for (int kt = 0; kt < 4; kt++)
        ld_tile(WHH + kt * 16384, g_Whh_h + (size_t)n0 * NH + kt * 64, tid);

    float creg[2][4];
#pragma unroll
    for (int mf = 0; mf < 2; mf++)
#pragma unroll
        for (int nf = 0; nf < 4; nf++) creg[mf][nf] = 0.f;
    __syncthreads();

    // prefetch step-0 kt0 package into parity0
    issue_x0(STRM, g_x0h + (size_t)rbase * NH, g_x0l + (size_t)rbase * NH, n0, 0, tid);

    for (int tg = 0; tg < NT; tg++) {
        const __nv_bfloat16* x0h = g_x0h + ((size_t)tg * NGRID + rbase) * NH;
        const __nv_bfloat16* x0l = g_x0l + ((size_t)tg * NGRID + rbase) * NH;

        float acc[2][4][4];
#pragma unroll
        for (int a = 0; a < 2; a++)
#pragma unroll
            for (int b = 0; b < 4; b++)
#pragma unroll
                for (int c = 0; c < 4; c++) acc[a][b][c] = 0.f;

        // ---- x0 phase: pipelined (kt+1 in flight during kt's MMA) ----
#pragma unroll 1
        for (int kt = 0; kt < 4; kt++) {
            uint32_t P = STRM + (uint32_t)(kt & 1) * 65536;
            CPA_WAIT0();
            __syncthreads();
            if (kt < 3)
                issue_x0(STRM + (uint32_t)((kt + 1) & 1) * 65536, x0h, x0l, n0, kt + 1, tid);
            mma_chunk(P, P + 32768, P + 49152, acc,
                      wm * 32, wn * 32, rowAl, kselA, rowBl, kselB);
        }

        // ---- h phase: resident Whh_hi (T1,T2) + streamed Whh_lo ring (T3) ----
        if (tg > 0) {
            const uint32_t WL0 = STRM + 98304, WL1 = STRM + 114688;
            __syncthreads();   // all warps done reading parity1 (x0 kt3)
            // Whh_lo kt0 load has NO h dependency: issue before the flag wait
            cpa_tile(WL0, g_Whh_l + (size_t)n0 * NH, tid);
            CPA_COMMIT();

            if (tid == 0) {
                volatile unsigned* c = &g_cnt[rbk * 32];
                while (*c < 8u * (unsigned)tg) __nanosleep(20);
                __threadfence();
            }
            __syncthreads();

            const __nv_bfloat16* hh = g_hh + (size_t)((tg - 1) & 1) * NGRID * NH + (size_t)rbase * NH;
            const __nv_bfloat16* hl = g_hl + (size_t)((tg - 1) & 1) * NGRID * NH + (size_t)rbase * NH;
            uint4 R[4];
            ldg_tile(R,     hh, tid);
            ldg_tile(R + 2, hl, tid);
#pragma unroll 1
            for (int kt = 0; kt < 4; kt++) {
                uint32_t ab = STRM + (uint32_t)(kt & 1) * 32768;   // A dbuf in parity0
                sts_tile(ab, R, tid);
                sts_tile(ab + 16384, R + 2, tid);
                if (kt < 3) {
                    ldg_tile(R,     hh + (kt + 1) * 64, tid);
                    ldg_tile(R + 2, hl + (kt + 1) * 64, tid);
                }
                __syncthreads();
                mma_h12(ab, WHH + kt * 16384, acc,
                        wm * 32, wn * 32, rowAl, kselA, rowBl, kselB);
                CPA_WAIT0();
                __syncthreads();
                if (kt < 3) {
                    cpa_tile((kt & 1) ? WL0 : WL1,
                             g_Whh_l + (size_t)n0 * NH + (kt + 1) * 64, tid);
                    CPA_COMMIT();
                }
                mma_h3(ab, (kt & 1) ? WL1 : WL0, acc,
                       wm * 32, wn * 32, rowAl, kselA, rowBl, kselB);
            }
        }

        __syncthreads();   // stream region fully consumed; stage safe

        // prefetch next step's kt0 package (lands during epilogue/writeout)
        if (tg + 1 < NT)
            issue_x0(STRM, x0h + (size_t)NGRID * NH, x0l + (size_t)NGRID * NH, n0, 0, tid);

        // ---- epilogue: gates -> cell update; stage h tile; out partials ----
#pragma unroll
        for (int mf = 0; mf < 2; mf++) {
            int rloc = wm * 32 + mf * 16 + gid + (tig & 1) * 8;
            int row = rbase + rloc;
            float pout = 0.f;
#pragma unroll
            for (int nf = 0; nf < 4; nf++) {
                float c0 = acc[mf][nf][0], c1 = acc[mf][nf][1];
                float c2 = acc[mf][nf][2], c3 = acc[mf][nf][3];
                float s0 = (lane & 1) ? c0 : c2;
                float s1 = (lane & 1) ? c1 : c3;
                float r0 = __shfl_xor_sync(0xffffffffu, s0, 1);
                float r1 = __shfl_xor_sync(0xffffffffu, s1, 1);
                float gi, gf, gg, go;
                if (!(lane & 1)) { gi = c0; gf = c1; gg = r0; go = r1; }
                else             { gi = r0; gf = r1; gg = c2; go = c3; }
                int hl_i = wn * 8 + nf * 2 + (tig >> 1);
                float4 bv = *(const float4*)&bias_s[hl_i * 4];
                float iv = gi + bv.x, fv = gf + bv.y, gv = gg + bv.z, ov = go + bv.w;
                float cn = sigf(fv) * creg[mf][nf] + sigf(iv) * tanhfast(gv);
                creg[mf][nf] = cn;
                float hv = sigf(ov) * tanhfast(cn);
                pout += hv * Wout_s[nhat * 32 + hl_i];
                __nv_bfloat16 bh = __float2bfloat16(hv);
                __nv_bfloat16 bl = __float2bfloat16(hv - __bfloat162float(bh));
                uint32_t so = (uint32_t)(rloc * 64 + hl_i * 2);
                asm volatile("st.shared.u16 [%0], %1;" :: "r"(STAGE + so), "h"(*(unsigned short*)&bh));
                asm volatile("st.shared.u16 [%0], %1;" :: "r"(STAGE + 8192 + so), "h"(*(unsigned short*)&bl));
            }
            float pr = pout + __shfl_xor_sync(0xffffffffu, pout, 2);
            if ((tig >> 1) == 0)
                g_part[((size_t)tg * NGRID + row) * 32 + nhat * 4 + wn] = pr;
        }
        __syncthreads();

        // coalesced h writeout: 128 rows x 32 cols hi/lo
        {
            int row = tid >> 2, seg = tid & 3;
            uint4 vh, vl;
            asm volatile("ld.shared.v4.b32 {%0,%1,%2,%3}, [%4];"
                         : "=r"(vh.x), "=r"(vh.y), "=r"(vh.z), "=r"(vh.w)
                         : "r"(STAGE + row * 64 + seg * 16));
            asm volatile("ld.shared.v4.b32 {%0,%1,%2,%3}, [%4];"
                         : "=r"(vl.x), "=r"(vl.y), "=r"(vl.z), "=r"(vl.w)
                         : "r"(STAGE + 8192 + row * 64 + seg * 16));
            size_t go = (size_t)(tg & 1) * NGRID * NH + (size_t)(rbase + row) * NH + nhat * 32 + seg * 8;
            *(uint4*)(g_hh + go) = vh;
            *(uint4*)(g_hl + go) = vl;
        }
        __syncthreads();
        if (tid == 0) {
            __threadfence();
            atomicAdd(&g_cnt[rbk * 32], 1u);
        }
    }
}

// ---------------- out = sum(32 partials) + b_out ----------------
__global__ __launch_bounds__(256) void k_out(const float* __restrict__ b_out,
                                             float* __restrict__ out) {
    size_t r = (size_t)blockIdx.x * 256 + threadIdx.x;
    const float4* p = (const float4*)(g_part + r * 32);
    float s = 0.f;
#pragma unroll
    for (int j = 0; j < 8; j++) {
        float4 v = p[j];
        s += v.x + v.y + v.z + v.w;
    }
    out[r] = s + b_out[0];
}

// ---------------- launch ----------------
extern "C" void kernel_launch(void* const* d_in, const int* in_sizes, int n_in,
                              void* d_out, int out_size) {
    const float* x     = (const float*)d_in[0];
    const float* W_in  = (const float*)d_in[1];
    const float* b_in  = (const float*)d_in[2];
    const float* W_ih  = (const float*)d_in[3];
    const float* b_ih  = (const float*)d_in[4];
    const float* W_hh  = (const float*)d_in[5];
    const float* b_hh  = (const float*)d_in[6];
    const float* W_out = (const float*)d_in[7];
    const float* b_out = (const float*)d_in[8];
    float* out = (float*)d_out;

    static int attr_done = 0;
    if (!attr_done) {
        cudaFuncSetAttribute(k_scan, cudaFuncAttributeMaxDynamicSharedMemorySize, DSMEM);
        attr_done = 1;
    }

    k_prep<<<(NG4 * NH + 255) / 256, 256>>>(W_in, W_ih, b_ih, b_hh, W_hh);
    k_x0<<<dim3(M_TOT / 128, NH / 128), 256>>>(x, b_in);
    k_scan<<<128, 512, DSMEM>>>(W_out);
    k_out<<<M_TOT / 256, 256>>>(b_out, out);
}

// round 14
// speedup vs baseline: 1.6866x; 1.0335x over previous
#include <cuda_runtime.h>
#include <cuda_bf16.h>
#include <math.h>
#include <stdint.h>

// ---------------- problem constants ----------------
#define NT    365
#define NGRID 2048
#define NX    32
#define NH    256
#define NG4   1024
#define M_TOT (NT * NGRID)        // 747520

// scan SMEM layout (dynamic):
//   WHH_HI  [0, 64K)                resident Whh hi (4 kt x 16K)
//   STRM    [64K, 192K)             x0 phase: 2 x 64K parity bufs
//                                   h phase: h dbuf at STRM+{0,32K}, WL ring at
//                                   STRM+98304 / STRM+114688
//   STAGE   [192K, 208K)
#define STRM_OFF  65536
#define STAGE_OFF 196608
#define DSMEM     212992

// ---------------- device globals (~0.9 GB) ----------------
__device__ __nv_bfloat16 g_x0h[(size_t)M_TOT * NH];
__device__ __nv_bfloat16 g_x0l[(size_t)M_TOT * NH];
__device__ __nv_bfloat16 g_hh[2 * NGRID * NH];        // h ring hi
__device__ __nv_bfloat16 g_hl[2 * NGRID * NH];        // h ring lo
__device__ float g_part[(size_t)M_TOT * 32];
__device__ float g_WinT[NX * NH];
__device__ __nv_bfloat16 g_Wih_h[NG4 * NH], g_Wih_l[NG4 * NH];  // [c][k], c=h*4+g
__device__ __nv_bfloat16 g_Whh_h[NG4 * NH], g_Whh_l[NG4 * NH];
__device__ float g_biasr[NG4];
__device__ unsigned g_cnt[16 * 32];    // per-row-group progress counters (padded)

// ---------------- helpers ----------------
// fast sigmoid / tanh: __expf rel-err ~2^-21 -> gate-level error ~1e-6 (safe)
__device__ __forceinline__ float sigf(float x) {
    return __fdividef(1.0f, 1.0f + __expf(-x));
}
__device__ __forceinline__ float tanhfast(float x) {
    return 2.0f * sigf(2.0f * x) - 1.0f;
}

__device__ __forceinline__ uint32_t smem_u32(const void* p) {
    uint32_t a;
    asm("{ .reg .u64 t; cvta.to.shared.u64 t, %1; cvt.u32.u64 %0, t; }" : "=r"(a) : "l"(p));
    return a;
}
__device__ __forceinline__ uint32_t tadr(uint32_t tb, int row, int kcol) {
    uint32_t bo = (uint32_t)(row * 128 + kcol * 2);
    return tb + (bo ^ ((bo >> 3) & 0x70));
}
__device__ __forceinline__ void ldsm4(uint32_t* r, uint32_t addr) {
    asm volatile("ldmatrix.sync.aligned.m8n8.x4.shared.b16 {%0,%1,%2,%3}, [%4];"
                 : "=r"(r[0]), "=r"(r[1]), "=r"(r[2]), "=r"(r[3]) : "r"(addr));
}
__device__ __forceinline__ void mma16816(float* d, const uint32_t* a, const uint32_t* b) {
    asm volatile("mma.sync.aligned.m16n8k16.row.col.f32.bf16.bf16.f32 "
                 "{%0,%1,%2,%3}, {%4,%5,%6,%7}, {%8,%9}, {%0,%1,%2,%3};"
                 : "+f"(d[0]), "+f"(d[1]), "+f"(d[2]), "+f"(d[3])
                 : "r"(a[0]), "r"(a[1]), "r"(a[2]), "r"(a[3]), "r"(b[0]), "r"(b[1]));
}

// 512-thread tile movers: one 128x64 bf16 tile (row pitch 256 elems = 512B)
__device__ __forceinline__ void ldg_tile(uint4* R, const __nv_bfloat16* __restrict__ g, int tid) {
    const char* gp = (const char*)g;
#pragma unroll
    for (int j = 0; j < 2; j++) {
        int q = tid + j * 512;
        int row = q >> 3, ch = q & 7;
        R[j] = __ldcg((const uint4*)(gp + (size_t)row * 512 + ch * 16));
    }
}
__device__ __forceinline__ void sts_tile(uint32_t dst, const uint4* R, int tid) {
#pragma unroll
    for (int j = 0; j < 2; j++) {
        int q = tid + j * 512;
        int row = q >> 3, ch = q & 7;
        uint32_t bo = (uint32_t)(row * 128 + ch * 16);
        uint32_t off = dst + (bo ^ ((bo >> 3) & 0x70));
        asm volatile("st.shared.v4.b32 [%0], {%1,%2,%3,%4};"
                     :: "r"(off), "r"(R[j].x), "r"(R[j].y), "r"(R[j].z), "r"(R[j].w));
    }
}
__device__ __forceinline__ void ld_tile(uint32_t dst, const __nv_bfloat16* __restrict__ g, int tid) {
    uint4 R[2];
    ldg_tile(R, g, tid);
    sts_tile(dst, R, tid);
}
// cp.async version (global -> swizzled smem)
__device__ __forceinline__ void cpa_tile(uint32_t dst, const __nv_bfloat16* __restrict__ g, int tid) {
    const char* gp = (const char*)g;
#pragma unroll
    for (int j = 0; j < 2; j++) {
        int q = tid + j * 512;
        int row = q >> 3, ch = q & 7;
        uint32_t bo = (uint32_t)(row * 128 + ch * 16);
        uint32_t off = dst + (bo ^ ((bo >> 3) & 0x70));
        asm volatile("cp.async.cg.shared.global [%0], [%1], 16;"
                     :: "r"(off), "l"(gp + (size_t)row * 512 + ch * 16));
    }
}
#define CPA_COMMIT() asm volatile("cp.async.commit_group;" ::: "memory")
#define CPA_WAIT0()  asm volatile("cp.async.wait_group 0;" ::: "memory")

// issue full x0-phase kt package {x0h, x0l, wihh, wihl} into a 64K parity buffer
__device__ __forceinline__ void issue_x0(uint32_t P,
                                         const __nv_bfloat16* __restrict__ x0h,
                                         const __nv_bfloat16* __restrict__ x0l,
                                         int n0, int kt, int tid) {
    cpa_tile(P,         x0h + kt * 64, tid);
    cpa_tile(P + 16384, x0l + kt * 64, tid);
    cpa_tile(P + 32768, g_Wih_h + (size_t)n0 * NH + kt * 64, tid);
    cpa_tile(P + 49152, g_Wih_l + (size_t)n0 * NH + kt * 64, tid);
    CPA_COMMIT();
}

// 64-wide K chunk, warp tile 32x32: 3-term precision split, 4 k16 steps.
// A fragments loaded once per ks and reused by all three terms.
__device__ __forceinline__ void mma_chunk(uint32_t ahi, uint32_t alo,
                                          uint32_t whi, uint32_t wlo,
                                          float acc[2][4][4], int mrow, int nbase,
                                          int rowAl, int kselA, int rowBl, int kselB) {
#pragma unroll
    for (int ks = 0; ks < 4; ks++) {
        int kA = ks * 16 + kselA, kB = ks * 16 + kselB;
        uint32_t Ah[2][4], Al[2][4], Wh[2][4], Wl[2][4];
#pragma unroll
        for (int mf = 0; mf < 2; mf++) {
            int row = mrow + mf * 16 + rowAl;
            ldsm4(Ah[mf], tadr(ahi, row, kA));
            ldsm4(Al[mf], tadr(alo, row, kA));
        }
#pragma unroll
        for (int np = 0; np < 2; np++) {
            int n = nbase + np * 16 + rowBl;
            ldsm4(Wh[np], tadr(whi, n, kB));
            ldsm4(Wl[np], tadr(wlo, n, kB));
        }
#pragma unroll
        for (int mf = 0; mf < 2; mf++)
#pragma unroll
            for (int nf = 0; nf < 4; nf++)
                mma16816(acc[mf][nf], Ah[mf], &Wh[nf >> 1][(nf & 1) * 2]);
#pragma unroll
        for (int mf = 0; mf < 2; mf++)
#pragma unroll
            for (int nf = 0; nf < 4; nf++)
                mma16816(acc[mf][nf], Al[mf], &Wh[nf >> 1][(nf & 1) * 2]);
#pragma unroll
        for (int mf = 0; mf < 2; mf++)
#pragma unroll
            for (int nf = 0; nf < 4; nf++)
                mma16816(acc[mf][nf], Ah[mf], &Wl[nf >> 1][(nf & 1) * 2]);
    }
}

// ---------------- prep ----------------
__global__ void k_prep(const float* __restrict__ W_in,
                       const float* __restrict__ W_ih,
                       const float* __restrict__ b_ih,
                       const float* __restrict__ b_hh,
                       const float* __restrict__ W_hh) {
    int i = blockIdx.x * blockDim.x + threadIdx.x;
    if (i < 16) g_cnt[i * 32] = 0;
    if (i < NX * NH) {
        int k = i / NH, h = i % NH;
        g_WinT[k * NH + h] = W_in[h * NX + k];
    }
    if (i < NG4 * NH) {
        int c = i >> 8, k = i & 255;
        int h = c >> 2, g = c & 3;
        int n = g * NH + h;
        float wih = W_ih[n * NH + k];
        float whh = W_hh[n * NH + k];
        __nv_bfloat16 ih_h = __float2bfloat16(wih);
        __nv_bfloat16 hh_h = __float2bfloat16(whh);
        g_Wih_h[i] = ih_h;
        g_Wih_l[i] = __float2bfloat16(wih - __bfloat162float(ih_h));
        g_Whh_h[i] = hh_h;
        g_Whh_l[i] = __float2bfloat16(whh - __bfloat162float(hh_h));
    }
    if (i < NG4) {
        int h = i >> 2, g = i & 3;
        int n = g * NH + h;
        g_biasr[i] = b_ih[n] + b_hh[n];
    }
}

// ---------------- x0 = relu(x @ W_in^T + b_in) -> bf16 hi/lo ----------------
typedef unsigned long long u64t;
__device__ __forceinline__ u64t pk2(float lo, float hi) {
    u64t r; asm("mov.b64 %0, {%1, %2};" : "=l"(r) : "f"(lo), "f"(hi)); return r;
}
__device__ __forceinline__ float2 upk2(u64t v) {
    float2 r; asm("mov.b64 {%0, %1}, %2;" : "=f"(r.x), "=f"(r.y) : "l"(v)); return r;
}
#define FMA2(d, a, b) asm("fma.rn.f32x2 %0, %1, %2, %0;" : "+l"(d) : "l"(a), "l"(b))

__global__ __launch_bounds__(256, 1) void k_x0(const float* __restrict__ x,
                                               const float* __restrict__ b_in) {
    __shared__ float A_s[32][129];
    __shared__ float B_s[32][128];
    int tid = threadIdx.x;
    int r0 = blockIdx.x * 128;
    int c0 = blockIdx.y * 128;

    const float* Ag = x + (size_t)r0 * NX;
#pragma unroll
    for (int j = 0; j < 16; j++) {
        int idx = tid + j * 256;
        A_s[idx & 31][idx >> 5] = Ag[idx];
    }
#pragma unroll
    for (int j = 0; j < 16; j++) {
        int idx = tid + j * 256;
        int k = idx >> 7, col = idx & 127;
        B_s[k][col] = g_WinT[k * NH + c0 + col];
    }
    __syncthreads();

    int tx = tid & 7, ty = tid >> 3;
    int cb = tx * 16, rb = ty * 4;

    u64t acc[4][8];
#pragma unroll
    for (int p = 0; p < 8; p++) {
        u64t bp = pk2(b_in[c0 + cb + 2 * p], b_in[c0 + cb + 2 * p + 1]);
        acc[0][p] = bp; acc[1][p] = bp; acc[2][p] = bp; acc[3][p] = bp;
    }
#pragma unroll
    for (int kk = 0; kk < 32; kk++) {
        u64t a2[4];
#pragma unroll
        for (int i = 0; i < 4; i++) { float a = A_s[kk][rb + i]; a2[i] = pk2(a, a); }
        const u64t* bs = reinterpret_cast<const u64t*>(&B_s[kk][cb]);
        u64t b2[8];
#pragma unroll
        for (int p = 0; p < 8; p++) b2[p] = bs[p];
#pragma unroll
        for (int i = 0; i < 4; i++)
#pragma unroll
            for (int p = 0; p < 8; p++) FMA2(acc[i][p], a2[i], b2[p]);
    }
#pragma unroll
    for (int i = 0; i < 4; i++) {
        size_t r = (size_t)(r0 + rb + i);
        union { unsigned short s[16]; uint4 v[2]; } uh, ul;
#pragma unroll
        for (int p = 0; p < 8; p++) {
            float2 u = upk2(acc[i][p]);
            float f0 = fmaxf(u.x, 0.f), f1 = fmaxf(u.y, 0.f);
            __nv_bfloat16 h0 = __float2bfloat16(f0);
            __nv_bfloat16 h1 = __float2bfloat16(f1);
            __nv_bfloat16 l0 = __float2bfloat16(f0 - __bfloat162float(h0));
            __nv_bfloat16 l1 = __float2bfloat16(f1 - __bfloat162float(h1));
            uh.s[2 * p] = *(unsigned short*)&h0; uh.s[2 * p + 1] = *(unsigned short*)&h1;
            ul.s[2 * p] = *(unsigned short*)&l0; ul.s[2 * p + 1] = *(unsigned short*)&l1;
        }
        uint4* dh = (uint4*)(g_x0h + r * NH + c0 + cb);
        uint4* dl = (uint4*)(g_x0l + r * NH + c0 + cb);
        dh[0] = uh.v[0]; dh[1] = uh.v[1];
        dl[0] = ul.v[0]; dl[1] = ul.v[1];
    }
}

// ---------------- fused persistent scan, fully cp.async-pipelined ----------------
__global__ __launch_bounds__(512, 1) void k_scan(const float* __restrict__ W_out) {
    extern __shared__ char sm[];
    __shared__ float Wout_s[NH];
    __shared__ float bias_s[128];
    uint32_t sb = smem_u32(sm);
    const uint32_t WHH = sb;                       // resident Whh_hi (64K)
    const uint32_t STRM = sb + STRM_OFF;           // 128K stream region
    const uint32_t STAGE = sb + STAGE_OFF;

    int tid = threadIdx.x, lane = tid & 31, w = tid >> 5;
    int wm = w >> 2, wn = w & 3;
    int g8 = lane >> 3, r8 = lane & 7;
    int rowAl = (g8 & 1) * 8 + r8, kselA = (g8 >> 1) * 8;
    int rowBl = (g8 >> 1) * 8 + r8, kselB = (g8 & 1) * 8;
    int gid = lane >> 2, tig = lane & 3;
    int nhat = blockIdx.x & 7, rbk = blockIdx.x >> 3;
    int n0 = nhat * 128, rbase = rbk * 128;

    if (tid < NH) Wout_s[tid] = W_out[tid];
    if (tid < 128) bias_s[tid] = g_biasr[n0 + tid];
#pragma unroll
    for (int kt = 0; kt < 4; kt++)
        ld_tile(WHH + kt * 16384, g_Whh_h + (size_t)n0 * NH + kt * 64, tid);

    float creg[2][4];
#pragma unroll
    for (int mf = 0; mf < 2; mf++)
#pragma unroll
        for (int nf = 0; nf < 4; nf++) creg[mf][nf] = 0.f;
    __syncthreads();

    // prefetch step-0 kt0 package into parity0
    issue_x0(STRM, g_x0h + (size_t)rbase * NH, g_x0l + (size_t)rbase * NH, n0, 0, tid);

    for (int tg = 0; tg < NT; tg++) {
        const __nv_bfloat16* x0h = g_x0h + ((size_t)tg * NGRID + rbase) * NH;
        const __nv_bfloat16* x0l = g_x0l + ((size_t)tg * NGRID + rbase) * NH;

        float acc[2][4][4];
#pragma unroll
        for (int a = 0; a < 2; a++)
#pragma unroll
            for (int b = 0; b < 4; b++)
#pragma unroll
                for (int c = 0; c < 4; c++) acc[a][b][c] = 0.f;

        // ---- x0 phase: pipelined (kt+1 in flight during kt's MMA) ----
#pragma unroll 1
        for (int kt = 0; kt < 4; kt++) {
            uint32_t P = STRM + (uint32_t)(kt & 1) * 65536;
            CPA_WAIT0();
            __syncthreads();
            if (kt < 3)
                issue_x0(STRM + (uint32_t)((kt + 1) & 1) * 65536, x0h, x0l, n0, kt + 1, tid);
            mma_chunk(P, P + 16384, P + 32768, P + 49152, acc,
                      wm * 32, wn * 32, rowAl, kselA, rowBl, kselB);
        }

        // ---- h phase: resident Whh_hi + cp.async h dbuf + WL ring ----
        if (tg > 0) {
            const uint32_t WL0 = STRM + 98304, WL1 = STRM + 114688;
            __syncthreads();   // all warps done reading parity1 (x0 kt3)
            // Whh_lo kt0 has NO h dependency: issue before the flag wait
            cpa_tile(WL0, g_Whh_l + (size_t)n0 * NH, tid);
            CPA_COMMIT();

            if (tid == 0) {
                volatile unsigned* c = &g_cnt[rbk * 32];
                while (*c < 8u * (unsigned)tg) __nanosleep(20);
                __threadfence();
            }
            __syncthreads();

            const __nv_bfloat16* hh = g_hh + (size_t)((tg - 1) & 1) * NGRID * NH + (size_t)rbase * NH;
            const __nv_bfloat16* hl = g_hl + (size_t)((tg - 1) & 1) * NGRID * NH + (size_t)rbase * NH;
            // h kt0 into parity0 (x0 phase done with it)
            cpa_tile(STRM,         hh, tid);
            cpa_tile(STRM + 16384, hl, tid);
            CPA_COMMIT();

#pragma unroll 1
            for (int kt = 0; kt < 4; kt++) {
                uint32_t ab = STRM + (uint32_t)(kt & 1) * 32768;
                CPA_WAIT0();
                __syncthreads();
                if (kt < 3) {
                    uint32_t ab2 = STRM + (uint32_t)((kt + 1) & 1) * 32768;
                    cpa_tile(ab2,         hh + (kt + 1) * 64, tid);
                    cpa_tile(ab2 + 16384, hl + (kt + 1) * 64, tid);
                    cpa_tile((kt & 1) ? WL0 : WL1,
                             g_Whh_l + (size_t)n0 * NH + (kt + 1) * 64, tid);
                    CPA_COMMIT();
                }
                mma_chunk(ab, ab + 16384, WHH + kt * 16384, (kt & 1) ? WL1 : WL0, acc,
                          wm * 32, wn * 32, rowAl, kselA, rowBl, kselB);
            }
        }

        __syncthreads();   // stream region fully consumed; stage safe

        // prefetch next step's kt0 package (lands during epilogue/writeout)
        if (tg + 1 < NT)
            issue_x0(STRM, x0h + (size_t)NGRID * NH, x0l + (size_t)NGRID * NH, n0, 0, tid);

        // ---- epilogue: gates -> cell update; stage h tile; out partials ----
#pragma unroll
        for (int mf = 0; mf < 2; mf++) {
            int rloc = wm * 32 + mf * 16 + gid + (tig & 1) * 8;
            int row = rbase + rloc;
            float pout = 0.f;
#pragma unroll
            for (int nf = 0; nf < 4; nf++) {
                float c0 = acc[mf][nf][0], c1 = acc[mf][nf][1];
                float c2 = acc[mf][nf][2], c3 = acc[mf][nf][3];
                float s0 = (lane & 1) ? c0 : c2;
                float s1 = (lane & 1) ? c1 : c3;
                float r0 = __shfl_xor_sync(0xffffffffu, s0, 1);
                float r1 = __shfl_xor_sync(0xffffffffu, s1, 1);
                float gi, gf, gg, go;
                if (!(lane & 1)) { gi = c0; gf = c1; gg = r0; go = r1; }
                else             { gi = r0; gf = r1; gg = c2; go = c3; }
                int hl_i = wn * 8 + nf * 2 + (tig >> 1);
                float4 bv = *(const float4*)&bias_s[hl_i * 4];
                float iv = gi + bv.x, fv = gf + bv.y, gv = gg + bv.z, ov = go + bv.w;
                float cn = sigf(fv) * creg[mf][nf] + sigf(iv) * tanhfast(gv);
                creg[mf][nf] = cn;
                float hv = sigf(ov) * tanhfast(cn);
                pout += hv * Wout_s[nhat * 32 + hl_i];
                __nv_bfloat16 bh = __float2bfloat16(hv);
                __nv_bfloat16 bl = __float2bfloat16(hv - __bfloat162float(bh));
                uint32_t so = (uint32_t)(rloc * 64 + hl_i * 2);
                asm volatile("st.shared.u16 [%0], %1;" :: "r"(STAGE + so), "h"(*(unsigned short*)&bh));
                asm volatile("st.shared.u16 [%0], %1;" :: "r"(STAGE + 8192 + so), "h"(*(unsigned short*)&bl));
            }
            float pr = pout + __shfl_xor_sync(0xffffffffu, pout, 2);
            if ((tig >> 1) == 0)
                g_part[((size_t)tg * NGRID + row) * 32 + nhat * 4 + wn] = pr;
        }
        __syncthreads();

        // coalesced h writeout: 128 rows x 32 cols hi/lo
        {
            int row = tid >> 2, seg = tid & 3;
            uint4 vh, vl;
            asm volatile("ld.shared.v4.b32 {%0,%1,%2,%3}, [%4];"
                         : "=r"(vh.x), "=r"(vh.y), "=r"(vh.z), "=r"(vh.w)
                         : "r"(STAGE + row * 64 + seg * 16));
            asm volatile("ld.shared.v4.b32 {%0,%1,%2,%3}, [%4];"
                         : "=r"(vl.x), "=r"(vl.y), "=r"(vl.z), "=r"(vl.w)
                         : "r"(STAGE + 8192 + row * 64 + seg * 16));
            size_t go = (size_t)(tg & 1) * NGRID * NH + (size_t)(rbase + row) * NH + nhat * 32 + seg * 8;
            *(uint4*)(g_hh + go) = vh;
            *(uint4*)(g_hl + go) = vl;
        }
        __syncthreads();
        if (tid == 0) {
            __threadfence();
            atomicAdd(&g_cnt[rbk * 32], 1u);
        }
    }
}

// ---------------- out = sum(32 partials) + b_out ----------------
__global__ __launch_bounds__(256) void k_out(const float* __restrict__ b_out,
                                             float* __restrict__ out) {
    size_t r = (size_t)blockIdx.x * 256 + threadIdx.x;
    const float4* p = (const float4*)(g_part + r * 32);
    float s = 0.f;
#pragma unroll
    for (int j = 0; j < 8; j++) {
        float4 v = p[j];
        s += v.x + v.y + v.z + v.w;
    }
    out[r] = s + b_out[0];
}

// ---------------- launch ----------------
extern "C" void kernel_launch(void* const* d_in, const int* in_sizes, int n_in,
                              void* d_out, int out_size) {
    const float* x     = (const float*)d_in[0];
    const float* W_in  = (const float*)d_in[1];
    const float* b_in  = (const float*)d_in[2];
    const float* W_ih  = (const float*)d_in[3];
    const float* b_ih  = (const float*)d_in[4];
    const float* W_hh  = (const float*)d_in[5];
    const float* b_hh  = (const float*)d_in[6];
    const float* W_out = (const float*)d_in[7];
    const float* b_out = (const float*)d_in[8];
    float* out = (float*)d_out;

    static int attr_done = 0;
    if (!attr_done) {
        cudaFuncSetAttribute(k_scan, cudaFuncAttributeMaxDynamicSharedMemorySize, DSMEM);
        attr_done = 1;
    }

    k_prep<<<(NG4 * NH + 255) / 256, 256>>>(W_in, W_ih, b_ih, b_hh, W_hh);
    k_x0<<<dim3(M_TOT / 128, NH / 128), 256>>>(x, b_in);
    k_scan<<<128, 512, DSMEM>>>(W_out);
    k_out<<<M_TOT / 256, 256>>>(b_out, out);
}

// round 15
// speedup vs baseline: 1.7440x; 1.0340x over previous
#include <cuda_runtime.h>
#include <cuda_bf16.h>
#include <math.h>
#include <stdint.h>

// ---------------- problem constants ----------------
#define NT    365
#define NGRID 2048
#define NX    32
#define NH    256
#define NG4   1024
#define M_TOT (NT * NGRID)        // 747520

// scan SMEM layout (dynamic):
//   WHH_HI  [0, 64K)                resident Whh hi (4 kt x 16K)
//   STRM    [64K, 192K)             2 x 64K parity buffers B0/B1
//     x0 pkg: {x0h, x0l, wihh, wihl} @ +0,+16K,+32K,+48K
//     h  pkg: {hh, hl, whhlo}        @ +0,+16K,+32K
//   STAGE   [192K, 208K)
#define STRM_OFF  65536
#define STAGE_OFF 196608
#define DSMEM     212992

// ---------------- device globals (~0.9 GB) ----------------
__device__ __nv_bfloat16 g_x0h[(size_t)M_TOT * NH];
__device__ __nv_bfloat16 g_x0l[(size_t)M_TOT * NH];
__device__ __nv_bfloat16 g_hh[2 * NGRID * NH];        // h ring hi
__device__ __nv_bfloat16 g_hl[2 * NGRID * NH];        // h ring lo
__device__ float g_part[(size_t)M_TOT * 32];
__device__ float g_WinT[NX * NH];
__device__ __nv_bfloat16 g_Wih_h[NG4 * NH], g_Wih_l[NG4 * NH];  // [c][k], c=h*4+g
__device__ __nv_bfloat16 g_Whh_h[NG4 * NH], g_Whh_l[NG4 * NH];
__device__ float g_biasr[NG4];
__device__ unsigned g_cnt[16 * 32];    // per-row-group progress counters (padded)

// ---------------- helpers ----------------
__device__ __forceinline__ float sigf(float x) {
    return __fdividef(1.0f, 1.0f + __expf(-x));
}
__device__ __forceinline__ float tanhfast(float x) {
    return 2.0f * sigf(2.0f * x) - 1.0f;
}

__device__ __forceinline__ uint32_t smem_u32(const void* p) {
    uint32_t a;
    asm("{ .reg .u64 t; cvta.to.shared.u64 t, %1; cvt.u32.u64 %0, t; }" : "=r"(a) : "l"(p));
    return a;
}
__device__ __forceinline__ uint32_t tadr(uint32_t tb, int row, int kcol) {
    uint32_t bo = (uint32_t)(row * 128 + kcol * 2);
    return tb + (bo ^ ((bo >> 3) & 0x70));
}
__device__ __forceinline__ void ldsm4(uint32_t* r, uint32_t addr) {
    asm volatile("ldmatrix.sync.aligned.m8n8.x4.shared.b16 {%0,%1,%2,%3}, [%4];"
                 : "=r"(r[0]), "=r"(r[1]), "=r"(r[2]), "=r"(r[3]) : "r"(addr));
}
__device__ __forceinline__ void mma16816(float* d, const uint32_t* a, const uint32_t* b) {
    asm volatile("mma.sync.aligned.m16n8k16.row.col.f32.bf16.bf16.f32 "
                 "{%0,%1,%2,%3}, {%4,%5,%6,%7}, {%8,%9}, {%0,%1,%2,%3};"
                 : "+f"(d[0]), "+f"(d[1]), "+f"(d[2]), "+f"(d[3])
                 : "r"(a[0]), "r"(a[1]), "r"(a[2]), "r"(a[3]), "r"(b[0]), "r"(b[1]));
}

// 512-thread tile movers: one 128x64 bf16 tile (row pitch 256 elems = 512B)
__device__ __forceinline__ void ldg_tile(uint4* R, const __nv_bfloat16* __restrict__ g, int tid) {
    const char* gp = (const char*)g;
#pragma unroll
    for (int j = 0; j < 2; j++) {
        int q = tid + j * 512;
        int row = q >> 3, ch = q & 7;
        R[j] = __ldcg((const uint4*)(gp + (size_t)row * 512 + ch * 16));
    }
}
__device__ __forceinline__ void sts_tile(uint32_t dst, const uint4* R, int tid) {
#pragma unroll
    for (int j = 0; j < 2; j++) {
        int q = tid + j * 512;
        int row = q >> 3, ch = q & 7;
        uint32_t bo = (uint32_t)(row * 128 + ch * 16);
        uint32_t off = dst + (bo ^ ((bo >> 3) & 0x70));
        asm volatile("st.shared.v4.b32 [%0], {%1,%2,%3,%4};"
                     :: "r"(off), "r"(R[j].x), "r"(R[j].y), "r"(R[j].z), "r"(R[j].w));
    }
}
__device__ __forceinline__ void ld_tile(uint32_t dst, const __nv_bfloat16* __restrict__ g, int tid) {
    uint4 R[2];
    ldg_tile(R, g, tid);
    sts_tile(dst, R, tid);
}
// cp.async (global -> swizzled smem)
__device__ __forceinline__ void cpa_tile(uint32_t dst, const __nv_bfloat16* __restrict__ g, int tid) {
    const char* gp = (const char*)g;
#pragma unroll
    for (int j = 0; j < 2; j++) {
        int q = tid + j * 512;
        int row = q >> 3, ch = q & 7;
        uint32_t bo = (uint32_t)(row * 128 + ch * 16);
        uint32_t off = dst + (bo ^ ((bo >> 3) & 0x70));
        asm volatile("cp.async.cg.shared.global [%0], [%1], 16;"
                     :: "r"(off), "l"(gp + (size_t)row * 512 + ch * 16));
    }
}
#define CPA_COMMIT() asm volatile("cp.async.commit_group;" ::: "memory")
#define CPA_WAIT0()  asm volatile("cp.async.wait_group 0;" ::: "memory")

// issue x0-stage package {x0h, x0l, wihh, wihl}
__device__ __forceinline__ void issue_x0(uint32_t P,
                                         const __nv_bfloat16* __restrict__ x0h,
                                         const __nv_bfloat16* __restrict__ x0l,
                                         int n0, int kt, int tid) {
    cpa_tile(P,         x0h + kt * 64, tid);
    cpa_tile(P + 16384, x0l + kt * 64, tid);
    cpa_tile(P + 32768, g_Wih_h + (size_t)n0 * NH + kt * 64, tid);
    cpa_tile(P + 49152, g_Wih_l + (size_t)n0 * NH + kt * 64, tid);
    CPA_COMMIT();
}
// issue h-stage package {hh, hl, whh_lo}
__device__ __forceinline__ void issue_h(uint32_t P,
                                        const __nv_bfloat16* __restrict__ hh,
                                        const __nv_bfloat16* __restrict__ hl,
                                        int n0, int kt, int tid) {
    cpa_tile(P,         hh + kt * 64, tid);
    cpa_tile(P + 16384, hl + kt * 64, tid);
    cpa_tile(P + 32768, g_Whh_l + (size_t)n0 * NH + kt * 64, tid);
    CPA_COMMIT();
}

// 64-wide K chunk, warp tile 32x32: 3-term precision split, 4 k16 steps
__device__ __forceinline__ void mma_chunk(uint32_t ahi, uint32_t alo,
                                          uint32_t whi, uint32_t wlo,
                                          float acc[2][4][4], int mrow, int nbase,
                                          int rowAl, int kselA, int rowBl, int kselB) {
#pragma unroll
    for (int ks = 0; ks < 4; ks++) {
        int kA = ks * 16 + kselA, kB = ks * 16 + kselB;
        uint32_t Ah[2][4], Al[2][4], Wh[2][4], Wl[2][4];
#pragma unroll
        for (int mf = 0; mf < 2; mf++) {
            int row = mrow + mf * 16 + rowAl;
            ldsm4(Ah[mf], tadr(ahi, row, kA));
            ldsm4(Al[mf], tadr(alo, row, kA));
        }
#pragma unroll
        for (int np = 0; np < 2; np++) {
            int n = nbase + np * 16 + rowBl;
            ldsm4(Wh[np], tadr(whi, n, kB));
            ldsm4(Wl[np], tadr(wlo, n, kB));
        }
#pragma unroll
        for (int mf = 0; mf < 2; mf++)
#pragma unroll
            for (int nf = 0; nf < 4; nf++)
                mma16816(acc[mf][nf], Ah[mf], &Wh[nf >> 1][(nf & 1) * 2]);
#pragma unroll
        for (int mf = 0; mf < 2; mf++)
#pragma unroll
            for (int nf = 0; nf < 4; nf++)
                mma16816(acc[mf][nf], Al[mf], &Wh[nf >> 1][(nf & 1) * 2]);
#pragma unroll
        for (int mf = 0; mf < 2; mf++)
#pragma unroll
            for (int nf = 0; nf < 4; nf++)
                mma16816(acc[mf][nf], Ah[mf], &Wl[nf >> 1][(nf & 1) * 2]);
    }
}

// ---------------- prep ----------------
__global__ void k_prep(const float* __restrict__ W_in,
                       const float* __restrict__ W_ih,
                       const float* __restrict__ b_ih,
                       const float* __restrict__ b_hh,
                       const float* __restrict__ W_hh) {
    int i = blockIdx.x * blockDim.x + threadIdx.x;
    if (i < 16) g_cnt[i * 32] = 0;
    if (i < NX * NH) {
        int k = i / NH, h = i % NH;
        g_WinT[k * NH + h] = W_in[h * NX + k];
    }
    if (i < NG4 * NH) {
        int c = i >> 8, k = i & 255;
        int h = c >> 2, g = c & 3;
        int n = g * NH + h;
        float wih = W_ih[n * NH + k];
        float whh = W_hh[n * NH + k];
        __nv_bfloat16 ih_h = __float2bfloat16(wih);
        __nv_bfloat16 hh_h = __float2bfloat16(whh);
        g_Wih_h[i] = ih_h;
        g_Wih_l[i] = __float2bfloat16(wih - __bfloat162float(ih_h));
        g_Whh_h[i] = hh_h;
        g_Whh_l[i] = __float2bfloat16(whh - __bfloat162float(hh_h));
    }
    if (i < NG4) {
        int h = i >> 2, g = i & 3;
        int n = g * NH + h;
        g_biasr[i] = b_ih[n] + b_hh[n];
    }
}

// ---------------- x0 = relu(x @ W_in^T + b_in) -> bf16 hi/lo ----------------
typedef unsigned long long u64t;
__device__ __forceinline__ u64t pk2(float lo, float hi) {
    u64t r; asm("mov.b64 %0, {%1, %2};" : "=l"(r) : "f"(lo), "f"(hi)); return r;
}
__device__ __forceinline__ float2 upk2(u64t v) {
    float2 r; asm("mov.b64 {%0, %1}, %2;" : "=f"(r.x), "=f"(r.y) : "l"(v)); return r;
}
#define FMA2(d, a, b) asm("fma.rn.f32x2 %0, %1, %2, %0;" : "+l"(d) : "l"(a), "l"(b))

__global__ __launch_bounds__(256, 1) void k_x0(const float* __restrict__ x,
                                               const float* __restrict__ b_in) {
    __shared__ float A_s[32][129];
    __shared__ float B_s[32][128];
    int tid = threadIdx.x;
    int r0 = blockIdx.x * 128;
    int c0 = blockIdx.y * 128;

    const float* Ag = x + (size_t)r0 * NX;
#pragma unroll
    for (int j = 0; j < 16; j++) {
        int idx = tid + j * 256;
        A_s[idx & 31][idx >> 5] = Ag[idx];
    }
#pragma unroll
    for (int j = 0; j < 16; j++) {
        int idx = tid + j * 256;
        int k = idx >> 7, col = idx & 127;
        B_s[k][col] = g_WinT[k * NH + c0 + col];
    }
    __syncthreads();

    int tx = tid & 7, ty = tid >> 3;
    int cb = tx * 16, rb = ty * 4;

    u64t acc[4][8];
#pragma unroll
    for (int p = 0; p < 8; p++) {
        u64t bp = pk2(b_in[c0 + cb + 2 * p], b_in[c0 + cb + 2 * p + 1]);
        acc[0][p] = bp; acc[1][p] = bp; acc[2][p] = bp; acc[3][p] = bp;
    }
#pragma unroll
    for (int kk = 0; kk < 32; kk++) {
        u64t a2[4];
#pragma unroll
        for (int i = 0; i < 4; i++) { float a = A_s[kk][rb + i]; a2[i] = pk2(a, a); }
        const u64t* bs = reinterpret_cast<const u64t*>(&B_s[kk][cb]);
        u64t b2[8];
#pragma unroll
        for (int p = 0; p < 8; p++) b2[p] = bs[p];
#pragma unroll
        for (int i = 0; i < 4; i++)
#pragma unroll
            for (int p = 0; p < 8; p++) FMA2(acc[i][p], a2[i], b2[p]);
    }
#pragma unroll
    for (int i = 0; i < 4; i++) {
        size_t r = (size_t)(r0 + rb + i);
        union { unsigned short s[16]; uint4 v[2]; } uh, ul;
#pragma unroll
        for (int p = 0; p < 8; p++) {
            float2 u = upk2(acc[i][p]);
            float f0 = fmaxf(u.x, 0.f), f1 = fmaxf(u.y, 0.f);
            __nv_bfloat16 h0 = __float2bfloat16(f0);
            __nv_bfloat16 h1 = __float2bfloat16(f1);
            __nv_bfloat16 l0 = __float2bfloat16(f0 - __bfloat162float(h0));
            __nv_bfloat16 l1 = __float2bfloat16(f1 - __bfloat162float(h1));
            uh.s[2 * p] = *(unsigned short*)&h0; uh.s[2 * p + 1] = *(unsigned short*)&h1;
            ul.s[2 * p] = *(unsigned short*)&l0; ul.s[2 * p + 1] = *(unsigned short*)&l1;
        }
        uint4* dh = (uint4*)(g_x0h + r * NH + c0 + cb);
        uint4* dl = (uint4*)(g_x0l + r * NH + c0 + cb);
        dh[0] = uh.v[0]; dh[1] = uh.v[1];
        dl[0] = ul.v[0]; dl[1] = ul.v[1];
    }
}

// ---------------- fused persistent scan, boundary-chained pipeline ----------------
__global__ __launch_bounds__(512, 1) void k_scan(const float* __restrict__ W_out) {
    extern __shared__ char sm[];
    __shared__ float Wout_s[NH];
    __shared__ float bias_s[128];
    uint32_t sb = smem_u32(sm);
    const uint32_t WHH = sb;                       // resident Whh_hi (64K)
    const uint32_t B0 = sb + STRM_OFF;             // parity buffer 0
    const uint32_t B1 = sb + STRM_OFF + 65536;     // parity buffer 1
    const uint32_t STAGE = sb + STAGE_OFF;

    int tid = threadIdx.x, lane = tid & 31, w = tid >> 5;
    int wm = w >> 2, wn = w & 3;
    int g8 = lane >> 3, r8 = lane & 7;
    int rowAl = (g8 & 1) * 8 + r8, kselA = (g8 >> 1) * 8;
    int rowBl = (g8 >> 1) * 8 + r8, kselB = (g8 & 1) * 8;
    int gid = lane >> 2, tig = lane & 3;
    int nhat = blockIdx.x & 7, rbk = blockIdx.x >> 3;
    int n0 = nhat * 128, rbase = rbk * 128;

    if (tid < NH) Wout_s[tid] = W_out[tid];
    if (tid < 128) bias_s[tid] = g_biasr[n0 + tid];
#pragma unroll
    for (int kt = 0; kt < 4; kt++)
        ld_tile(WHH + kt * 16384, g_Whh_h + (size_t)n0 * NH + kt * 64, tid);

    float creg[2][4];
#pragma unroll
    for (int mf = 0; mf < 2; mf++)
#pragma unroll
        for (int nf = 0; nf < 4; nf++) creg[mf][nf] = 0.f;
    __syncthreads();

    // prologue: step-0 x0 kt0 into B0
    issue_x0(B0, g_x0h + (size_t)rbase * NH, g_x0l + (size_t)rbase * NH, n0, 0, tid);

    for (int tg = 0; tg < NT; tg++) {
        const __nv_bfloat16* x0h = g_x0h + ((size_t)tg * NGRID + rbase) * NH;
        const __nv_bfloat16* x0l = g_x0l + ((size_t)tg * NGRID + rbase) * NH;
        const __nv_bfloat16* hh = g_hh + (size_t)((tg - 1) & 1) * NGRID * NH + (size_t)rbase * NH;
        const __nv_bfloat16* hl = g_hl + (size_t)((tg - 1) & 1) * NGRID * NH + (size_t)rbase * NH;

        float acc[2][4][4];
#pragma unroll
        for (int a = 0; a < 2; a++)
#pragma unroll
            for (int b = 0; b < 4; b++)
#pragma unroll
                for (int c = 0; c < 4; c++) acc[a][b][c] = 0.f;

        // ---- x0 stages kt0..3 ----
#pragma unroll 1
        for (int kt = 0; kt < 4; kt++) {
            uint32_t P = (kt & 1) ? B1 : B0;
            CPA_WAIT0();
            __syncthreads();
            if (kt < 3) {
                issue_x0((kt & 1) ? B0 : B1, x0h, x0l, n0, kt + 1, tid);
            } else if (tg > 0) {
                // flag wait + h-pkg0 issue, overlapped with mma(x0 kt3)
                if (tid == 0) {
                    volatile unsigned* c = &g_cnt[rbk * 32];
                    while (*c < 8u * (unsigned)tg) __nanosleep(20);
                    __threadfence();
                }
                __syncthreads();
                issue_h(B0, hh, hl, n0, 0, tid);    // B0 free since mma(kt2)
            } else if (tg + 1 < NT) {
                // tg==0: chain next step's x0 kt0 into B0
                issue_x0(B0, x0h + (size_t)NGRID * NH, x0l + (size_t)NGRID * NH, n0, 0, tid);
            }
            mma_chunk(P, P + 16384, P + 32768, P + 49152, acc,
                      wm * 32, wn * 32, rowAl, kselA, rowBl, kselB);
        }

        // ---- h stages kt0..3 (tg>0) ----
        if (tg > 0) {
#pragma unroll 1
            for (int kt = 0; kt < 4; kt++) {
                uint32_t P = (kt & 1) ? B1 : B0;
                CPA_WAIT0();
                __syncthreads();
                if (kt < 3) {
                    issue_h((kt & 1) ? B0 : B1, hh, hl, n0, kt + 1, tid);
                } else if (tg + 1 < NT) {
                    // chain next step's x0 kt0 into B0 (free since mma h kt2)
                    issue_x0(B0, x0h + (size_t)NGRID * NH, x0l + (size_t)NGRID * NH, n0, 0, tid);
                }
                mma_chunk(P, P + 16384, WHH + kt * 16384, P + 32768, acc,
                          wm * 32, wn * 32, rowAl, kselA, rowBl, kselB);
            }
        }

        __syncthreads();   // stream reads done (next x0 kt0 already in flight into B0)

        // ---- epilogue: gates -> cell update; stage h tile; out partials ----
#pragma unroll
        for (int mf = 0; mf < 2; mf++) {
            int rloc = wm * 32 + mf * 16 + gid + (tig & 1) * 8;
            int row = rbase + rloc;
            float pout = 0.f;
#pragma unroll
            for (int nf = 0; nf < 4; nf++) {
                float c0 = acc[mf][nf][0], c1 = acc[mf][nf][1];
                float c2 = acc[mf][nf][2], c3 = acc[mf][nf][3];
                float s0 = (lane & 1) ? c0 : c2;
                float s1 = (lane & 1) ? c1 : c3;
                float r0 = __shfl_xor_sync(0xffffffffu, s0, 1);
                float r1 = __shfl_xor_sync(0xffffffffu, s1, 1);
                float gi, gf, gg, go;
                if (!(lane & 1)) { gi = c0; gf = c1; gg = r0; go = r1; }
                else             { gi = r0; gf = r1; gg = c2; go = c3; }
                int hl_i = wn * 8 + nf * 2 + (tig >> 1);
                float4 bv = *(const float4*)&bias_s[hl_i * 4];
                float iv = gi + bv.x, fv = gf + bv.y, gv = gg + bv.z, ov = go + bv.w;
                float cn = sigf(fv) * creg[mf][nf] + sigf(iv) * tanhfast(gv);
                creg[mf][nf] = cn;
                float hv = sigf(ov) * tanhfast(cn);
                pout += hv * Wout_s[nhat * 32 + hl_i];
                __nv_bfloat16 bh = __float2bfloat16(hv);
                __nv_bfloat16 bl = __float2bfloat16(hv - __bfloat162float(bh));
                uint32_t so = (uint32_t)(rloc * 64 + hl_i * 2);
                asm volatile("st.shared.u16 [%0], %1;" :: "r"(STAGE + so), "h"(*(unsigned short*)&bh));
                asm volatile("st.shared.u16 [%0], %1;" :: "r"(STAGE + 8192 + so), "h"(*(unsigned short*)&bl));
            }
            float pr = pout + __shfl_xor_sync(0xffffffffu, pout, 2);
            if ((tig >> 1) == 0)
                g_part[((size_t)tg * NGRID + row) * 32 + nhat * 4 + wn] = pr;
        }
        __syncthreads();

        // coalesced h writeout: 128 rows x 32 cols hi/lo
        {
            int row = tid >> 2, seg = tid & 3;
            uint4 vh, vl;
            asm volatile("ld.shared.v4.b32 {%0,%1,%2,%3}, [%4];"
                         : "=r"(vh.x), "=r"(vh.y), "=r"(vh.z), "=r"(vh.w)
                         : "r"(STAGE + row * 64 + seg * 16));
            asm volatile("ld.shared.v4.b32 {%0,%1,%2,%3}, [%4];"
                         : "=r"(vl.x), "=r"(vl.y), "=r"(vl.z), "=r"(vl.w)
                         : "r"(STAGE + 8192 + row * 64 + seg * 16));
            size_t go = (size_t)(tg & 1) * NGRID * NH + (size_t)(rbase + row) * NH + nhat * 32 + seg * 8;
            *(uint4*)(g_hh + go) = vh;
            *(uint4*)(g_hl + go) = vl;
        }
        __syncthreads();
        if (tid == 0) {
            __threadfence();
            atomicAdd(&g_cnt[rbk * 32], 1u);
        }
    }
}

// ---------------- out = sum(32 partials) + b_out ----------------
__global__ __launch_bounds__(256) void k_out(const float* __restrict__ b_out,
                                             float* __restrict__ out) {
    size_t r = (size_t)blockIdx.x * 256 + threadIdx.x;
    const float4* p = (const float4*)(g_part + r * 32);
    float s = 0.f;
#pragma unroll
    for (int j = 0; j < 8; j++) {
        float4 v = p[j];
        s += v.x + v.y + v.z + v.w;
    }
    out[r] = s + b_out[0];
}

// ---------------- launch ----------------
extern "C" void kernel_launch(void* const* d_in, const int* in_sizes, int n_in,
                              void* d_out, int out_size) {
    const float* x     = (const float*)d_in[0];
    const float* W_in  = (const float*)d_in[1];
    const float* b_in  = (const float*)d_in[2];
    const float* W_ih  = (const float*)d_in[3];
    const float* b_ih  = (const float*)d_in[4];
    const float* W_hh  = (const float*)d_in[5];
    const float* b_hh  = (const float*)d_in[6];
    const float* W_out = (const float*)d_in[7];
    const float* b_out = (const float*)d_in[8];
    float* out = (float*)d_out;

    static int attr_done = 0;
    if (!attr_done) {
        cudaFuncSetAttribute(k_scan, cudaFuncAttributeMaxDynamicSharedMemorySize, DSMEM);
        attr_done = 1;
    }

    k_prep<<<(NG4 * NH + 255) / 256, 256>>>(W_in, W_ih, b_ih, b_hh, W_hh);
    k_x0<<<dim3(M_TOT / 128, NH / 128), 256>>>(x, b_in);
    k_scan<<<128, 512, DSMEM>>>(W_out);
    k_out<<<M_TOT / 256, 256>>>(b_out, out);
}

// round 16
// speedup vs baseline: 2.2848x; 1.3101x over previous
#include <cuda_runtime.h>
#include <cuda_fp16.h>
#include <math.h>
#include <stdint.h>

// ---------------- problem constants ----------------
#define NT    365
#define NGRID 2048
#define NX    32
#define NH    256
#define NG4   1024
#define M_TOT (NT * NGRID)        // 747520

// scan SMEM layout (dynamic):
//   WHH_HI  [0, 64K)                resident Whh hi fp16 (4 kt x 16K)
//   STRM    [64K, 192K)             2 x 64K parity buffers B0/B1
//     x0 pkg: {x0h, x0l, wihh} @ +0,+16K,+32K
//     h  pkg: {hh, hl}         @ +0,+16K
//   STAGE   [192K, 208K)
#define STRM_OFF  65536
#define STAGE_OFF 196608
#define DSMEM     212992

// ---------------- device globals (~0.8 GB) ----------------
__device__ __half g_x0h[(size_t)M_TOT * NH];
__device__ __half g_x0l[(size_t)M_TOT * NH];
__device__ __half g_hh[2 * NGRID * NH];        // h ring hi
__device__ __half g_hl[2 * NGRID * NH];        // h ring lo
__device__ float g_part[(size_t)M_TOT * 32];
__device__ float g_WinT[NX * NH];
__device__ __half g_Wih_h[NG4 * NH];           // [c][k], c=h*4+g (fp16 hi only)
__device__ __half g_Whh_h[NG4 * NH];
__device__ float g_biasr[NG4];
__device__ unsigned g_cnt[16 * 32];

// ---------------- helpers ----------------
__device__ __forceinline__ float sigf(float x) {
    return __fdividef(1.0f, 1.0f + __expf(-x));
}
__device__ __forceinline__ float tanhfast(float x) {
    return 2.0f * sigf(2.0f * x) - 1.0f;
}

__device__ __forceinline__ uint32_t smem_u32(const void* p) {
    uint32_t a;
    asm("{ .reg .u64 t; cvta.to.shared.u64 t, %1; cvt.u32.u64 %0, t; }" : "=r"(a) : "l"(p));
    return a;
}
__device__ __forceinline__ uint32_t tadr(uint32_t tb, int row, int kcol) {
    uint32_t bo = (uint32_t)(row * 128 + kcol * 2);
    return tb + (bo ^ ((bo >> 3) & 0x70));
}
__device__ __forceinline__ void ldsm4(uint32_t* r, uint32_t addr) {
    asm volatile("ldmatrix.sync.aligned.m8n8.x4.shared.b16 {%0,%1,%2,%3}, [%4];"
                 : "=r"(r[0]), "=r"(r[1]), "=r"(r[2]), "=r"(r[3]) : "r"(addr));
}
__device__ __forceinline__ void mma16816(float* d, const uint32_t* a, const uint32_t* b) {
    asm volatile("mma.sync.aligned.m16n8k16.row.col.f32.f16.f16.f32 "
                 "{%0,%1,%2,%3}, {%4,%5,%6,%7}, {%8,%9}, {%0,%1,%2,%3};"
                 : "+f"(d[0]), "+f"(d[1]), "+f"(d[2]), "+f"(d[3])
                 : "r"(a[0]), "r"(a[1]), "r"(a[2]), "r"(a[3]), "r"(b[0]), "r"(b[1]));
}

// 512-thread tile movers: one 128x64 fp16 tile (row pitch 256 elems = 512B)
__device__ __forceinline__ void ldg_tile(uint4* R, const __half* __restrict__ g, int tid) {
    const char* gp = (const char*)g;
#pragma unroll
    for (int j = 0; j < 2; j++) {
        int q = tid + j * 512;
        int row = q >> 3, ch = q & 7;
        R[j] = __ldcg((const uint4*)(gp + (size_t)row * 512 + ch * 16));
    }
}
__device__ __forceinline__ void sts_tile(uint32_t dst, const uint4* R, int tid) {
#pragma unroll
    for (int j = 0; j < 2; j++) {
        int q = tid + j * 512;
        int row = q >> 3, ch = q & 7;
        uint32_t bo = (uint32_t)(row * 128 + ch * 16);
        uint32_t off = dst + (bo ^ ((bo >> 3) & 0x70));
        asm volatile("st.shared.v4.b32 [%0], {%1,%2,%3,%4};"
                     :: "r"(off), "r"(R[j].x), "r"(R[j].y), "r"(R[j].z), "r"(R[j].w));
    }
}
__device__ __forceinline__ void ld_tile(uint32_t dst, const __half* __restrict__ g, int tid) {
    uint4 R[2];
    ldg_tile(R, g, tid);
    sts_tile(dst, R, tid);
}
// cp.async (global -> swizzled smem)
__device__ __forceinline__ void cpa_tile(uint32_t dst, const __half* __restrict__ g, int tid) {
    const char* gp = (const char*)g;
#pragma unroll
    for (int j = 0; j < 2; j++) {
        int q = tid + j * 512;
        int row = q >> 3, ch = q & 7;
        uint32_t bo = (uint32_t)(row * 128 + ch * 16);
        uint32_t off = dst + (bo ^ ((bo >> 3) & 0x70));
        asm volatile("cp.async.cg.shared.global [%0], [%1], 16;"
                     :: "r"(off), "l"(gp + (size_t)row * 512 + ch * 16));
    }
}
#define CPA_COMMIT() asm volatile("cp.async.commit_group;" ::: "memory")
#define CPA_WAIT0()  asm volatile("cp.async.wait_group 0;" ::: "memory")

// issue x0-stage package {x0h, x0l, wihh}
__device__ __forceinline__ void issue_x0(uint32_t P,
                                         const __half* __restrict__ x0h,
                                         const __half* __restrict__ x0l,
                                         int n0, int kt, int tid) {
    cpa_tile(P,         x0h + kt * 64, tid);
    cpa_tile(P + 16384, x0l + kt * 64, tid);
    cpa_tile(P + 32768, g_Wih_h + (size_t)n0 * NH + kt * 64, tid);
    CPA_COMMIT();
}
// issue h-stage package {hh, hl}
__device__ __forceinline__ void issue_h(uint32_t P,
                                        const __half* __restrict__ hh,
                                        const __half* __restrict__ hl,
                                        int kt, int tid) {
    cpa_tile(P,         hh + kt * 64, tid);
    cpa_tile(P + 16384, hl + kt * 64, tid);
    CPA_COMMIT();
}

// 64-wide K chunk, warp tile 32x32: 2-term fp16 split (Ah*W + Al*W), 4 k16 steps
__device__ __forceinline__ void mma_chunk(uint32_t ahi, uint32_t alo, uint32_t whi,
                                          float acc[2][4][4], int mrow, int nbase,
                                          int rowAl, int kselA, int rowBl, int kselB) {
#pragma unroll
    for (int ks = 0; ks < 4; ks++) {
        int kA = ks * 16 + kselA, kB = ks * 16 + kselB;
        uint32_t Ah[2][4], Al[2][4], Wh[2][4];
#pragma unroll
        for (int mf = 0; mf < 2; mf++) {
            int row = mrow + mf * 16 + rowAl;
            ldsm4(Ah[mf], tadr(ahi, row, kA));
            ldsm4(Al[mf], tadr(alo, row, kA));
        }
#pragma unroll
        for (int np = 0; np < 2; np++)
            ldsm4(Wh[np], tadr(whi, nbase + np * 16 + rowBl, kB));
#pragma unroll
        for (int mf = 0; mf < 2; mf++)
#pragma unroll
            for (int nf = 0; nf < 4; nf++)
                mma16816(acc[mf][nf], Ah[mf], &Wh[nf >> 1][(nf & 1) * 2]);
#pragma unroll
        for (int mf = 0; mf < 2; mf++)
#pragma unroll
            for (int nf = 0; nf < 4; nf++)
                mma16816(acc[mf][nf], Al[mf], &Wh[nf >> 1][(nf & 1) * 2]);
    }
}

// ---------------- prep ----------------
__global__ void k_prep(const float* __restrict__ W_in,
                       const float* __restrict__ W_ih,
                       const float* __restrict__ b_ih,
                       const float* __restrict__ b_hh,
                       const float* __restrict__ W_hh) {
    int i = blockIdx.x * blockDim.x + threadIdx.x;
    if (i < 16) g_cnt[i * 32] = 0;
    if (i < NX * NH) {
        int k = i / NH, h = i % NH;
        g_WinT[k * NH + h] = W_in[h * NX + k];
    }
    if (i < NG4 * NH) {
        int c = i >> 8, k = i & 255;
        int h = c >> 2, g = c & 3;
        int n = g * NH + h;
        g_Wih_h[i] = __float2half(W_ih[n * NH + k]);
        g_Whh_h[i] = __float2half(W_hh[n * NH + k]);
    }
    if (i < NG4) {
        int h = i >> 2, g = i & 3;
        int n = g * NH + h;
        g_biasr[i] = b_ih[n] + b_hh[n];
    }
}

// ---------------- x0 = relu(x @ W_in^T + b_in) -> fp16 hi/lo ----------------
typedef unsigned long long u64t;
__device__ __forceinline__ u64t pk2(float lo, float hi) {
    u64t r; asm("mov.b64 %0, {%1, %2};" : "=l"(r) : "f"(lo), "f"(hi)); return r;
}
__device__ __forceinline__ float2 upk2(u64t v) {
    float2 r; asm("mov.b64 {%0, %1}, %2;" : "=f"(r.x), "=f"(r.y) : "l"(v)); return r;
}
#define FMA2(d, a, b) asm("fma.rn.f32x2 %0, %1, %2, %0;" : "+l"(d) : "l"(a), "l"(b))

__global__ __launch_bounds__(256, 1) void k_x0(const float* __restrict__ x,
                                               const float* __restrict__ b_in) {
    __shared__ float A_s[32][129];
    __shared__ float B_s[32][128];
    int tid = threadIdx.x;
    int r0 = blockIdx.x * 128;
    int c0 = blockIdx.y * 128;

    const float* Ag = x + (size_t)r0 * NX;
#pragma unroll
    for (int j = 0; j < 16; j++) {
        int idx = tid + j * 256;
        A_s[idx & 31][idx >> 5] = Ag[idx];
    }
#pragma unroll
    for (int j = 0; j < 16; j++) {
        int idx = tid + j * 256;
        int k = idx >> 7, col = idx & 127;
        B_s[k][col] = g_WinT[k * NH + c0 + col];
    }
    __syncthreads();

    int tx = tid & 7, ty = tid >> 3;
    int cb = tx * 16, rb = ty * 4;

    u64t acc[4][8];
#pragma unroll
    for (int p = 0; p < 8; p++) {
        u64t bp = pk2(b_in[c0 + cb + 2 * p], b_in[c0 + cb + 2 * p + 1]);
        acc[0][p] = bp; acc[1][p] = bp; acc[2][p] = bp; acc[3][p] = bp;
    }
#pragma unroll
    for (int kk = 0; kk < 32; kk++) {
        u64t a2[4];
#pragma unroll
        for (int i = 0; i < 4; i++) { float a = A_s[kk][rb + i]; a2[i] = pk2(a, a); }
        const u64t* bs = reinterpret_cast<const u64t*>(&B_s[kk][cb]);
        u64t b2[8];
#pragma unroll
        for (int p = 0; p < 8; p++) b2[p] = bs[p];
#pragma unroll
        for (int i = 0; i < 4; i++)
#pragma unroll
            for (int p = 0; p < 8; p++) FMA2(acc[i][p], a2[i], b2[p]);
    }
#pragma unroll
    for (int i = 0; i < 4; i++) {
        size_t r = (size_t)(r0 + rb + i);
        union { unsigned short s[16]; uint4 v[2]; } uh, ul;
#pragma unroll
        for (int p = 0; p < 8; p++) {
            float2 u = upk2(acc[i][p]);
            float f0 = fmaxf(u.x, 0.f), f1 = fmaxf(u.y, 0.f);
            __half h0 = __float2half(f0);
            __half h1 = __float2half(f1);
            __half l0 = __float2half(f0 - __half2float(h0));
            __half l1 = __float2half(f1 - __half2float(h1));
            uh.s[2 * p] = *(unsigned short*)&h0; uh.s[2 * p + 1] = *(unsigned short*)&h1;
            ul.s[2 * p] = *(unsigned short*)&l0; ul.s[2 * p + 1] = *(unsigned short*)&l1;
        }
        uint4* dh = (uint4*)(g_x0h + r * NH + c0 + cb);
        uint4* dl = (uint4*)(g_x0l + r * NH + c0 + cb);
        dh[0] = uh.v[0]; dh[1] = uh.v[1];
        dl[0] = ul.v[0]; dl[1] = ul.v[1];
    }
}

// ---------------- fused persistent scan, boundary-chained pipeline ----------------
__global__ __launch_bounds__(512, 1) void k_scan(const float* __restrict__ W_out) {
    extern __shared__ char sm[];
    __shared__ float Wout_s[NH];
    __shared__ float bias_s[128];
    uint32_t sb = smem_u32(sm);
    const uint32_t WHH = sb;                       // resident Whh_hi fp16 (64K)
    const uint32_t B0 = sb + STRM_OFF;
    const uint32_t B1 = sb + STRM_OFF + 65536;
    const uint32_t STAGE = sb + STAGE_OFF;

    int tid = threadIdx.x, lane = tid & 31, w = tid >> 5;
    int wm = w >> 2, wn = w & 3;
    int g8 = lane >> 3, r8 = lane & 7;
    int rowAl = (g8 & 1) * 8 + r8, kselA = (g8 >> 1) * 8;
    int rowBl = (g8 >> 1) * 8 + r8, kselB = (g8 & 1) * 8;
    int gid = lane >> 2, tig = lane & 3;
    int nhat = blockIdx.x & 7, rbk = blockIdx.x >> 3;
    int n0 = nhat * 128, rbase = rbk * 128;

    if (tid < NH) Wout_s[tid] = W_out[tid];
    if (tid < 128) bias_s[tid] = g_biasr[n0 + tid];
#pragma unroll
    for (int kt = 0; kt < 4; kt++)
        ld_tile(WHH + kt * 16384, g_Whh_h + (size_t)n0 * NH + kt * 64, tid);

    float creg[2][4];
#pragma unroll
    for (int mf = 0; mf < 2; mf++)
#pragma unroll
        for (int nf = 0; nf < 4; nf++) creg[mf][nf] = 0.f;
    __syncthreads();

    // prologue: step-0 x0 kt0 into B0
    issue_x0(B0, g_x0h + (size_t)rbase * NH, g_x0l + (size_t)rbase * NH, n0, 0, tid);

    for (int tg = 0; tg < NT; tg++) {
        const __half* x0h = g_x0h + ((size_t)tg * NGRID + rbase) * NH;
        const __half* x0l = g_x0l + ((size_t)tg * NGRID + rbase) * NH;
        const __half* hh = g_hh + (size_t)((tg - 1) & 1) * NGRID * NH + (size_t)rbase * NH;
        const __half* hl = g_hl + (size_t)((tg - 1) & 1) * NGRID * NH + (size_t)rbase * NH;

        float acc[2][4][4];
#pragma unroll
        for (int a = 0; a < 2; a++)
#pragma unroll
            for (int b = 0; b < 4; b++)
#pragma unroll
                for (int c = 0; c < 4; c++) acc[a][b][c] = 0.f;

        // ---- x0 stages kt0..3 ----
#pragma unroll 1
        for (int kt = 0; kt < 4; kt++) {
            uint32_t P = (kt & 1) ? B1 : B0;
            CPA_WAIT0();
            __syncthreads();
            if (kt < 3) {
                issue_x0((kt & 1) ? B0 : B1, x0h, x0l, n0, kt + 1, tid);
            } else if (tg > 0) {
                if (tid == 0) {
                    volatile unsigned* c = &g_cnt[rbk * 32];
                    while (*c < 8u * (unsigned)tg) __nanosleep(20);
                    __threadfence();
                }
                __syncthreads();
                issue_h(B0, hh, hl, 0, tid);
            } else if (tg + 1 < NT) {
                issue_x0(B0, x0h + (size_t)NGRID * NH, x0l + (size_t)NGRID * NH, n0, 0, tid);
            }
            mma_chunk(P, P + 16384, P + 32768, acc,
                      wm * 32, wn * 32, rowAl, kselA, rowBl, kselB);
        }

        // ---- h stages kt0..3 (tg>0) ----
        if (tg > 0) {
#pragma unroll 1
            for (int kt = 0; kt < 4; kt++) {
                uint32_t P = (kt & 1) ? B1 : B0;
                CPA_WAIT0();
                __syncthreads();
                if (kt < 3) {
                    issue_h((kt & 1) ? B0 : B1, hh, hl, kt + 1, tid);
                } else if (tg + 1 < NT) {
                    issue_x0(B0, x0h + (size_t)NGRID * NH, x0l + (size_t)NGRID * NH, n0, 0, tid);
                }
                mma_chunk(P, P + 16384, WHH + kt * 16384, acc,
                          wm * 32, wn * 32, rowAl, kselA, rowBl, kselB);
            }
        }

        __syncthreads();

        // ---- epilogue: gates -> cell update; stage h tile; out partials ----
#pragma unroll
        for (int mf = 0; mf < 2; mf++) {
            int rloc = wm * 32 + mf * 16 + gid + (tig & 1) * 8;
            int row = rbase + rloc;
            float pout = 0.f;
#pragma unroll
            for (int nf = 0; nf < 4; nf++) {
                float c0 = acc[mf][nf][0], c1 = acc[mf][nf][1];
                float c2 = acc[mf][nf][2], c3 = acc[mf][nf][3];
                float s0 = (lane & 1) ? c0 : c2;
                float s1 = (lane & 1) ? c1 : c3;
                float r0 = __shfl_xor_sync(0xffffffffu, s0, 1);
                float r1 = __shfl_xor_sync(0xffffffffu, s1, 1);
                float gi, gf, gg, go;
                if (!(lane & 1)) { gi = c0; gf = c1; gg = r0; go = r1; }
                else             { gi = r0; gf = r1; gg = c2; go = c3; }
                int hl_i = wn * 8 + nf * 2 + (tig >> 1);
                float4 bv = *(const float4*)&bias_s[hl_i * 4];
                float iv = gi + bv.x, fv = gf + bv.y, gv = gg + bv.z, ov = go + bv.w;
                float cn = sigf(fv) * creg[mf][nf] + sigf(iv) * tanhfast(gv);
                creg[mf][nf] = cn;
                float hv = sigf(ov) * tanhfast(cn);
                pout += hv * Wout_s[nhat * 32 + hl_i];
                __half bh = __float2half(hv);
                __half bl = __float2half(hv - __half2float(bh));
                uint32_t so = (uint32_t)(rloc * 64 + hl_i * 2);
                asm volatile("st.shared.u16 [%0], %1;" :: "r"(STAGE + so), "h"(*(unsigned short*)&bh));
                asm volatile("st.shared.u16 [%0], %1;" :: "r"(STAGE + 8192 + so), "h"(*(unsigned short*)&bl));
            }
            float pr = pout + __shfl_xor_sync(0xffffffffu, pout, 2);
            if ((tig >> 1) == 0)
                g_part[((size_t)tg * NGRID + row) * 32 + nhat * 4 + wn] = pr;
        }
        __syncthreads();

        // coalesced h writeout: 128 rows x 32 cols hi/lo
        {
            int row = tid >> 2, seg = tid & 3;
            uint4 vh, vl;
            asm volatile("ld.shared.v4.b32 {%0,%1,%2,%3}, [%4];"
                         : "=r"(vh.x), "=r"(vh.y), "=r"(vh.z), "=r"(vh.w)
                         : "r"(STAGE + row * 64 + seg * 16));
            asm volatile("ld.shared.v4.b32 {%0,%1,%2,%3}, [%4];"
                         : "=r"(vl.x), "=r"(vl.y), "=r"(vl.z), "=r"(vl.w)
                         : "r"(STAGE + 8192 + row * 64 + seg * 16));
            size_t go = (size_t)(tg & 1) * NGRID * NH + (size_t)(rbase + row) * NH + nhat * 32 + seg * 8;
            *(uint4*)(g_hh + go) = vh;
            *(uint4*)(g_hl + go) = vl;
        }
        __syncthreads();
        if (tid == 0) {
            __threadfence();
            atomicAdd(&g_cnt[rbk * 32], 1u);
        }
    }
}

// ---------------- out = sum(32 partials) + b_out ----------------
__global__ __launch_bounds__(256) void k_out(const float* __restrict__ b_out,
                                             float* __restrict__ out) {
    size_t r = (size_t)blockIdx.x * 256 + threadIdx.x;
    const float4* p = (const float4*)(g_part + r * 32);
    float s = 0.f;
#pragma unroll
    for (int j = 0; j < 8; j++) {
        float4 v = p[j];
        s += v.x + v.y + v.z + v.w;
    }
    out[r] = s + b_out[0];
}

// ---------------- launch ----------------
extern "C" void kernel_launch(void* const* d_in, const int* in_sizes, int n_in,
                              void* d_out, int out_size) {
    const float* x     = (const float*)d_in[0];
    const float* W_in  = (const float*)d_in[1];
    const float* b_in  = (const float*)d_in[2];
    const float* W_ih  = (const float*)d_in[3];
    const float* b_ih  = (const float*)d_in[4];
    const float* W_hh  = (const float*)d_in[5];
    const float* b_hh  = (const float*)d_in[6];
    const float* W_out = (const float*)d_in[7];
    const float* b_out = (const float*)d_in[8];
    float* out = (float*)d_out;

    static int attr_done = 0;
    if (!attr_done) {
        cudaFuncSetAttribute(k_scan, cudaFuncAttributeMaxDynamicSharedMemorySize, DSMEM);
        attr_done = 1;
    }

    k_prep<<<(NG4 * NH + 255) / 256, 256>>>(W_in, W_ih, b_ih, b_hh, W_hh);
    k_x0<<<dim3(M_TOT / 128, NH / 128), 256>>>(x, b_in);
    k_scan<<<128, 512, DSMEM>>>(W_out);
    k_out<<<M_TOT / 256, 256>>>(b_out, out);
}

// round 17
// speedup vs baseline: 3.2095x; 1.4047x over previous
#include <cuda_runtime.h>
#include <cuda_fp16.h>
#include <math.h>
#include <stdint.h>

// ---------------- problem constants ----------------
#define NT    365
#define NGRID 2048
#define NX    32
#define NH    256
#define NG4   1024
#define M_TOT (NT * NGRID)        // 747520

// scan SMEM layout (dynamic):
//   WHH  [0, 64K)        resident Whh fp16 (4 kt x 16K)
//   STRM [64K, 128K)     2 x 32K parity buffers B0/B1
//     x0 pkg: {x0h, wihh} @ +0,+16K ;  h pkg: {hh} @ +0
//   STAGE [128K, 136K)
#define STRM_OFF  65536
#define STAGE_OFF 131072
#define DSMEM     147456

// ---------------- device globals (~0.4 GB) ----------------
__device__ __half g_x0h[(size_t)M_TOT * NH];
__device__ __half g_hh[2 * NGRID * NH];        // h ring (fp16)
__device__ float g_part[(size_t)M_TOT * 32];
__device__ float g_WinT[NX * NH];
__device__ __half g_Wih_h[NG4 * NH];           // [c][k], c=h*4+g
__device__ __half g_Whh_h[NG4 * NH];
__device__ float g_biasr[NG4];
__device__ unsigned g_cnt[16 * 32];

// ---------------- helpers ----------------
__device__ __forceinline__ float sigf(float x) {
    return __fdividef(1.0f, 1.0f + __expf(-x));
}
__device__ __forceinline__ float tanhfast(float x) {
    return 2.0f * sigf(2.0f * x) - 1.0f;
}

__device__ __forceinline__ uint32_t smem_u32(const void* p) {
    uint32_t a;
    asm("{ .reg .u64 t; cvta.to.shared.u64 t, %1; cvt.u32.u64 %0, t; }" : "=r"(a) : "l"(p));
    return a;
}
__device__ __forceinline__ uint32_t tadr(uint32_t tb, int row, int kcol) {
    uint32_t bo = (uint32_t)(row * 128 + kcol * 2);
    return tb + (bo ^ ((bo >> 3) & 0x70));
}
__device__ __forceinline__ void ldsm4(uint32_t* r, uint32_t addr) {
    asm volatile("ldmatrix.sync.aligned.m8n8.x4.shared.b16 {%0,%1,%2,%3}, [%4];"
                 : "=r"(r[0]), "=r"(r[1]), "=r"(r[2]), "=r"(r[3]) : "r"(addr));
}
__device__ __forceinline__ void mma16816(float* d, const uint32_t* a, const uint32_t* b) {
    asm volatile("mma.sync.aligned.m16n8k16.row.col.f32.f16.f16.f32 "
                 "{%0,%1,%2,%3}, {%4,%5,%6,%7}, {%8,%9}, {%0,%1,%2,%3};"
                 : "+f"(d[0]), "+f"(d[1]), "+f"(d[2]), "+f"(d[3])
                 : "r"(a[0]), "r"(a[1]), "r"(a[2]), "r"(a[3]), "r"(b[0]), "r"(b[1]));
}

// 512-thread tile movers: one 128x64 fp16 tile (row pitch 256 elems = 512B)
__device__ __forceinline__ void ldg_tile(uint4* R, const __half* __restrict__ g, int tid) {
    const char* gp = (const char*)g;
#pragma unroll
    for (int j = 0; j < 2; j++) {
        int q = tid + j * 512;
        int row = q >> 3, ch = q & 7;
        R[j] = __ldcg((const uint4*)(gp + (size_t)row * 512 + ch * 16));
    }
}
__device__ __forceinline__ void sts_tile(uint32_t dst, const uint4* R, int tid) {
#pragma unroll
    for (int j = 0; j < 2; j++) {
        int q = tid + j * 512;
        int row = q >> 3, ch = q & 7;
        uint32_t bo = (uint32_t)(row * 128 + ch * 16);
        uint32_t off = dst + (bo ^ ((bo >> 3) & 0x70));
        asm volatile("st.shared.v4.b32 [%0], {%1,%2,%3,%4};"
                     :: "r"(off), "r"(R[j].x), "r"(R[j].y), "r"(R[j].z), "r"(R[j].w));
    }
}
__device__ __forceinline__ void ld_tile(uint32_t dst, const __half* __restrict__ g, int tid) {
    uint4 R[2];
    ldg_tile(R, g, tid);
    sts_tile(dst, R, tid);
}
// cp.async (global -> swizzled smem)
__device__ __forceinline__ void cpa_tile(uint32_t dst, const __half* __restrict__ g, int tid) {
    const char* gp = (const char*)g;
#pragma unroll
    for (int j = 0; j < 2; j++) {
        int q = tid + j * 512;
        int row = q >> 3, ch = q & 7;
        uint32_t bo = (uint32_t)(row * 128 + ch * 16);
        uint32_t off = dst + (bo ^ ((bo >> 3) & 0x70));
        asm volatile("cp.async.cg.shared.global [%0], [%1], 16;"
                     :: "r"(off), "l"(gp + (size_t)row * 512 + ch * 16));
    }
}
#define CPA_COMMIT() asm volatile("cp.async.commit_group;" ::: "memory")
#define CPA_WAIT0()  asm volatile("cp.async.wait_group 0;" ::: "memory")

// issue x0-stage package {x0h, wihh}
__device__ __forceinline__ void issue_x0(uint32_t P, const __half* __restrict__ x0h,
                                         int n0, int kt, int tid) {
    cpa_tile(P,         x0h + kt * 64, tid);
    cpa_tile(P + 16384, g_Wih_h + (size_t)n0 * NH + kt * 64, tid);
    CPA_COMMIT();
}
// issue h-stage package {hh}
__device__ __forceinline__ void issue_h(uint32_t P, const __half* __restrict__ hh,
                                        int kt, int tid) {
    cpa_tile(P, hh + kt * 64, tid);
    CPA_COMMIT();
}

// 64-wide K chunk, warp tile 32x32: plain fp16 x fp16, fp32 acc, 4 k16 steps
__device__ __forceinline__ void mma_chunk(uint32_t abuf, uint32_t wbuf,
                                          float acc[2][4][4], int mrow, int nbase,
                                          int rowAl, int kselA, int rowBl, int kselB) {
#pragma unroll
    for (int ks = 0; ks < 4; ks++) {
        int kA = ks * 16 + kselA, kB = ks * 16 + kselB;
        uint32_t Ah[2][4], Wh[2][4];
#pragma unroll
        for (int mf = 0; mf < 2; mf++)
            ldsm4(Ah[mf], tadr(abuf, mrow + mf * 16 + rowAl, kA));
#pragma unroll
        for (int np = 0; np < 2; np++)
            ldsm4(Wh[np], tadr(wbuf, nbase + np * 16 + rowBl, kB));
#pragma unroll
        for (int mf = 0; mf < 2; mf++)
#pragma unroll
            for (int nf = 0; nf < 4; nf++)
                mma16816(acc[mf][nf], Ah[mf], &Wh[nf >> 1][(nf & 1) * 2]);
    }
}

// ---------------- prep ----------------
__global__ void k_prep(const float* __restrict__ W_in,
                       const float* __restrict__ W_ih,
                       const float* __restrict__ b_ih,
                       const float* __restrict__ b_hh,
                       const float* __restrict__ W_hh) {
    int i = blockIdx.x * blockDim.x + threadIdx.x;
    if (i < 16) g_cnt[i * 32] = 0;
    if (i < NX * NH) {
        int k = i / NH, h = i % NH;
        g_WinT[k * NH + h] = W_in[h * NX + k];
    }
    if (i < NG4 * NH) {
        int c = i >> 8, k = i & 255;
        int h = c >> 2, g = c & 3;
        int n = g * NH + h;
        g_Wih_h[i] = __float2half(W_ih[n * NH + k]);
        g_Whh_h[i] = __float2half(W_hh[n * NH + k]);
    }
    if (i < NG4) {
        int h = i >> 2, g = i & 3;
        int n = g * NH + h;
        g_biasr[i] = b_ih[n] + b_hh[n];
    }
}

// ---------------- x0 = relu(x @ W_in^T + b_in) -> fp16 ----------------
typedef unsigned long long u64t;
__device__ __forceinline__ u64t pk2(float lo, float hi) {
    u64t r; asm("mov.b64 %0, {%1, %2};" : "=l"(r) : "f"(lo), "f"(hi)); return r;
}
__device__ __forceinline__ float2 upk2(u64t v) {
    float2 r; asm("mov.b64 {%0, %1}, %2;" : "=f"(r.x), "=f"(r.y) : "l"(v)); return r;
}
#define FMA2(d, a, b) asm("fma.rn.f32x2 %0, %1, %2, %0;" : "+l"(d) : "l"(a), "l"(b))

__global__ __launch_bounds__(256, 1) void k_x0(const float* __restrict__ x,
                                               const float* __restrict__ b_in) {
    __shared__ float A_s[32][129];
    __shared__ float B_s[32][128];
    int tid = threadIdx.x;
    int r0 = blockIdx.x * 128;
    int c0 = blockIdx.y * 128;

    const float* Ag = x + (size_t)r0 * NX;
#pragma unroll
    for (int j = 0; j < 16; j++) {
        int idx = tid + j * 256;
        A_s[idx & 31][idx >> 5] = Ag[idx];
    }
#pragma unroll
    for (int j = 0; j < 16; j++) {
        int idx = tid + j * 256;
        int k = idx >> 7, col = idx & 127;
        B_s[k][col] = g_WinT[k * NH + c0 + col];
    }
    __syncthreads();

    int tx = tid & 7, ty = tid >> 3;
    int cb = tx * 16, rb = ty * 4;

    u64t acc[4][8];
#pragma unroll
    for (int p = 0; p < 8; p++) {
        u64t bp = pk2(b_in[c0 + cb + 2 * p], b_in[c0 + cb + 2 * p + 1]);
        acc[0][p] = bp; acc[1][p] = bp; acc[2][p] = bp; acc[3][p] = bp;
    }
#pragma unroll
    for (int kk = 0; kk < 32; kk++) {
        u64t a2[4];
#pragma unroll
        for (int i = 0; i < 4; i++) { float a = A_s[kk][rb + i]; a2[i] = pk2(a, a); }
        const u64t* bs = reinterpret_cast<const u64t*>(&B_s[kk][cb]);
        u64t b2[8];
#pragma unroll
        for (int p = 0; p < 8; p++) b2[p] = bs[p];
#pragma unroll
        for (int i = 0; i < 4; i++)
#pragma unroll
            for (int p = 0; p < 8; p++) FMA2(acc[i][p], a2[i], b2[p]);
    }
#pragma unroll
    for (int i = 0; i < 4; i++) {
        size_t r = (size_t)(r0 + rb + i);
        union { unsigned short s[16]; uint4 v[2]; } uh;
#pragma unroll
        for (int p = 0; p < 8; p++) {
            float2 u = upk2(acc[i][p]);
            __half h0 = __float2half(fmaxf(u.x, 0.f));
            __half h1 = __float2half(fmaxf(u.y, 0.f));
            uh.s[2 * p] = *(unsigned short*)&h0;
            uh.s[2 * p + 1] = *(unsigned short*)&h1;
        }
        uint4* dh = (uint4*)(g_x0h + r * NH + c0 + cb);
        dh[0] = uh.v[0]; dh[1] = uh.v[1];
    }
}

// ---------------- fused persistent scan, boundary-chained pipeline ----------------
__global__ __launch_bounds__(512, 1) void k_scan(const float* __restrict__ W_out) {
    extern __shared__ char sm[];
    __shared__ float Wout_s[NH];
    __shared__ float bias_s[128];
    uint32_t sb = smem_u32(sm);
    const uint32_t WHH = sb;                       // resident Whh fp16 (64K)
    const uint32_t B0 = sb + STRM_OFF;
    const uint32_t B1 = sb + STRM_OFF + 32768;
    const uint32_t STAGE = sb + STAGE_OFF;

    int tid = threadIdx.x, lane = tid & 31, w = tid >> 5;
    int wm = w >> 2, wn = w & 3;
    int g8 = lane >> 3, r8 = lane & 7;
    int rowAl = (g8 & 1) * 8 + r8, kselA = (g8 >> 1) * 8;
    int rowBl = (g8 >> 1) * 8 + r8, kselB = (g8 & 1) * 8;
    int gid = lane >> 2, tig = lane & 3;
    int nhat = blockIdx.x & 7, rbk = blockIdx.x >> 3;
    int n0 = nhat * 128, rbase = rbk * 128;

    if (tid < NH) Wout_s[tid] = W_out[tid];
    if (tid < 128) bias_s[tid] = g_biasr[n0 + tid];
#pragma unroll
    for (int kt = 0; kt < 4; kt++)
        ld_tile(WHH + kt * 16384, g_Whh_h + (size_t)n0 * NH + kt * 64, tid);

    float creg[2][4];
#pragma unroll
    for (int mf = 0; mf < 2; mf++)
#pragma unroll
        for (int nf = 0; nf < 4; nf++) creg[mf][nf] = 0.f;
    __syncthreads();

    // prologue: step-0 x0 kt0 into B0
    issue_x0(B0, g_x0h + (size_t)rbase * NH, n0, 0, tid);

    for (int tg = 0; tg < NT; tg++) {
        const __half* x0h = g_x0h + ((size_t)tg * NGRID + rbase) * NH;
        const __half* hh = g_hh + (size_t)((tg - 1) & 1) * NGRID * NH + (size_t)rbase * NH;

        float acc[2][4][4];
#pragma unroll
        for (int a = 0; a < 2; a++)
#pragma unroll
            for (int b = 0; b < 4; b++)
#pragma unroll
                for (int c = 0; c < 4; c++) acc[a][b][c] = 0.f;

        // ---- x0 stages kt0..3 ----
#pragma unroll 1
        for (int kt = 0; kt < 4; kt++) {
            uint32_t P = (kt & 1) ? B1 : B0;
            CPA_WAIT0();
            __syncthreads();
            if (kt < 3) {
                issue_x0((kt & 1) ? B0 : B1, x0h, n0, kt + 1, tid);
            } else if (tg > 0) {
                if (tid == 0) {
                    volatile unsigned* c = &g_cnt[rbk * 32];
                    while (*c < 8u * (unsigned)tg) __nanosleep(20);
                    __threadfence();
                }
                __syncthreads();
                issue_h(B0, hh, 0, tid);
            } else if (tg + 1 < NT) {
                issue_x0(B0, x0h + (size_t)NGRID * NH, n0, 0, tid);
            }
            mma_chunk(P, P + 16384, acc,
                      wm * 32, wn * 32, rowAl, kselA, rowBl, kselB);
        }

        // ---- h stages kt0..3 (tg>0) ----
        if (tg > 0) {
#pragma unroll 1
            for (int kt = 0; kt < 4; kt++) {
                uint32_t P = (kt & 1) ? B1 : B0;
                CPA_WAIT0();
                __syncthreads();
                if (kt < 3) {
                    issue_h((kt & 1) ? B0 : B1, hh, kt + 1, tid);
                } else if (tg + 1 < NT) {
                    issue_x0(B0, x0h + (size_t)NGRID * NH, n0, 0, tid);
                }
                mma_chunk(P, WHH + kt * 16384, acc,
                          wm * 32, wn * 32, rowAl, kselA, rowBl, kselB);
            }
        }

        __syncthreads();

        // ---- epilogue: gates -> cell update; stage h tile; out partials ----
#pragma unroll
        for (int mf = 0; mf < 2; mf++) {
            int rloc = wm * 32 + mf * 16 + gid + (tig & 1) * 8;
            int row = rbase + rloc;
            float pout = 0.f;
#pragma unroll
            for (int nf = 0; nf < 4; nf++) {
                float c0 = acc[mf][nf][0], c1 = acc[mf][nf][1];
                float c2 = acc[mf][nf][2], c3 = acc[mf][nf][3];
                float s0 = (lane & 1) ? c0 : c2;
                float s1 = (lane & 1) ? c1 : c3;
                float r0 = __shfl_xor_sync(0xffffffffu, s0, 1);
                float r1 = __shfl_xor_sync(0xffffffffu, s1, 1);
                float gi, gf, gg, go;
                if (!(lane & 1)) { gi = c0; gf = c1; gg = r0; go = r1; }
                else             { gi = r0; gf = r1; gg = c2; go = c3; }
                int hl_i = wn * 8 + nf * 2 + (tig >> 1);
                float4 bv = *(const float4*)&bias_s[hl_i * 4];
                float iv = gi + bv.x, fv = gf + bv.y, gv = gg + bv.z, ov = go + bv.w;
                float cn = sigf(fv) * creg[mf][nf] + sigf(iv) * tanhfast(gv);
                creg[mf][nf] = cn;
                float hv = sigf(ov) * tanhfast(cn);
                pout += hv * Wout_s[nhat * 32 + hl_i];
                __half bh = __float2half(hv);
                uint32_t so = (uint32_t)(rloc * 64 + hl_i * 2);
                asm volatile("st.shared.u16 [%0], %1;" :: "r"(STAGE + so), "h"(*(unsigned short*)&bh));
            }
            float pr = pout + __shfl_xor_sync(0xffffffffu, pout, 2);
            if ((tig >> 1) == 0)
                g_part[((size_t)tg * NGRID + row) * 32 + nhat * 4 + wn] = pr;
        }
        __syncthreads();

        // coalesced h writeout: 128 rows x 32 cols fp16
        {
            int row = tid >> 2, seg = tid & 3;
            uint4 vh;
            asm volatile("ld.shared.v4.b32 {%0,%1,%2,%3}, [%4];"
                         : "=r"(vh.x), "=r"(vh.y), "=r"(vh.z), "=r"(vh.w)
                         : "r"(STAGE + row * 64 + seg * 16));
            size_t go = (size_t)(tg & 1) * NGRID * NH + (size_t)(rbase + row) * NH + nhat * 32 + seg * 8;
            *(uint4*)(g_hh + go) = vh;
        }
        __syncthreads();
        if (tid == 0) {
            __threadfence();
            atomicAdd(&g_cnt[rbk * 32], 1u);
        }
    }
}

// ---------------- out = sum(32 partials) + b_out ----------------
__global__ __launch_bounds__(256) void k_out(const float* __restrict__ b_out,
                                             float* __restrict__ out) {
    size_t r = (size_t)blockIdx.x * 256 + threadIdx.x;
    const float4* p = (const float4*)(g_part + r * 32);
    float s = 0.f;
#pragma unroll
    for (int j = 0; j < 8; j++) {
        float4 v = p[j];
        s += v.x + v.y + v.z + v.w;
    }
    out[r] = s + b_out[0];
}

// ---------------- launch ----------------
extern "C" void kernel_launch(void* const* d_in, const int* in_sizes, int n_in,
                              void* d_out, int out_size) {
    const float* x     = (const float*)d_in[0];
    const float* W_in  = (const float*)d_in[1];
    const float* b_in  = (const float*)d_in[2];
    const float* W_ih  = (const float*)d_in[3];
    const float* b_ih  = (const float*)d_in[4];
    const float* W_hh  = (const float*)d_in[5];
    const float* b_hh  = (const float*)d_in[6];
    const float* W_out = (const float*)d_in[7];
    const float* b_out = (const float*)d_in[8];
    float* out = (float*)d_out;

    static int attr_done = 0;
    if (!attr_done) {
        cudaFuncSetAttribute(k_scan, cudaFuncAttributeMaxDynamicSharedMemorySize, DSMEM);
        attr_done = 1;
    }

    k_prep<<<(NG4 * NH + 255) / 256, 256>>>(W_in, W_ih, b_ih, b_hh, W_hh);
    k_x0<<<dim3(M_TOT / 128, NH / 128), 256>>>(x, b_in);
    k_scan<<<128, 512, DSMEM>>>(W_out);
    k_out<<<M_TOT / 256, 256>>>(b_out, out);
}